// round 6
// baseline (speedup 1.0000x reference)
#include <cuda_runtime.h>
#include <cuda_bf16.h>
#include <cstdint>

#define B_ 4
#define S_ 2048
#define D_ 1024
#define H_ 16
#define DH_ 64
#define BS_ 8192
#define HD_ 1024

// ---------------- scratch (bf16 hi/lo splits) ----------------
__device__ __nv_bfloat16 g_qh[BS_*HD_], g_ql[BS_*HD_];
__device__ __nv_bfloat16 g_kh[BS_*HD_], g_kl[BS_*HD_];
__device__ __nv_bfloat16 g_vh[BS_*HD_], g_vl[BS_*HD_];
__device__ __nv_bfloat16 g_Wqh[D_*HD_], g_Wql[D_*HD_];
__device__ __nv_bfloat16 g_Wkh[D_*HD_], g_Wkl[D_*HD_];
__device__ __nv_bfloat16 g_Wvh[D_*HD_], g_Wvl[D_*HD_];
__device__ __nv_bfloat16 g_Woh[HD_*D_], g_Wol[HD_*D_];
__device__ __nv_bfloat16 g_Qh[BS_*HD_], g_Ql[BS_*HD_];   // [bh][s][dh]
__device__ __nv_bfloat16 g_Kh[BS_*HD_], g_Kl[BS_*HD_];   // [bh][s][dh]
__device__ __nv_bfloat16 g_Vph[BS_*HD_], g_Vpl[BS_*HD_]; // [bh][s][dh]
__device__ __nv_bfloat16 g_Vth[BS_*HD_], g_Vtl[BS_*HD_]; // [bh][dh][s]
__device__ __nv_bfloat16 g_AOh[BS_*HD_], g_AOl[BS_*HD_]; // [row][1024]

// ---------------- helpers ----------------
__device__ __forceinline__ void sp2(float a, float b, uint32_t& h, uint32_t& l) {
    __nv_bfloat16 ha = __float2bfloat16(a), hb = __float2bfloat16(b);
    float la = a - __bfloat162float(ha);
    float lb = b - __bfloat162float(hb);
    __nv_bfloat162 hp(ha, hb);
    __nv_bfloat162 lp(__float2bfloat16(la), __float2bfloat16(lb));
    h = *reinterpret_cast<uint32_t*>(&hp);
    l = *reinterpret_cast<uint32_t*>(&lp);
}

__device__ __forceinline__ void mma_bf16(float* d, uint32_t a0, uint32_t a1,
                                         uint32_t a2, uint32_t a3,
                                         uint32_t b0, uint32_t b1) {
    asm volatile(
        "mma.sync.aligned.m16n8k16.row.col.f32.bf16.bf16.f32 "
        "{%0,%1,%2,%3}, {%4,%5,%6,%7}, {%8,%9}, {%0,%1,%2,%3};"
        : "+f"(d[0]), "+f"(d[1]), "+f"(d[2]), "+f"(d[3])
        : "r"(a0), "r"(a1), "r"(a2), "r"(a3), "r"(b0), "r"(b1));
}

__device__ __forceinline__ void cp16(uint32_t s, const void* g) {
    asm volatile("cp.async.cg.shared.global [%0], [%1], 16;" :: "r"(s), "l"(g));
}
#define CP_COMMIT asm volatile("cp.async.commit_group;")
#define CP_WAIT0  asm volatile("cp.async.wait_group 0;" ::: "memory")
#define CP_WAIT1  asm volatile("cp.async.wait_group 1;" ::: "memory")

// ---------------------------------------------------------------------------
__global__ void split_in(const float* __restrict__ x,
                         __nv_bfloat16* __restrict__ hi,
                         __nv_bfloat16* __restrict__ lo, int n4) {
    int i = blockIdx.x * blockDim.x + threadIdx.x;
    if (i < n4) {
        float4 v = ((const float4*)x)[i];
        uint2 hh, ll;
        sp2(v.x, v.y, hh.x, ll.x);
        sp2(v.z, v.w, hh.y, ll.y);
        ((uint2*)hi)[i] = hh;
        ((uint2*)lo)[i] = ll;
    }
}

// ---------------------------------------------------------------------------
__global__ void wsplit(const float* __restrict__ W,
                       __nv_bfloat16* __restrict__ th,
                       __nv_bfloat16* __restrict__ tl) {
    __shared__ float t[32][33];
    const int k0 = blockIdx.y * 32, n0 = blockIdx.x * 32;
    const int tx = threadIdx.x, ty = threadIdx.y;
    #pragma unroll
    for (int r = 0; r < 4; r++)
        t[ty + r * 8][tx] = W[(size_t)(k0 + ty + r * 8) * 1024 + n0 + tx];
    __syncthreads();
    #pragma unroll
    for (int r = 0; r < 4; r++) {
        int n = ty + r * 8;
        float v = t[tx][n];
        __nv_bfloat16 hb = __float2bfloat16(v);
        float l = v - __bfloat162float(hb);
        th[(size_t)(n0 + n) * 1024 + k0 + tx] = hb;
        tl[(size_t)(n0 + n) * 1024 + k0 + tx] = __float2bfloat16(l);
    }
}

// ---------------------------------------------------------------------------
// Projection GEMM (bf16 3-term) — unchanged from R4.
// ---------------------------------------------------------------------------
#define PK 40
#define PROJ_SMEM (2 * 4 * 128 * PK * 2)

template<int OUTMODE>
__global__ void __launch_bounds__(256, 2)
proj_bf16(const __nv_bfloat16* __restrict__ Ah, const __nv_bfloat16* __restrict__ Al,
          const __nv_bfloat16* __restrict__ Bh, const __nv_bfloat16* __restrict__ Bl,
          const float* __restrict__ bias,
          __nv_bfloat16* __restrict__ Ch, __nv_bfloat16* __restrict__ Cl,
          float* __restrict__ Cf) {
    extern __shared__ __nv_bfloat16 dsm[];
    const int BUF = 4 * 128 * PK;
    __nv_bfloat16* base = dsm;

    const int tid = threadIdx.x;
    const int m0 = blockIdx.y * 128, n0 = blockIdx.x * 128;
    const int w = tid >> 5, lane = tid & 31, g = lane >> 2, t = lane & 3;
    const int mw = (w & 1) * 64, nw = (w >> 1) * 32;

    const uint32_t smu = (uint32_t)__cvta_generic_to_shared(dsm);

    float acc[4][4][4] = {};

    auto stage = [&](int it, int buf) {
        const int k0 = it * 32;
        const uint32_t bu = smu + (uint32_t)buf * BUF * 2;
        #pragma unroll
        for (int r = 0; r < 2; r++) {
            int c = tid + r * 256;
            int row = c >> 2, q8 = (c & 3) * 8;
            uint32_t o = (uint32_t)(row * PK + q8) * 2;
            size_t gi = (size_t)(m0 + row) * 1024 + k0 + q8;
            cp16(bu + o,                       Ah + gi);
            cp16(bu + 128 * PK * 2 + o,        Al + gi);
            size_t gb = (size_t)(n0 + row) * 1024 + k0 + q8;
            cp16(bu + 2 * 128 * PK * 2 + o,    Bh + gb);
            cp16(bu + 3 * 128 * PK * 2 + o,    Bl + gb);
        }
    };

    stage(0, 0); CP_COMMIT;

    for (int it = 0; it < 32; it++) {
        const int buf = it & 1;
        if (it + 1 < 32) { stage(it + 1, buf ^ 1); CP_COMMIT; CP_WAIT1; }
        else             { CP_WAIT0; }
        __syncthreads();

        const __nv_bfloat16* pAh = base + buf * BUF;
        const __nv_bfloat16* pAl = pAh + 128 * PK;
        const __nv_bfloat16* pBh = pAl + 128 * PK;
        const __nv_bfloat16* pBl = pBh + 128 * PK;

        #pragma unroll
        for (int ks = 0; ks < 32; ks += 16) {
            uint32_t bh[4][2], bl[4][2];
            #pragma unroll
            for (int j = 0; j < 4; j++) {
                const int n = nw + j * 8 + g;
                bh[j][0] = *(const uint32_t*)&pBh[n * PK + ks + 2 * t];
                bh[j][1] = *(const uint32_t*)&pBh[n * PK + ks + 2 * t + 8];
                bl[j][0] = *(const uint32_t*)&pBl[n * PK + ks + 2 * t];
                bl[j][1] = *(const uint32_t*)&pBl[n * PK + ks + 2 * t + 8];
            }
            #pragma unroll
            for (int i = 0; i < 4; i++) {
                const int m = mw + i * 16 + g;
                uint32_t ah0 = *(const uint32_t*)&pAh[m * PK + ks + 2 * t];
                uint32_t ah1 = *(const uint32_t*)&pAh[(m + 8) * PK + ks + 2 * t];
                uint32_t ah2 = *(const uint32_t*)&pAh[m * PK + ks + 2 * t + 8];
                uint32_t ah3 = *(const uint32_t*)&pAh[(m + 8) * PK + ks + 2 * t + 8];
                uint32_t al0 = *(const uint32_t*)&pAl[m * PK + ks + 2 * t];
                uint32_t al1 = *(const uint32_t*)&pAl[(m + 8) * PK + ks + 2 * t];
                uint32_t al2 = *(const uint32_t*)&pAl[m * PK + ks + 2 * t + 8];
                uint32_t al3 = *(const uint32_t*)&pAl[(m + 8) * PK + ks + 2 * t + 8];
                #pragma unroll
                for (int j = 0; j < 4; j++) {
                    mma_bf16(acc[i][j], ah0, ah1, ah2, ah3, bh[j][0], bh[j][1]);
                    mma_bf16(acc[i][j], al0, al1, al2, al3, bh[j][0], bh[j][1]);
                    mma_bf16(acc[i][j], ah0, ah1, ah2, ah3, bl[j][0], bl[j][1]);
                }
            }
        }
        __syncthreads();
    }

    #pragma unroll
    for (int i = 0; i < 4; i++) {
        #pragma unroll
        for (int j = 0; j < 4; j++) {
            const int row0 = m0 + mw + i * 16 + g;
            const int col  = n0 + nw + j * 8 + t * 2;
            const float b0 = bias[col], b1 = bias[col + 1];
            float c00 = acc[i][j][0] + b0, c01 = acc[i][j][1] + b1;
            float c10 = acc[i][j][2] + b0, c11 = acc[i][j][3] + b1;
            if (OUTMODE == 2) {
                *(float2*)&Cf[(size_t)row0 * 1024 + col]       = make_float2(c00, c01);
                *(float2*)&Cf[(size_t)(row0 + 8) * 1024 + col] = make_float2(c10, c11);
            } else {
                size_t d0, d1;
                if (OUTMODE == 0) {
                    int bI = row0 >> 11, s = row0 & 2047, h = col >> 6, d = col & 63;
                    d0 = (((size_t)(bI * 16 + h) * 2048 + s) * 64 + d);
                    d1 = d0 + 8 * 64;
                } else {
                    d0 = (size_t)row0 * 1024 + col;
                    d1 = d0 + 8 * 1024;
                }
                uint32_t hu, lu;
                sp2(c00, c01, hu, lu);
                *(uint32_t*)&Ch[d0] = hu; *(uint32_t*)&Cl[d0] = lu;
                sp2(c10, c11, hu, lu);
                *(uint32_t*)&Ch[d1] = hu; *(uint32_t*)&Cl[d1] = lu;
            }
        }
    }
}

// ---------------------------------------------------------------------------
__global__ void vtrans(const __nv_bfloat16* __restrict__ ih,
                       const __nv_bfloat16* __restrict__ il,
                       __nv_bfloat16* __restrict__ oh,
                       __nv_bfloat16* __restrict__ ol) {
    __shared__ __nv_bfloat16 t[64][72];
    const int s0 = blockIdx.x * 64;
    const int bh = blockIdx.y;
    const int tid = threadIdx.x;

    for (int pass = 0; pass < 2; pass++) {
        const __nv_bfloat16* src = pass ? il : ih;
        __nv_bfloat16* dst = pass ? ol : oh;
        #pragma unroll
        for (int r = 0; r < 8; r++) {
            int c = tid + r * 256;
            int row = c >> 5, c2 = (c & 31) * 2;
            *(uint32_t*)&t[row][c2] =
                *(const uint32_t*)&src[((size_t)bh * 2048 + s0 + row) * 64 + c2];
        }
        __syncthreads();
        #pragma unroll
        for (int r = 0; r < 8; r++) {
            int c = tid + r * 256;
            int d = c >> 5, s2 = (c & 31) * 2;
            __nv_bfloat162 p(t[s2][d], t[s2 + 1][d]);
            *(uint32_t*)&dst[((size_t)bh * 64 + d) * 2048 + s0 + s2] =
                *(uint32_t*)&p;
        }
        __syncthreads();
    }
}

// ---------------------------------------------------------------------------
// Fused attention, bf16 3-term, stats-then-recompute.
// PASS A: S = 0.125*Q*K^T over 16 x (128-row K tiles), NO global writes,
//         online row max m and row sum l.
// PASS B: per 64-row kv tile: recompute S, P = exp(S-m)/l -> write alpha
//         (only alpha write), split P to smem, O += P*V.
// smem (bf16 units, pitch 72):
//   sQh 0        sQl 9216      (128x72 each; resident both passes)
//   pass A: sKh0 18432  sKl0 27648  sKh1 36864  sKl1 46080   (128x72 each)
//   pass B: pKh 18432  pKl 23040  pVh 27648  pVl 32256 (64x72 each)
//           sPh 36864  sPl 46080 (128x72 each)
//   float region at 55296: sM[128] sF[128] sL[128] sRed[512]
// total = 55296*2 + 896*4 = 114176 B -> 2 CTAs/SM (228352 <= 233472)
// ---------------------------------------------------------------------------
#define PQ 72
#define ATTN_SMEM (55296 * 2 + 896 * 4)

__global__ void __launch_bounds__(256, 2)
attn_bf16(float* __restrict__ alpha,
          __nv_bfloat16* __restrict__ AOh, __nv_bfloat16* __restrict__ AOl) {
    extern __shared__ __nv_bfloat16 dsm[];
    __nv_bfloat16* sQh = dsm;
    __nv_bfloat16* sQl = dsm + 9216;
    __nv_bfloat16* sKh0 = dsm + 18432;
    __nv_bfloat16* sKl0 = dsm + 27648;
    __nv_bfloat16* sKh1 = dsm + 36864;
    __nv_bfloat16* sKl1 = dsm + 46080;
    float* fsm  = (float*)(dsm + 55296);
    float* sM   = fsm;
    float* sF   = fsm + 128;
    float* sL   = fsm + 256;
    float* sRed = fsm + 384;

    const int tid = threadIdx.x;
    const int w = tid >> 5, lane = tid & 31, g = lane >> 2, t = lane & 3;
    const int mw = (w & 1) * 64;
    const int wc = w >> 1;
    const int q0 = blockIdx.x * 128;
    const int bh = blockIdx.y;

    const __nv_bfloat16* Qhb = g_Qh + ((size_t)bh * 2048 + q0) * 64;
    const __nv_bfloat16* Qlb = g_Ql + ((size_t)bh * 2048 + q0) * 64;
    const __nv_bfloat16* Khb = g_Kh + (size_t)bh * 2048 * 64;
    const __nv_bfloat16* Klb = g_Kl + (size_t)bh * 2048 * 64;
    const __nv_bfloat16* Vthb = g_Vth + (size_t)bh * 64 * 2048;
    const __nv_bfloat16* Vtlb = g_Vtl + (size_t)bh * 64 * 2048;
    float* Ab = alpha + ((size_t)bh * 2048 + q0) * 2048;

    const uint32_t smu = (uint32_t)__cvta_generic_to_shared(dsm);

    if (tid < 128) { sM[tid] = -3e38f; sL[tid] = 0.f; }

    // stage Q (once)
    #pragma unroll
    for (int r = 0; r < 4; r++) {
        int c = tid + r * 256;
        int row = c >> 3, q8 = (c & 7) * 8;
        uint32_t o = (uint32_t)(row * PQ + q8) * 2;
        size_t gi = (size_t)row * 64 + q8;
        cp16(smu + o,            Qhb + gi);
        cp16(smu + 9216 * 2 + o, Qlb + gi);
    }
    auto stageK = [&](int kt, int buf) {
        const uint32_t bh_off = (buf ? 36864u : 18432u) * 2;
        const uint32_t bl_off = (buf ? 46080u : 27648u) * 2;
        const size_t src = (size_t)kt * 128 * 64;
        #pragma unroll
        for (int r = 0; r < 4; r++) {
            int c = tid + r * 256;
            int row = c >> 3, q8 = (c & 7) * 8;
            uint32_t o = (uint32_t)(row * PQ + q8) * 2;
            cp16(smu + bh_off + o, Khb + src + (size_t)row * 64 + q8);
            cp16(smu + bl_off + o, Klb + src + (size_t)row * 64 + q8);
        }
    };
    stageK(0, 0);
    CP_COMMIT;

    // =================== PASS A: stats only ===================
    for (int kt = 0; kt < 16; kt++) {
        const __nv_bfloat16* pKh = (kt & 1) ? sKh1 : sKh0;
        const __nv_bfloat16* pKl = (kt & 1) ? sKl1 : sKl0;
        if (kt + 1 < 16) { stageK(kt + 1, (kt & 1) ^ 1); CP_COMMIT; CP_WAIT1; }
        else             { CP_WAIT0; }
        __syncthreads();

        float acc[4][4][4] = {};
        #pragma unroll
        for (int ks = 0; ks < 64; ks += 16) {
            uint32_t kh[4][2], kl[4][2];
            #pragma unroll
            for (int j = 0; j < 4; j++) {
                const int n = wc * 32 + j * 8 + g;
                kh[j][0] = *(const uint32_t*)&pKh[n * PQ + ks + 2 * t];
                kh[j][1] = *(const uint32_t*)&pKh[n * PQ + ks + 2 * t + 8];
                kl[j][0] = *(const uint32_t*)&pKl[n * PQ + ks + 2 * t];
                kl[j][1] = *(const uint32_t*)&pKl[n * PQ + ks + 2 * t + 8];
            }
            #pragma unroll
            for (int i = 0; i < 4; i++) {
                const int m = mw + i * 16 + g;
                uint32_t qh0 = *(const uint32_t*)&sQh[m * PQ + ks + 2 * t];
                uint32_t qh1 = *(const uint32_t*)&sQh[(m + 8) * PQ + ks + 2 * t];
                uint32_t qh2 = *(const uint32_t*)&sQh[m * PQ + ks + 2 * t + 8];
                uint32_t qh3 = *(const uint32_t*)&sQh[(m + 8) * PQ + ks + 2 * t + 8];
                uint32_t ql0 = *(const uint32_t*)&sQl[m * PQ + ks + 2 * t];
                uint32_t ql1 = *(const uint32_t*)&sQl[(m + 8) * PQ + ks + 2 * t];
                uint32_t ql2 = *(const uint32_t*)&sQl[m * PQ + ks + 2 * t + 8];
                uint32_t ql3 = *(const uint32_t*)&sQl[(m + 8) * PQ + ks + 2 * t + 8];
                #pragma unroll
                for (int j = 0; j < 4; j++) {
                    mma_bf16(acc[i][j], qh0, qh1, qh2, qh3, kh[j][0], kh[j][1]);
                    mma_bf16(acc[i][j], ql0, ql1, ql2, ql3, kh[j][0], kh[j][1]);
                    mma_bf16(acc[i][j], qh0, qh1, qh2, qh3, kl[j][0], kl[j][1]);
                }
            }
        }
        #pragma unroll
        for (int i = 0; i < 4; i++)
            #pragma unroll
            for (int j = 0; j < 4; j++)
                #pragma unroll
                for (int r = 0; r < 4; r++) acc[i][j][r] *= 0.125f;

        // row max
        float rmax[8];
        #pragma unroll
        for (int i = 0; i < 4; i++) {
            float m0v = -3e38f, m1v = -3e38f;
            #pragma unroll
            for (int j = 0; j < 4; j++) {
                m0v = fmaxf(m0v, fmaxf(acc[i][j][0], acc[i][j][1]));
                m1v = fmaxf(m1v, fmaxf(acc[i][j][2], acc[i][j][3]));
            }
            rmax[i * 2] = m0v; rmax[i * 2 + 1] = m1v;
        }
        #pragma unroll
        for (int o = 1; o <= 2; o <<= 1)
            #pragma unroll
            for (int e = 0; e < 8; e++)
                rmax[e] = fmaxf(rmax[e], __shfl_xor_sync(0xffffffffu, rmax[e], o));
        if (t == 0) {
            #pragma unroll
            for (int i = 0; i < 4; i++) {
                sRed[wc * 128 + mw + i * 16 + g]     = rmax[i * 2];
                sRed[wc * 128 + mw + i * 16 + g + 8] = rmax[i * 2 + 1];
            }
        }
        __syncthreads();
        if (tid < 128) {
            float tm = fmaxf(fmaxf(sRed[tid], sRed[128 + tid]),
                             fmaxf(sRed[256 + tid], sRed[384 + tid]));
            float mo = sM[tid];
            float mn = fmaxf(mo, tm);
            sM[tid] = mn;
            sF[tid] = __expf(mo - mn);
        }
        __syncthreads();

        // row sum of exp
        float rsum[8];
        #pragma unroll
        for (int i = 0; i < 4; i++) {
            const int row = mw + i * 16 + g;
            const float mn0 = sM[row], mn1 = sM[row + 8];
            float s0 = 0.f, s1 = 0.f;
            #pragma unroll
            for (int j = 0; j < 4; j++) {
                s0 += __expf(acc[i][j][0] - mn0) + __expf(acc[i][j][1] - mn0);
                s1 += __expf(acc[i][j][2] - mn1) + __expf(acc[i][j][3] - mn1);
            }
            rsum[i * 2] = s0; rsum[i * 2 + 1] = s1;
        }
        #pragma unroll
        for (int o = 1; o <= 2; o <<= 1)
            #pragma unroll
            for (int e = 0; e < 8; e++)
                rsum[e] += __shfl_xor_sync(0xffffffffu, rsum[e], o);
        if (t == 0) {
            #pragma unroll
            for (int i = 0; i < 4; i++) {
                sRed[wc * 128 + mw + i * 16 + g]     = rsum[i * 2];
                sRed[wc * 128 + mw + i * 16 + g + 8] = rsum[i * 2 + 1];
            }
        }
        __syncthreads();
        if (tid < 128) {
            sL[tid] = sL[tid] * sF[tid] +
                      (sRed[tid] + sRed[128 + tid] + sRed[256 + tid] + sRed[384 + tid]);
        }
        __syncthreads();
    }

    if (tid < 128) sL[tid] = 1.0f / sL[tid];
    __syncthreads();

    // =================== PASS B: recompute + P write + AV ===================
    __nv_bfloat16* pKh = dsm + 18432;   // 64 x 72
    __nv_bfloat16* pKl = dsm + 23040;
    __nv_bfloat16* pVh = dsm + 27648;   // Vt tile: 64 d-rows x 64 kv
    __nv_bfloat16* pVl = dsm + 32256;
    __nv_bfloat16* sPh = dsm + 36864;   // 128 x 72
    __nv_bfloat16* sPl = dsm + 46080;

    float accO[4][2][4] = {};

    for (int kt = 0; kt < 32; kt++) {
        const int kb = kt * 64;
        // stage K (64 kv rows x 64) and Vt (64 d rows x 64 kv), single buffer
        #pragma unroll
        for (int r = 0; r < 2; r++) {
            int c = tid + r * 256;
            int row = c >> 3, q8 = (c & 7) * 8;
            uint32_t o = (uint32_t)(row * PQ + q8) * 2;
            cp16(smu + 18432u * 2 + o, Khb + (size_t)(kb + row) * 64 + q8);
            cp16(smu + 23040u * 2 + o, Klb + (size_t)(kb + row) * 64 + q8);
            cp16(smu + 27648u * 2 + o, Vthb + (size_t)row * 2048 + kb + q8);
            cp16(smu + 32256u * 2 + o, Vtlb + (size_t)row * 2048 + kb + q8);
        }
        CP_COMMIT; CP_WAIT0;
        __syncthreads();

        // recompute S tile: 128 q x 64 kv (warps 2x4, TN=2)
        float acc[4][2][4] = {};
        #pragma unroll
        for (int ks = 0; ks < 64; ks += 16) {
            uint32_t kh[2][2], kl[2][2];
            #pragma unroll
            for (int j = 0; j < 2; j++) {
                const int n = wc * 16 + j * 8 + g;
                kh[j][0] = *(const uint32_t*)&pKh[n * PQ + ks + 2 * t];
                kh[j][1] = *(const uint32_t*)&pKh[n * PQ + ks + 2 * t + 8];
                kl[j][0] = *(const uint32_t*)&pKl[n * PQ + ks + 2 * t];
                kl[j][1] = *(const uint32_t*)&pKl[n * PQ + ks + 2 * t + 8];
            }
            #pragma unroll
            for (int i = 0; i < 4; i++) {
                const int m = mw + i * 16 + g;
                uint32_t qh0 = *(const uint32_t*)&sQh[m * PQ + ks + 2 * t];
                uint32_t qh1 = *(const uint32_t*)&sQh[(m + 8) * PQ + ks + 2 * t];
                uint32_t qh2 = *(const uint32_t*)&sQh[m * PQ + ks + 2 * t + 8];
                uint32_t qh3 = *(const uint32_t*)&sQh[(m + 8) * PQ + ks + 2 * t + 8];
                uint32_t ql0 = *(const uint32_t*)&sQl[m * PQ + ks + 2 * t];
                uint32_t ql1 = *(const uint32_t*)&sQl[(m + 8) * PQ + ks + 2 * t];
                uint32_t ql2 = *(const uint32_t*)&sQl[m * PQ + ks + 2 * t + 8];
                uint32_t ql3 = *(const uint32_t*)&sQl[(m + 8) * PQ + ks + 2 * t + 8];
                #pragma unroll
                for (int j = 0; j < 2; j++) {
                    mma_bf16(acc[i][j], qh0, qh1, qh2, qh3, kh[j][0], kh[j][1]);
                    mma_bf16(acc[i][j], ql0, ql1, ql2, ql3, kh[j][0], kh[j][1]);
                    mma_bf16(acc[i][j], qh0, qh1, qh2, qh3, kl[j][0], kl[j][1]);
                }
            }
        }

        // P = exp(0.125*S - m) * invl ; write alpha; split into sP
        #pragma unroll
        for (int i = 0; i < 4; i++) {
            const int r0 = mw + i * 16 + g;
            const float m0v = sM[r0],      l0v = sL[r0];
            const float m1v = sM[r0 + 8],  l1v = sL[r0 + 8];
            #pragma unroll
            for (int j = 0; j < 2; j++) {
                const int cl = wc * 16 + j * 8 + t * 2;   // col within 64
                float p00 = __expf(acc[i][j][0] * 0.125f - m0v) * l0v;
                float p01 = __expf(acc[i][j][1] * 0.125f - m0v) * l0v;
                float p10 = __expf(acc[i][j][2] * 0.125f - m1v) * l1v;
                float p11 = __expf(acc[i][j][3] * 0.125f - m1v) * l1v;
                *(float2*)&Ab[(size_t)r0 * 2048 + kb + cl]       = make_float2(p00, p01);
                *(float2*)&Ab[(size_t)(r0 + 8) * 2048 + kb + cl] = make_float2(p10, p11);
                uint32_t hu, lu;
                sp2(p00, p01, hu, lu);
                *(uint32_t*)&sPh[r0 * PQ + cl] = hu;
                *(uint32_t*)&sPl[r0 * PQ + cl] = lu;
                sp2(p10, p11, hu, lu);
                *(uint32_t*)&sPh[(r0 + 8) * PQ + cl] = hu;
                *(uint32_t*)&sPl[(r0 + 8) * PQ + cl] = lu;
            }
        }
        __syncthreads();

        // O += P(128 x 64kv) * Vt^T  (n = d, 4 warps x 16)
        #pragma unroll
        for (int ks = 0; ks < 64; ks += 16) {
            uint32_t vh[2][2], vl[2][2];
            #pragma unroll
            for (int j = 0; j < 2; j++) {
                const int n = wc * 16 + j * 8 + g;
                vh[j][0] = *(const uint32_t*)&pVh[n * PQ + ks + 2 * t];
                vh[j][1] = *(const uint32_t*)&pVh[n * PQ + ks + 2 * t + 8];
                vl[j][0] = *(const uint32_t*)&pVl[n * PQ + ks + 2 * t];
                vl[j][1] = *(const uint32_t*)&pVl[n * PQ + ks + 2 * t + 8];
            }
            #pragma unroll
            for (int i = 0; i < 4; i++) {
                const int m = mw + i * 16 + g;
                uint32_t ph0 = *(const uint32_t*)&sPh[m * PQ + ks + 2 * t];
                uint32_t ph1 = *(const uint32_t*)&sPh[(m + 8) * PQ + ks + 2 * t];
                uint32_t ph2 = *(const uint32_t*)&sPh[m * PQ + ks + 2 * t + 8];
                uint32_t ph3 = *(const uint32_t*)&sPh[(m + 8) * PQ + ks + 2 * t + 8];
                uint32_t pl0 = *(const uint32_t*)&sPl[m * PQ + ks + 2 * t];
                uint32_t pl1 = *(const uint32_t*)&sPl[(m + 8) * PQ + ks + 2 * t];
                uint32_t pl2 = *(const uint32_t*)&sPl[m * PQ + ks + 2 * t + 8];
                uint32_t pl3 = *(const uint32_t*)&sPl[(m + 8) * PQ + ks + 2 * t + 8];
                #pragma unroll
                for (int j = 0; j < 2; j++) {
                    mma_bf16(accO[i][j], ph0, ph1, ph2, ph3, vh[j][0], vh[j][1]);
                    mma_bf16(accO[i][j], pl0, pl1, pl2, pl3, vh[j][0], vh[j][1]);
                    mma_bf16(accO[i][j], ph0, ph1, ph2, ph3, vl[j][0], vl[j][1]);
                }
            }
        }
        __syncthreads();
    }

    // epilogue: AO split (flat [row][1024], col = h*64 + d)
    const int b = bh >> 4, h = bh & 15;
    #pragma unroll
    for (int i = 0; i < 4; i++) {
        #pragma unroll
        for (int j = 0; j < 2; j++) {
            const int row = q0 + mw + i * 16 + g;
            const int col = h * 64 + wc * 16 + j * 8 + t * 2;
            uint32_t hu, lu;
            size_t d0 = ((size_t)(b * 2048 + row)) * 1024 + col;
            sp2(accO[i][j][0], accO[i][j][1], hu, lu);
            *(uint32_t*)&AOh[d0] = hu; *(uint32_t*)&AOl[d0] = lu;
            size_t d1 = ((size_t)(b * 2048 + row + 8)) * 1024 + col;
            sp2(accO[i][j][2], accO[i][j][3], hu, lu);
            *(uint32_t*)&AOh[d1] = hu; *(uint32_t*)&AOl[d1] = lu;
        }
    }
}

// ---------------------------------------------------------------------------
extern "C" void kernel_launch(void* const* d_in, const int* in_sizes, int n_in,
                              void* d_out, int out_size) {
    const float* q  = (const float*)d_in[0];
    const float* k  = (const float*)d_in[1];
    const float* v  = (const float*)d_in[2];
    const float* Wq = (const float*)d_in[3];
    const float* bq = (const float*)d_in[4];
    const float* Wk = (const float*)d_in[5];
    const float* bk = (const float*)d_in[6];
    const float* Wv = (const float*)d_in[7];
    const float* bv = (const float*)d_in[8];
    const float* Wo = (const float*)d_in[9];
    const float* bo = (const float*)d_in[10];

    float* out   = (float*)d_out;
    float* alpha = out + (size_t)B_ * S_ * D_;

    __nv_bfloat16 *qh,*ql,*kh,*kl,*vh,*vl;
    __nv_bfloat16 *Wqh,*Wql,*Wkh,*Wkl,*Wvh,*Wvl,*Woh,*Wol;
    __nv_bfloat16 *Qh,*Ql,*Kh,*Kl,*Vph,*Vpl,*Vth,*Vtl,*AOh,*AOl;
    cudaGetSymbolAddress((void**)&qh, g_qh);   cudaGetSymbolAddress((void**)&ql, g_ql);
    cudaGetSymbolAddress((void**)&kh, g_kh);   cudaGetSymbolAddress((void**)&kl, g_kl);
    cudaGetSymbolAddress((void**)&vh, g_vh);   cudaGetSymbolAddress((void**)&vl, g_vl);
    cudaGetSymbolAddress((void**)&Wqh, g_Wqh); cudaGetSymbolAddress((void**)&Wql, g_Wql);
    cudaGetSymbolAddress((void**)&Wkh, g_Wkh); cudaGetSymbolAddress((void**)&Wkl, g_Wkl);
    cudaGetSymbolAddress((void**)&Wvh, g_Wvh); cudaGetSymbolAddress((void**)&Wvl, g_Wvl);
    cudaGetSymbolAddress((void**)&Woh, g_Woh); cudaGetSymbolAddress((void**)&Wol, g_Wol);
    cudaGetSymbolAddress((void**)&Qh, g_Qh);   cudaGetSymbolAddress((void**)&Ql, g_Ql);
    cudaGetSymbolAddress((void**)&Kh, g_Kh);   cudaGetSymbolAddress((void**)&Kl, g_Kl);
    cudaGetSymbolAddress((void**)&Vph, g_Vph); cudaGetSymbolAddress((void**)&Vpl, g_Vpl);
    cudaGetSymbolAddress((void**)&Vth, g_Vth); cudaGetSymbolAddress((void**)&Vtl, g_Vtl);
    cudaGetSymbolAddress((void**)&AOh, g_AOh); cudaGetSymbolAddress((void**)&AOl, g_AOl);

    static bool attr_set = false;
    if (!attr_set) {
        cudaFuncSetAttribute(proj_bf16<0>, cudaFuncAttributeMaxDynamicSharedMemorySize, PROJ_SMEM);
        cudaFuncSetAttribute(proj_bf16<2>, cudaFuncAttributeMaxDynamicSharedMemorySize, PROJ_SMEM);
        cudaFuncSetAttribute(attn_bf16, cudaFuncAttributeMaxDynamicSharedMemorySize, ATTN_SMEM);
        attr_set = true;
    }

    const int n4 = BS_ * HD_ / 4;
    split_in<<<(n4 + 255) / 256, 256>>>(q, qh, ql, n4);
    split_in<<<(n4 + 255) / 256, 256>>>(k, kh, kl, n4);
    split_in<<<(n4 + 255) / 256, 256>>>(v, vh, vl, n4);

    dim3 gW(32, 32), bW(32, 8);
    wsplit<<<gW, bW>>>(Wq, Wqh, Wql);
    wsplit<<<gW, bW>>>(Wk, Wkh, Wkl);
    wsplit<<<gW, bW>>>(Wv, Wvh, Wvl);
    wsplit<<<gW, bW>>>(Wo, Woh, Wol);

    dim3 gProj(HD_ / 128, BS_ / 128);   // (8, 64)
    proj_bf16<0><<<gProj, 256, PROJ_SMEM>>>(qh, ql, Wqh, Wql, bq, Qh, Ql, nullptr);
    proj_bf16<0><<<gProj, 256, PROJ_SMEM>>>(kh, kl, Wkh, Wkl, bk, Kh, Kl, nullptr);
    proj_bf16<0><<<gProj, 256, PROJ_SMEM>>>(vh, vl, Wvh, Wvl, bv, Vph, Vpl, nullptr);

    vtrans<<<dim3(32, 64), 256>>>(Vph, Vpl, Vth, Vtl);

    dim3 gAttn(S_ / 128, B_ * H_);      // (16, 64)
    attn_bf16<<<gAttn, 256, ATTN_SMEM>>>(alpha, AOh, AOl);

    proj_bf16<2><<<gProj, 256, PROJ_SMEM>>>(AOh, AOl, Woh, Wol, bo, nullptr, nullptr, out);
}

// round 7
// speedup vs baseline: 1.2258x; 1.2258x over previous
#include <cuda_runtime.h>
#include <cuda_bf16.h>
#include <cstdint>

#define B_ 4
#define S_ 2048
#define D_ 1024
#define H_ 16
#define DH_ 64
#define BS_ 8192
#define HD_ 1024

// ---------------- scratch (bf16 hi/lo splits) ----------------
__device__ __nv_bfloat16 g_qh[BS_*HD_], g_ql[BS_*HD_];
__device__ __nv_bfloat16 g_kh[BS_*HD_], g_kl[BS_*HD_];
__device__ __nv_bfloat16 g_vh[BS_*HD_], g_vl[BS_*HD_];
__device__ __nv_bfloat16 g_Wqh[D_*HD_], g_Wql[D_*HD_];
__device__ __nv_bfloat16 g_Wkh[D_*HD_], g_Wkl[D_*HD_];
__device__ __nv_bfloat16 g_Wvh[D_*HD_], g_Wvl[D_*HD_];
__device__ __nv_bfloat16 g_Woh[HD_*D_], g_Wol[HD_*D_];
__device__ __nv_bfloat16 g_Qh[BS_*HD_], g_Ql[BS_*HD_];   // [bh][s][dh]
__device__ __nv_bfloat16 g_Kh[BS_*HD_], g_Kl[BS_*HD_];   // [bh][s][dh]
__device__ __nv_bfloat16 g_Vph[BS_*HD_], g_Vpl[BS_*HD_]; // [bh][s][dh]
__device__ __nv_bfloat16 g_Vth[BS_*HD_], g_Vtl[BS_*HD_]; // [bh][dh][s]
__device__ __nv_bfloat16 g_AOh[BS_*HD_], g_AOl[BS_*HD_]; // [row][1024]

// ---------------- helpers ----------------
__device__ __forceinline__ void sp2(float a, float b, uint32_t& h, uint32_t& l) {
    __nv_bfloat16 ha = __float2bfloat16(a), hb = __float2bfloat16(b);
    float la = a - __bfloat162float(ha);
    float lb = b - __bfloat162float(hb);
    __nv_bfloat162 hp(ha, hb);
    __nv_bfloat162 lp(__float2bfloat16(la), __float2bfloat16(lb));
    h = *reinterpret_cast<uint32_t*>(&hp);
    l = *reinterpret_cast<uint32_t*>(&lp);
}

__device__ __forceinline__ void mma_bf16(float* d, uint32_t a0, uint32_t a1,
                                         uint32_t a2, uint32_t a3,
                                         uint32_t b0, uint32_t b1) {
    asm volatile(
        "mma.sync.aligned.m16n8k16.row.col.f32.bf16.bf16.f32 "
        "{%0,%1,%2,%3}, {%4,%5,%6,%7}, {%8,%9}, {%0,%1,%2,%3};"
        : "+f"(d[0]), "+f"(d[1]), "+f"(d[2]), "+f"(d[3])
        : "r"(a0), "r"(a1), "r"(a2), "r"(a3), "r"(b0), "r"(b1));
}

__device__ __forceinline__ void cp16(uint32_t s, const void* g) {
    asm volatile("cp.async.cg.shared.global [%0], [%1], 16;" :: "r"(s), "l"(g));
}
#define CP_COMMIT asm volatile("cp.async.commit_group;")
#define CP_WAIT0  asm volatile("cp.async.wait_group 0;" ::: "memory")
#define CP_WAIT1  asm volatile("cp.async.wait_group 1;" ::: "memory")

// ---------------------------------------------------------------------------
__global__ void split_in(const float* __restrict__ x,
                         __nv_bfloat16* __restrict__ hi,
                         __nv_bfloat16* __restrict__ lo, int n4) {
    int i = blockIdx.x * blockDim.x + threadIdx.x;
    if (i < n4) {
        float4 v = ((const float4*)x)[i];
        uint2 hh, ll;
        sp2(v.x, v.y, hh.x, ll.x);
        sp2(v.z, v.w, hh.y, ll.y);
        ((uint2*)hi)[i] = hh;
        ((uint2*)lo)[i] = ll;
    }
}

// ---------------------------------------------------------------------------
__global__ void wsplit(const float* __restrict__ W,
                       __nv_bfloat16* __restrict__ th,
                       __nv_bfloat16* __restrict__ tl) {
    __shared__ float t[32][33];
    const int k0 = blockIdx.y * 32, n0 = blockIdx.x * 32;
    const int tx = threadIdx.x, ty = threadIdx.y;
    #pragma unroll
    for (int r = 0; r < 4; r++)
        t[ty + r * 8][tx] = W[(size_t)(k0 + ty + r * 8) * 1024 + n0 + tx];
    __syncthreads();
    #pragma unroll
    for (int r = 0; r < 4; r++) {
        int n = ty + r * 8;
        float v = t[tx][n];
        __nv_bfloat16 hb = __float2bfloat16(v);
        float l = v - __bfloat162float(hb);
        th[(size_t)(n0 + n) * 1024 + k0 + tx] = hb;
        tl[(size_t)(n0 + n) * 1024 + k0 + tx] = __float2bfloat16(l);
    }
}

// ---------------------------------------------------------------------------
// Projection GEMM (bf16 3-term)
// ---------------------------------------------------------------------------
#define PK 40
#define PROJ_SMEM (2 * 4 * 128 * PK * 2)

template<int OUTMODE>
__global__ void __launch_bounds__(256, 2)
proj_bf16(const __nv_bfloat16* __restrict__ Ah, const __nv_bfloat16* __restrict__ Al,
          const __nv_bfloat16* __restrict__ Bh, const __nv_bfloat16* __restrict__ Bl,
          const float* __restrict__ bias,
          __nv_bfloat16* __restrict__ Ch, __nv_bfloat16* __restrict__ Cl,
          float* __restrict__ Cf) {
    extern __shared__ __nv_bfloat16 dsm[];
    const int BUF = 4 * 128 * PK;
    __nv_bfloat16* base = dsm;

    const int tid = threadIdx.x;
    const int m0 = blockIdx.y * 128, n0 = blockIdx.x * 128;
    const int w = tid >> 5, lane = tid & 31, g = lane >> 2, t = lane & 3;
    const int mw = (w & 1) * 64, nw = (w >> 1) * 32;

    const uint32_t smu = (uint32_t)__cvta_generic_to_shared(dsm);

    float acc[4][4][4] = {};

    auto stage = [&](int it, int buf) {
        const int k0 = it * 32;
        const uint32_t bu = smu + (uint32_t)buf * BUF * 2;
        #pragma unroll
        for (int r = 0; r < 2; r++) {
            int c = tid + r * 256;
            int row = c >> 2, q8 = (c & 3) * 8;
            uint32_t o = (uint32_t)(row * PK + q8) * 2;
            size_t gi = (size_t)(m0 + row) * 1024 + k0 + q8;
            cp16(bu + o,                       Ah + gi);
            cp16(bu + 128 * PK * 2 + o,        Al + gi);
            size_t gb = (size_t)(n0 + row) * 1024 + k0 + q8;
            cp16(bu + 2 * 128 * PK * 2 + o,    Bh + gb);
            cp16(bu + 3 * 128 * PK * 2 + o,    Bl + gb);
        }
    };

    stage(0, 0); CP_COMMIT;

    for (int it = 0; it < 32; it++) {
        const int buf = it & 1;
        if (it + 1 < 32) { stage(it + 1, buf ^ 1); CP_COMMIT; CP_WAIT1; }
        else             { CP_WAIT0; }
        __syncthreads();

        const __nv_bfloat16* pAh = base + buf * BUF;
        const __nv_bfloat16* pAl = pAh + 128 * PK;
        const __nv_bfloat16* pBh = pAl + 128 * PK;
        const __nv_bfloat16* pBl = pBh + 128 * PK;

        #pragma unroll
        for (int ks = 0; ks < 32; ks += 16) {
            uint32_t bh[4][2], bl[4][2];
            #pragma unroll
            for (int j = 0; j < 4; j++) {
                const int n = nw + j * 8 + g;
                bh[j][0] = *(const uint32_t*)&pBh[n * PK + ks + 2 * t];
                bh[j][1] = *(const uint32_t*)&pBh[n * PK + ks + 2 * t + 8];
                bl[j][0] = *(const uint32_t*)&pBl[n * PK + ks + 2 * t];
                bl[j][1] = *(const uint32_t*)&pBl[n * PK + ks + 2 * t + 8];
            }
            #pragma unroll
            for (int i = 0; i < 4; i++) {
                const int m = mw + i * 16 + g;
                uint32_t ah0 = *(const uint32_t*)&pAh[m * PK + ks + 2 * t];
                uint32_t ah1 = *(const uint32_t*)&pAh[(m + 8) * PK + ks + 2 * t];
                uint32_t ah2 = *(const uint32_t*)&pAh[m * PK + ks + 2 * t + 8];
                uint32_t ah3 = *(const uint32_t*)&pAh[(m + 8) * PK + ks + 2 * t + 8];
                uint32_t al0 = *(const uint32_t*)&pAl[m * PK + ks + 2 * t];
                uint32_t al1 = *(const uint32_t*)&pAl[(m + 8) * PK + ks + 2 * t];
                uint32_t al2 = *(const uint32_t*)&pAl[m * PK + ks + 2 * t + 8];
                uint32_t al3 = *(const uint32_t*)&pAl[(m + 8) * PK + ks + 2 * t + 8];
                #pragma unroll
                for (int j = 0; j < 4; j++) {
                    mma_bf16(acc[i][j], ah0, ah1, ah2, ah3, bh[j][0], bh[j][1]);
                    mma_bf16(acc[i][j], al0, al1, al2, al3, bh[j][0], bh[j][1]);
                    mma_bf16(acc[i][j], ah0, ah1, ah2, ah3, bl[j][0], bl[j][1]);
                }
            }
        }
        __syncthreads();
    }

    #pragma unroll
    for (int i = 0; i < 4; i++) {
        #pragma unroll
        for (int j = 0; j < 4; j++) {
            const int row0 = m0 + mw + i * 16 + g;
            const int col  = n0 + nw + j * 8 + t * 2;
            const float b0 = bias[col], b1 = bias[col + 1];
            float c00 = acc[i][j][0] + b0, c01 = acc[i][j][1] + b1;
            float c10 = acc[i][j][2] + b0, c11 = acc[i][j][3] + b1;
            if (OUTMODE == 2) {
                *(float2*)&Cf[(size_t)row0 * 1024 + col]       = make_float2(c00, c01);
                *(float2*)&Cf[(size_t)(row0 + 8) * 1024 + col] = make_float2(c10, c11);
            } else {
                size_t d0, d1;
                if (OUTMODE == 0) {
                    int bI = row0 >> 11, s = row0 & 2047, h = col >> 6, d = col & 63;
                    d0 = (((size_t)(bI * 16 + h) * 2048 + s) * 64 + d);
                    d1 = d0 + 8 * 64;
                } else {
                    d0 = (size_t)row0 * 1024 + col;
                    d1 = d0 + 8 * 1024;
                }
                uint32_t hu, lu;
                sp2(c00, c01, hu, lu);
                *(uint32_t*)&Ch[d0] = hu; *(uint32_t*)&Cl[d0] = lu;
                sp2(c10, c11, hu, lu);
                *(uint32_t*)&Ch[d1] = hu; *(uint32_t*)&Cl[d1] = lu;
            }
        }
    }
}

// ---------------------------------------------------------------------------
__global__ void vtrans(const __nv_bfloat16* __restrict__ ih,
                       const __nv_bfloat16* __restrict__ il,
                       __nv_bfloat16* __restrict__ oh,
                       __nv_bfloat16* __restrict__ ol) {
    __shared__ __nv_bfloat16 t[64][72];
    const int s0 = blockIdx.x * 64;
    const int bh = blockIdx.y;
    const int tid = threadIdx.x;

    for (int pass = 0; pass < 2; pass++) {
        const __nv_bfloat16* src = pass ? il : ih;
        __nv_bfloat16* dst = pass ? ol : oh;
        #pragma unroll
        for (int r = 0; r < 8; r++) {
            int c = tid + r * 256;
            int row = c >> 5, c2 = (c & 31) * 2;
            *(uint32_t*)&t[row][c2] =
                *(const uint32_t*)&src[((size_t)bh * 2048 + s0 + row) * 64 + c2];
        }
        __syncthreads();
        #pragma unroll
        for (int r = 0; r < 8; r++) {
            int c = tid + r * 256;
            int d = c >> 5, s2 = (c & 31) * 2;
            __nv_bfloat162 p(t[s2][d], t[s2 + 1][d]);
            *(uint32_t*)&dst[((size_t)bh * 64 + d) * 2048 + s0 + s2] =
                *(uint32_t*)&p;
        }
        __syncthreads();
    }
}

// ---------------------------------------------------------------------------
// Fused attention (R4 structure): Pass A writes raw S + online stats,
// Pass B re-reads S, normalizes (write P once), AV from smem.
// ONLY change vs R4: __launch_bounds__(256, 2) -> 2 CTAs/SM.
// smem/CTA = 114176 B; 2x = 228352 <= 228KB carveout.
// ---------------------------------------------------------------------------
#define PQ 72
#define PV 72
#define ATTN_SMEM (55296 * 2 + 896 * 4)

__global__ void __launch_bounds__(256, 2)
attn_bf16(float* __restrict__ alpha,
          __nv_bfloat16* __restrict__ AOh, __nv_bfloat16* __restrict__ AOl) {
    extern __shared__ __nv_bfloat16 dsm[];
    __nv_bfloat16* sQh = dsm;
    __nv_bfloat16* sQl = dsm + 9216;
    __nv_bfloat16* sKh0 = dsm + 18432;
    __nv_bfloat16* sKl0 = dsm + 27648;
    __nv_bfloat16* sKh1 = dsm + 36864;
    __nv_bfloat16* sKl1 = dsm + 46080;
    float* fsm  = (float*)(dsm + 55296);
    float* sM   = fsm;
    float* sF   = fsm + 128;
    float* sL   = fsm + 256;
    float* sRed = fsm + 384;

    const int tid = threadIdx.x;
    const int w = tid >> 5, lane = tid & 31, g = lane >> 2, t = lane & 3;
    const int mw = (w & 1) * 64;
    const int wc = w >> 1;
    const int q0 = blockIdx.x * 128;
    const int bh = blockIdx.y;

    const __nv_bfloat16* Qhb = g_Qh + ((size_t)bh * 2048 + q0) * 64;
    const __nv_bfloat16* Qlb = g_Ql + ((size_t)bh * 2048 + q0) * 64;
    const __nv_bfloat16* Khb = g_Kh + (size_t)bh * 2048 * 64;
    const __nv_bfloat16* Klb = g_Kl + (size_t)bh * 2048 * 64;
    const __nv_bfloat16* Vthb = g_Vth + (size_t)bh * 64 * 2048;
    const __nv_bfloat16* Vtlb = g_Vtl + (size_t)bh * 64 * 2048;
    float* Ab = alpha + ((size_t)bh * 2048 + q0) * 2048;

    const uint32_t smu = (uint32_t)__cvta_generic_to_shared(dsm);

    if (tid < 128) { sM[tid] = -3e38f; sL[tid] = 0.f; }

    // stage Q (once)
    #pragma unroll
    for (int r = 0; r < 4; r++) {
        int c = tid + r * 256;
        int row = c >> 3, q8 = (c & 7) * 8;
        uint32_t o = (uint32_t)(row * PQ + q8) * 2;
        size_t gi = (size_t)row * 64 + q8;
        cp16(smu + o,            Qhb + gi);
        cp16(smu + 9216 * 2 + o, Qlb + gi);
    }
    auto stageK = [&](int kt, int buf) {
        const uint32_t bh_off = (buf ? 36864u : 18432u) * 2;
        const uint32_t bl_off = (buf ? 46080u : 27648u) * 2;
        const size_t src = (size_t)kt * 128 * 64;
        #pragma unroll
        for (int r = 0; r < 4; r++) {
            int c = tid + r * 256;
            int row = c >> 3, q8 = (c & 7) * 8;
            uint32_t o = (uint32_t)(row * PQ + q8) * 2;
            cp16(smu + bh_off + o, Khb + src + (size_t)row * 64 + q8);
            cp16(smu + bl_off + o, Klb + src + (size_t)row * 64 + q8);
        }
    };
    stageK(0, 0);
    CP_COMMIT;

    // =================== PASS A ===================
    for (int kt = 0; kt < 16; kt++) {
        const __nv_bfloat16* pKh = (kt & 1) ? sKh1 : sKh0;
        const __nv_bfloat16* pKl = (kt & 1) ? sKl1 : sKl0;
        if (kt + 1 < 16) { stageK(kt + 1, (kt & 1) ^ 1); CP_COMMIT; CP_WAIT1; }
        else             { CP_WAIT0; }
        __syncthreads();

        float acc[4][4][4] = {};
        #pragma unroll
        for (int ks = 0; ks < 64; ks += 16) {
            uint32_t kh[4][2], kl[4][2];
            #pragma unroll
            for (int j = 0; j < 4; j++) {
                const int n = wc * 32 + j * 8 + g;
                kh[j][0] = *(const uint32_t*)&pKh[n * PQ + ks + 2 * t];
                kh[j][1] = *(const uint32_t*)&pKh[n * PQ + ks + 2 * t + 8];
                kl[j][0] = *(const uint32_t*)&pKl[n * PQ + ks + 2 * t];
                kl[j][1] = *(const uint32_t*)&pKl[n * PQ + ks + 2 * t + 8];
            }
            #pragma unroll
            for (int i = 0; i < 4; i++) {
                const int m = mw + i * 16 + g;
                uint32_t qh0 = *(const uint32_t*)&sQh[m * PQ + ks + 2 * t];
                uint32_t qh1 = *(const uint32_t*)&sQh[(m + 8) * PQ + ks + 2 * t];
                uint32_t qh2 = *(const uint32_t*)&sQh[m * PQ + ks + 2 * t + 8];
                uint32_t qh3 = *(const uint32_t*)&sQh[(m + 8) * PQ + ks + 2 * t + 8];
                uint32_t ql0 = *(const uint32_t*)&sQl[m * PQ + ks + 2 * t];
                uint32_t ql1 = *(const uint32_t*)&sQl[(m + 8) * PQ + ks + 2 * t];
                uint32_t ql2 = *(const uint32_t*)&sQl[m * PQ + ks + 2 * t + 8];
                uint32_t ql3 = *(const uint32_t*)&sQl[(m + 8) * PQ + ks + 2 * t + 8];
                #pragma unroll
                for (int j = 0; j < 4; j++) {
                    mma_bf16(acc[i][j], qh0, qh1, qh2, qh3, kh[j][0], kh[j][1]);
                    mma_bf16(acc[i][j], ql0, ql1, ql2, ql3, kh[j][0], kh[j][1]);
                    mma_bf16(acc[i][j], qh0, qh1, qh2, qh3, kl[j][0], kl[j][1]);
                }
            }
        }
        // scale + write raw S
        #pragma unroll
        for (int i = 0; i < 4; i++)
            #pragma unroll
            for (int j = 0; j < 4; j++)
                #pragma unroll
                for (int r = 0; r < 4; r++) acc[i][j][r] *= 0.125f;

        #pragma unroll
        for (int i = 0; i < 4; i++) {
            const int row = mw + i * 16 + g;
            #pragma unroll
            for (int j = 0; j < 4; j++) {
                const int cc = kt * 128 + wc * 32 + j * 8 + t * 2;
                *(float2*)&Ab[(size_t)row * 2048 + cc]       = make_float2(acc[i][j][0], acc[i][j][1]);
                *(float2*)&Ab[(size_t)(row + 8) * 2048 + cc] = make_float2(acc[i][j][2], acc[i][j][3]);
            }
        }

        // ---- row max ----
        float rmax[8];
        #pragma unroll
        for (int i = 0; i < 4; i++) {
            float m0v = -3e38f, m1v = -3e38f;
            #pragma unroll
            for (int j = 0; j < 4; j++) {
                m0v = fmaxf(m0v, fmaxf(acc[i][j][0], acc[i][j][1]));
                m1v = fmaxf(m1v, fmaxf(acc[i][j][2], acc[i][j][3]));
            }
            rmax[i * 2] = m0v; rmax[i * 2 + 1] = m1v;
        }
        #pragma unroll
        for (int o = 1; o <= 2; o <<= 1)
            #pragma unroll
            for (int e = 0; e < 8; e++)
                rmax[e] = fmaxf(rmax[e], __shfl_xor_sync(0xffffffffu, rmax[e], o));
        if (t == 0) {
            #pragma unroll
            for (int i = 0; i < 4; i++) {
                sRed[wc * 128 + mw + i * 16 + g]     = rmax[i * 2];
                sRed[wc * 128 + mw + i * 16 + g + 8] = rmax[i * 2 + 1];
            }
        }
        __syncthreads();
        if (tid < 128) {
            float tm = fmaxf(fmaxf(sRed[tid], sRed[128 + tid]),
                             fmaxf(sRed[256 + tid], sRed[384 + tid]));
            float mo = sM[tid];
            float mn = fmaxf(mo, tm);
            sM[tid] = mn;
            sF[tid] = __expf(mo - mn);
        }
        __syncthreads();

        // ---- row sum of exp ----
        float rsum[8];
        #pragma unroll
        for (int i = 0; i < 4; i++) {
            const int row = mw + i * 16 + g;
            const float mn0 = sM[row], mn1 = sM[row + 8];
            float s0 = 0.f, s1 = 0.f;
            #pragma unroll
            for (int j = 0; j < 4; j++) {
                s0 += __expf(acc[i][j][0] - mn0) + __expf(acc[i][j][1] - mn0);
                s1 += __expf(acc[i][j][2] - mn1) + __expf(acc[i][j][3] - mn1);
            }
            rsum[i * 2] = s0; rsum[i * 2 + 1] = s1;
        }
        #pragma unroll
        for (int o = 1; o <= 2; o <<= 1)
            #pragma unroll
            for (int e = 0; e < 8; e++)
                rsum[e] += __shfl_xor_sync(0xffffffffu, rsum[e], o);
        if (t == 0) {
            #pragma unroll
            for (int i = 0; i < 4; i++) {
                sRed[wc * 128 + mw + i * 16 + g]     = rsum[i * 2];
                sRed[wc * 128 + mw + i * 16 + g + 8] = rsum[i * 2 + 1];
            }
        }
        __syncthreads();
        if (tid < 128) {
            sL[tid] = sL[tid] * sF[tid] +
                      (sRed[tid] + sRed[128 + tid] + sRed[256 + tid] + sRed[384 + tid]);
        }
        __syncthreads();
    }

    if (tid < 128) sL[tid] = 1.0f / sL[tid];
    __syncthreads();

    // =================== PASS B ===================
    __nv_bfloat16* sPh = sKh0;
    __nv_bfloat16* sPl = sKl0;
    __nv_bfloat16* sVh = sQh;   // 64 x PV
    __nv_bfloat16* sVl = sQl;

    float accO[4][2][4] = {};
    const int pr = tid & 127;
    const int pc = (tid >> 7) * 32;
    const float rm = sM[pr];
    const float rl = sL[pr];

    for (int ch = 0; ch < 32; ch++) {
        const int kb = ch * 64;
        // stage Vt chunk: 64 d-rows x 64 s
        #pragma unroll
        for (int r = 0; r < 2; r++) {
            int c = tid + r * 256;
            int d = c >> 3, q8 = (c & 7) * 8;
            uint32_t o = (uint32_t)(d * PV + q8) * 2;
            size_t gi = (size_t)d * 2048 + kb + q8;
            cp16(smu + o,            Vthb + gi);
            cp16(smu + 9216 * 2 + o, Vtlb + gi);
        }
        CP_COMMIT;

        // P: read raw S, normalize, write alpha fp32 + smem bf16 split
        {
            float* rowp = Ab + (size_t)pr * 2048 + kb + pc;
            #pragma unroll
            for (int u = 0; u < 8; u++) {
                float4 s4 = *(const float4*)(rowp + u * 4);
                float4 p4;
                p4.x = __expf(s4.x - rm) * rl;
                p4.y = __expf(s4.y - rm) * rl;
                p4.z = __expf(s4.z - rm) * rl;
                p4.w = __expf(s4.w - rm) * rl;
                *(float4*)(rowp + u * 4) = p4;
                uint32_t hu, lu;
                sp2(p4.x, p4.y, hu, lu);
                *(uint32_t*)&sPh[pr * PQ + pc + u * 4]     = hu;
                *(uint32_t*)&sPl[pr * PQ + pc + u * 4]     = lu;
                sp2(p4.z, p4.w, hu, lu);
                *(uint32_t*)&sPh[pr * PQ + pc + u * 4 + 2] = hu;
                *(uint32_t*)&sPl[pr * PQ + pc + u * 4 + 2] = lu;
            }
        }
        CP_WAIT0;
        __syncthreads();

        // O += P * V
        #pragma unroll
        for (int ks = 0; ks < 64; ks += 16) {
            uint32_t vh[2][2], vl[2][2];
            #pragma unroll
            for (int j = 0; j < 2; j++) {
                const int n = wc * 16 + j * 8 + g;
                vh[j][0] = *(const uint32_t*)&sVh[n * PV + ks + 2 * t];
                vh[j][1] = *(const uint32_t*)&sVh[n * PV + ks + 2 * t + 8];
                vl[j][0] = *(const uint32_t*)&sVl[n * PV + ks + 2 * t];
                vl[j][1] = *(const uint32_t*)&sVl[n * PV + ks + 2 * t + 8];
            }
            #pragma unroll
            for (int i = 0; i < 4; i++) {
                const int m = mw + i * 16 + g;
                uint32_t ph0 = *(const uint32_t*)&sPh[m * PQ + ks + 2 * t];
                uint32_t ph1 = *(const uint32_t*)&sPh[(m + 8) * PQ + ks + 2 * t];
                uint32_t ph2 = *(const uint32_t*)&sPh[m * PQ + ks + 2 * t + 8];
                uint32_t ph3 = *(const uint32_t*)&sPh[(m + 8) * PQ + ks + 2 * t + 8];
                uint32_t pl0 = *(const uint32_t*)&sPl[m * PQ + ks + 2 * t];
                uint32_t pl1 = *(const uint32_t*)&sPl[(m + 8) * PQ + ks + 2 * t];
                uint32_t pl2 = *(const uint32_t*)&sPl[m * PQ + ks + 2 * t + 8];
                uint32_t pl3 = *(const uint32_t*)&sPl[(m + 8) * PQ + ks + 2 * t + 8];
                #pragma unroll
                for (int j = 0; j < 2; j++) {
                    mma_bf16(accO[i][j], ph0, ph1, ph2, ph3, vh[j][0], vh[j][1]);
                    mma_bf16(accO[i][j], pl0, pl1, pl2, pl3, vh[j][0], vh[j][1]);
                    mma_bf16(accO[i][j], ph0, ph1, ph2, ph3, vl[j][0], vl[j][1]);
                }
            }
        }
        __syncthreads();
    }

    // epilogue: AO split (flat [row][1024], col = h*64 + d)
    const int b = bh >> 4, h = bh & 15;
    #pragma unroll
    for (int i = 0; i < 4; i++) {
        #pragma unroll
        for (int j = 0; j < 2; j++) {
            const int row = q0 + mw + i * 16 + g;
            const int col = h * 64 + wc * 16 + j * 8 + t * 2;
            uint32_t hu, lu;
            size_t d0 = ((size_t)(b * 2048 + row)) * 1024 + col;
            sp2(accO[i][j][0], accO[i][j][1], hu, lu);
            *(uint32_t*)&AOh[d0] = hu; *(uint32_t*)&AOl[d0] = lu;
            size_t d1 = ((size_t)(b * 2048 + row + 8)) * 1024 + col;
            sp2(accO[i][j][2], accO[i][j][3], hu, lu);
            *(uint32_t*)&AOh[d1] = hu; *(uint32_t*)&AOl[d1] = lu;
        }
    }
}

// ---------------------------------------------------------------------------
extern "C" void kernel_launch(void* const* d_in, const int* in_sizes, int n_in,
                              void* d_out, int out_size) {
    const float* q  = (const float*)d_in[0];
    const float* k  = (const float*)d_in[1];
    const float* v  = (const float*)d_in[2];
    const float* Wq = (const float*)d_in[3];
    const float* bq = (const float*)d_in[4];
    const float* Wk = (const float*)d_in[5];
    const float* bk = (const float*)d_in[6];
    const float* Wv = (const float*)d_in[7];
    const float* bv = (const float*)d_in[8];
    const float* Wo = (const float*)d_in[9];
    const float* bo = (const float*)d_in[10];

    float* out   = (float*)d_out;
    float* alpha = out + (size_t)B_ * S_ * D_;

    __nv_bfloat16 *qh,*ql,*kh,*kl,*vh,*vl;
    __nv_bfloat16 *Wqh,*Wql,*Wkh,*Wkl,*Wvh,*Wvl,*Woh,*Wol;
    __nv_bfloat16 *Qh,*Ql,*Kh,*Kl,*Vph,*Vpl,*Vth,*Vtl,*AOh,*AOl;
    cudaGetSymbolAddress((void**)&qh, g_qh);   cudaGetSymbolAddress((void**)&ql, g_ql);
    cudaGetSymbolAddress((void**)&kh, g_kh);   cudaGetSymbolAddress((void**)&kl, g_kl);
    cudaGetSymbolAddress((void**)&vh, g_vh);   cudaGetSymbolAddress((void**)&vl, g_vl);
    cudaGetSymbolAddress((void**)&Wqh, g_Wqh); cudaGetSymbolAddress((void**)&Wql, g_Wql);
    cudaGetSymbolAddress((void**)&Wkh, g_Wkh); cudaGetSymbolAddress((void**)&Wkl, g_Wkl);
    cudaGetSymbolAddress((void**)&Wvh, g_Wvh); cudaGetSymbolAddress((void**)&Wvl, g_Wvl);
    cudaGetSymbolAddress((void**)&Woh, g_Woh); cudaGetSymbolAddress((void**)&Wol, g_Wol);
    cudaGetSymbolAddress((void**)&Qh, g_Qh);   cudaGetSymbolAddress((void**)&Ql, g_Ql);
    cudaGetSymbolAddress((void**)&Kh, g_Kh);   cudaGetSymbolAddress((void**)&Kl, g_Kl);
    cudaGetSymbolAddress((void**)&Vph, g_Vph); cudaGetSymbolAddress((void**)&Vpl, g_Vpl);
    cudaGetSymbolAddress((void**)&Vth, g_Vth); cudaGetSymbolAddress((void**)&Vtl, g_Vtl);
    cudaGetSymbolAddress((void**)&AOh, g_AOh); cudaGetSymbolAddress((void**)&AOl, g_AOl);

    static bool attr_set = false;
    if (!attr_set) {
        cudaFuncSetAttribute(proj_bf16<0>, cudaFuncAttributeMaxDynamicSharedMemorySize, PROJ_SMEM);
        cudaFuncSetAttribute(proj_bf16<2>, cudaFuncAttributeMaxDynamicSharedMemorySize, PROJ_SMEM);
        cudaFuncSetAttribute(attn_bf16, cudaFuncAttributeMaxDynamicSharedMemorySize, ATTN_SMEM);
        attr_set = true;
    }

    const int n4 = BS_ * HD_ / 4;
    split_in<<<(n4 + 255) / 256, 256>>>(q, qh, ql, n4);
    split_in<<<(n4 + 255) / 256, 256>>>(k, kh, kl, n4);
    split_in<<<(n4 + 255) / 256, 256>>>(v, vh, vl, n4);

    dim3 gW(32, 32), bW(32, 8);
    wsplit<<<gW, bW>>>(Wq, Wqh, Wql);
    wsplit<<<gW, bW>>>(Wk, Wkh, Wkl);
    wsplit<<<gW, bW>>>(Wv, Wvh, Wvl);
    wsplit<<<gW, bW>>>(Wo, Woh, Wol);

    dim3 gProj(HD_ / 128, BS_ / 128);   // (8, 64)
    proj_bf16<0><<<gProj, 256, PROJ_SMEM>>>(qh, ql, Wqh, Wql, bq, Qh, Ql, nullptr);
    proj_bf16<0><<<gProj, 256, PROJ_SMEM>>>(kh, kl, Wkh, Wkl, bk, Kh, Kl, nullptr);
    proj_bf16<0><<<gProj, 256, PROJ_SMEM>>>(vh, vl, Wvh, Wvl, bv, Vph, Vpl, nullptr);

    vtrans<<<dim3(32, 64), 256>>>(Vph, Vpl, Vth, Vtl);

    dim3 gAttn(S_ / 128, B_ * H_);      // (16, 64)
    attn_bf16<<<gAttn, 256, ATTN_SMEM>>>(alpha, AOh, AOl);

    proj_bf16<2><<<gProj, 256, PROJ_SMEM>>>(AOh, AOl, Woh, Wol, bo, nullptr, nullptr, out);
}

// round 10
// speedup vs baseline: 1.2524x; 1.0217x over previous
#include <cuda_runtime.h>
#include <cuda_bf16.h>
#include <cstdint>

#define B_ 4
#define S_ 2048
#define D_ 1024
#define H_ 16
#define DH_ 64
#define BS_ 8192
#define HD_ 1024

// ---------------- scratch (bf16 hi/lo splits) ----------------
__device__ __nv_bfloat16 g_qh[BS_*HD_], g_ql[BS_*HD_];
__device__ __nv_bfloat16 g_kh[BS_*HD_], g_kl[BS_*HD_];
__device__ __nv_bfloat16 g_vh[BS_*HD_], g_vl[BS_*HD_];
__device__ __nv_bfloat16 g_Wqh[D_*HD_], g_Wql[D_*HD_];
__device__ __nv_bfloat16 g_Wkh[D_*HD_], g_Wkl[D_*HD_];
__device__ __nv_bfloat16 g_Wvh[D_*HD_], g_Wvl[D_*HD_];
__device__ __nv_bfloat16 g_Woh[HD_*D_], g_Wol[HD_*D_];
__device__ __nv_bfloat16 g_Qh[BS_*HD_], g_Ql[BS_*HD_];   // [bh][s][dh]
__device__ __nv_bfloat16 g_Kh[BS_*HD_], g_Kl[BS_*HD_];   // [bh][s][dh]
__device__ __nv_bfloat16 g_Vph[BS_*HD_], g_Vpl[BS_*HD_]; // [bh][s][dh]
__device__ __nv_bfloat16 g_Vth[BS_*HD_], g_Vtl[BS_*HD_]; // [bh][dh][s]
__device__ __nv_bfloat16 g_AOh[BS_*HD_], g_AOl[BS_*HD_]; // [row][1024]

// ---------------- helpers ----------------
__device__ __forceinline__ void sp2(float a, float b, uint32_t& h, uint32_t& l) {
    __nv_bfloat16 ha = __float2bfloat16(a), hb = __float2bfloat16(b);
    float la = a - __bfloat162float(ha);
    float lb = b - __bfloat162float(hb);
    __nv_bfloat162 hp(ha, hb);
    __nv_bfloat162 lp(__float2bfloat16(la), __float2bfloat16(lb));
    h = *reinterpret_cast<uint32_t*>(&hp);
    l = *reinterpret_cast<uint32_t*>(&lp);
}

__device__ __forceinline__ void mma_bf16(float* d, uint32_t a0, uint32_t a1,
                                         uint32_t a2, uint32_t a3,
                                         uint32_t b0, uint32_t b1) {
    asm volatile(
        "mma.sync.aligned.m16n8k16.row.col.f32.bf16.bf16.f32 "
        "{%0,%1,%2,%3}, {%4,%5,%6,%7}, {%8,%9}, {%0,%1,%2,%3};"
        : "+f"(d[0]), "+f"(d[1]), "+f"(d[2]), "+f"(d[3])
        : "r"(a0), "r"(a1), "r"(a2), "r"(a3), "r"(b0), "r"(b1));
}

__device__ __forceinline__ void cp16(uint32_t s, const void* g) {
    asm volatile("cp.async.cg.shared.global [%0], [%1], 16;" :: "r"(s), "l"(g));
}
#define CP_COMMIT asm volatile("cp.async.commit_group;")
#define CP_WAIT0  asm volatile("cp.async.wait_group 0;" ::: "memory")
#define CP_WAIT1  asm volatile("cp.async.wait_group 1;" ::: "memory")

// ---------------------------------------------------------------------------
__global__ void split_in(const float* __restrict__ x,
                         __nv_bfloat16* __restrict__ hi,
                         __nv_bfloat16* __restrict__ lo, int n4) {
    int i = blockIdx.x * blockDim.x + threadIdx.x;
    if (i < n4) {
        float4 v = ((const float4*)x)[i];
        uint2 hh, ll;
        sp2(v.x, v.y, hh.x, ll.x);
        sp2(v.z, v.w, hh.y, ll.y);
        ((uint2*)hi)[i] = hh;
        ((uint2*)lo)[i] = ll;
    }
}

// ---------------------------------------------------------------------------
__global__ void wsplit(const float* __restrict__ W,
                       __nv_bfloat16* __restrict__ th,
                       __nv_bfloat16* __restrict__ tl) {
    __shared__ float t[32][33];
    const int k0 = blockIdx.y * 32, n0 = blockIdx.x * 32;
    const int tx = threadIdx.x, ty = threadIdx.y;
    #pragma unroll
    for (int r = 0; r < 4; r++)
        t[ty + r * 8][tx] = W[(size_t)(k0 + ty + r * 8) * 1024 + n0 + tx];
    __syncthreads();
    #pragma unroll
    for (int r = 0; r < 4; r++) {
        int n = ty + r * 8;
        float v = t[tx][n];
        __nv_bfloat16 hb = __float2bfloat16(v);
        float l = v - __bfloat162float(hb);
        th[(size_t)(n0 + n) * 1024 + k0 + tx] = hb;
        tl[(size_t)(n0 + n) * 1024 + k0 + tx] = __float2bfloat16(l);
    }
}

// ---------------------------------------------------------------------------
// Projection GEMM (bf16 3-term) — identical to the 2163us baseline.
// ---------------------------------------------------------------------------
#define PK 40
#define PROJ_SMEM (2 * 4 * 128 * PK * 2)

template<int OUTMODE>
__global__ void __launch_bounds__(256, 2)
proj_bf16(const __nv_bfloat16* __restrict__ Ah, const __nv_bfloat16* __restrict__ Al,
          const __nv_bfloat16* __restrict__ Bh, const __nv_bfloat16* __restrict__ Bl,
          const float* __restrict__ bias,
          __nv_bfloat16* __restrict__ Ch, __nv_bfloat16* __restrict__ Cl,
          float* __restrict__ Cf) {
    extern __shared__ __nv_bfloat16 dsm[];
    const int BUF = 4 * 128 * PK;
    __nv_bfloat16* base = dsm;

    const int tid = threadIdx.x;
    const int m0 = blockIdx.y * 128, n0 = blockIdx.x * 128;
    const int w = tid >> 5, lane = tid & 31, g = lane >> 2, t = lane & 3;
    const int mw = (w & 1) * 64, nw = (w >> 1) * 32;

    const uint32_t smu = (uint32_t)__cvta_generic_to_shared(dsm);

    float acc[4][4][4] = {};

    auto stage = [&](int it, int buf) {
        const int k0 = it * 32;
        const uint32_t bu = smu + (uint32_t)buf * BUF * 2;
        #pragma unroll
        for (int r = 0; r < 2; r++) {
            int c = tid + r * 256;
            int row = c >> 2, q8 = (c & 3) * 8;
            uint32_t o = (uint32_t)(row * PK + q8) * 2;
            size_t gi = (size_t)(m0 + row) * 1024 + k0 + q8;
            cp16(bu + o,                       Ah + gi);
            cp16(bu + 128 * PK * 2 + o,        Al + gi);
            size_t gb = (size_t)(n0 + row) * 1024 + k0 + q8;
            cp16(bu + 2 * 128 * PK * 2 + o,    Bh + gb);
            cp16(bu + 3 * 128 * PK * 2 + o,    Bl + gb);
        }
    };

    stage(0, 0); CP_COMMIT;

    for (int it = 0; it < 32; it++) {
        const int buf = it & 1;
        if (it + 1 < 32) { stage(it + 1, buf ^ 1); CP_COMMIT; CP_WAIT1; }
        else             { CP_WAIT0; }
        __syncthreads();

        const __nv_bfloat16* pAh = base + buf * BUF;
        const __nv_bfloat16* pAl = pAh + 128 * PK;
        const __nv_bfloat16* pBh = pAl + 128 * PK;
        const __nv_bfloat16* pBl = pBh + 128 * PK;

        #pragma unroll
        for (int ks = 0; ks < 32; ks += 16) {
            uint32_t bh[4][2], bl[4][2];
            #pragma unroll
            for (int j = 0; j < 4; j++) {
                const int n = nw + j * 8 + g;
                bh[j][0] = *(const uint32_t*)&pBh[n * PK + ks + 2 * t];
                bh[j][1] = *(const uint32_t*)&pBh[n * PK + ks + 2 * t + 8];
                bl[j][0] = *(const uint32_t*)&pBl[n * PK + ks + 2 * t];
                bl[j][1] = *(const uint32_t*)&pBl[n * PK + ks + 2 * t + 8];
            }
            #pragma unroll
            for (int i = 0; i < 4; i++) {
                const int m = mw + i * 16 + g;
                uint32_t ah0 = *(const uint32_t*)&pAh[m * PK + ks + 2 * t];
                uint32_t ah1 = *(const uint32_t*)&pAh[(m + 8) * PK + ks + 2 * t];
                uint32_t ah2 = *(const uint32_t*)&pAh[m * PK + ks + 2 * t + 8];
                uint32_t ah3 = *(const uint32_t*)&pAh[(m + 8) * PK + ks + 2 * t + 8];
                uint32_t al0 = *(const uint32_t*)&pAl[m * PK + ks + 2 * t];
                uint32_t al1 = *(const uint32_t*)&pAl[(m + 8) * PK + ks + 2 * t];
                uint32_t al2 = *(const uint32_t*)&pAl[m * PK + ks + 2 * t + 8];
                uint32_t al3 = *(const uint32_t*)&pAl[(m + 8) * PK + ks + 2 * t + 8];
                #pragma unroll
                for (int j = 0; j < 4; j++) {
                    mma_bf16(acc[i][j], ah0, ah1, ah2, ah3, bh[j][0], bh[j][1]);
                    mma_bf16(acc[i][j], al0, al1, al2, al3, bh[j][0], bh[j][1]);
                    mma_bf16(acc[i][j], ah0, ah1, ah2, ah3, bl[j][0], bl[j][1]);
                }
            }
        }
        __syncthreads();
    }

    #pragma unroll
    for (int i = 0; i < 4; i++) {
        #pragma unroll
        for (int j = 0; j < 4; j++) {
            const int row0 = m0 + mw + i * 16 + g;
            const int col  = n0 + nw + j * 8 + t * 2;
            const float b0 = bias[col], b1 = bias[col + 1];
            float c00 = acc[i][j][0] + b0, c01 = acc[i][j][1] + b1;
            float c10 = acc[i][j][2] + b0, c11 = acc[i][j][3] + b1;
            if (OUTMODE == 2) {
                *(float2*)&Cf[(size_t)row0 * 1024 + col]       = make_float2(c00, c01);
                *(float2*)&Cf[(size_t)(row0 + 8) * 1024 + col] = make_float2(c10, c11);
            } else {
                size_t d0, d1;
                if (OUTMODE == 0) {
                    int bI = row0 >> 11, s = row0 & 2047, h = col >> 6, d = col & 63;
                    d0 = (((size_t)(bI * 16 + h) * 2048 + s) * 64 + d);
                    d1 = d0 + 8 * 64;
                } else {
                    d0 = (size_t)row0 * 1024 + col;
                    d1 = d0 + 8 * 1024;
                }
                uint32_t hu, lu;
                sp2(c00, c01, hu, lu);
                *(uint32_t*)&Ch[d0] = hu; *(uint32_t*)&Cl[d0] = lu;
                sp2(c10, c11, hu, lu);
                *(uint32_t*)&Ch[d1] = hu; *(uint32_t*)&Cl[d1] = lu;
            }
        }
    }
}

// ---------------------------------------------------------------------------
__global__ void vtrans(const __nv_bfloat16* __restrict__ ih,
                       const __nv_bfloat16* __restrict__ il,
                       __nv_bfloat16* __restrict__ oh,
                       __nv_bfloat16* __restrict__ ol) {
    __shared__ __nv_bfloat16 t[64][72];
    const int s0 = blockIdx.x * 64;
    const int bh = blockIdx.y;
    const int tid = threadIdx.x;

    for (int pass = 0; pass < 2; pass++) {
        const __nv_bfloat16* src = pass ? il : ih;
        __nv_bfloat16* dst = pass ? ol : oh;
        #pragma unroll
        for (int r = 0; r < 8; r++) {
            int c = tid + r * 256;
            int row = c >> 5, c2 = (c & 31) * 2;
            *(uint32_t*)&t[row][c2] =
                *(const uint32_t*)&src[((size_t)bh * 2048 + s0 + row) * 64 + c2];
        }
        __syncthreads();
        #pragma unroll
        for (int r = 0; r < 8; r++) {
            int c = tid + r * 256;
            int d = c >> 5, s2 = (c & 31) * 2;
            __nv_bfloat162 p(t[s2][d], t[s2 + 1][d]);
            *(uint32_t*)&dst[((size_t)bh * 64 + d) * 2048 + s0 + s2] =
                *(uint32_t*)&p;
        }
        __syncthreads();
    }
}

// ---------------------------------------------------------------------------
// Fused attention (R4 structure, exp-once):
// PASS A: compute S tile, row-max update -> m_kt; write e = exp(S - m_kt) to
//         alpha (the only exps), record m_kt per (kt,row) in sMt, accumulate l.
// PASS B: read e, P = e * exp(m_kt - m_final) / l (one exp per row*tile),
//         write P to alpha, split to smem, O += P*V.
// float region (at dsm+55296): sM[128] sF[128] sL[128] sRed[512] sMt[16*128]
// smem total = 110592 + 2944*4 = 122368 B -> 1 CTA/SM.
// ---------------------------------------------------------------------------
#define PQ 72
#define PV 72
#define ATTN_SMEM (55296 * 2 + 2944 * 4)

__global__ void __launch_bounds__(256, 1)
attn_bf16(float* __restrict__ alpha,
          __nv_bfloat16* __restrict__ AOh, __nv_bfloat16* __restrict__ AOl) {
    extern __shared__ __nv_bfloat16 dsm[];
    __nv_bfloat16* sQh = dsm;
    __nv_bfloat16* sQl = dsm + 9216;
    __nv_bfloat16* sKh0 = dsm + 18432;
    __nv_bfloat16* sKl0 = dsm + 27648;
    __nv_bfloat16* sKh1 = dsm + 36864;
    __nv_bfloat16* sKl1 = dsm + 46080;
    float* fsm  = (float*)(dsm + 55296);
    float* sM   = fsm;
    float* sF   = fsm + 128;
    float* sL   = fsm + 256;
    float* sRed = fsm + 384;
    float* sMt  = fsm + 896;          // [16][128]

    const int tid = threadIdx.x;
    const int w = tid >> 5, lane = tid & 31, g = lane >> 2, t = lane & 3;
    const int mw = (w & 1) * 64;
    const int wc = w >> 1;
    const int q0 = blockIdx.x * 128;
    const int bh = blockIdx.y;

    const __nv_bfloat16* Qhb = g_Qh + ((size_t)bh * 2048 + q0) * 64;
    const __nv_bfloat16* Qlb = g_Ql + ((size_t)bh * 2048 + q0) * 64;
    const __nv_bfloat16* Khb = g_Kh + (size_t)bh * 2048 * 64;
    const __nv_bfloat16* Klb = g_Kl + (size_t)bh * 2048 * 64;
    const __nv_bfloat16* Vthb = g_Vth + (size_t)bh * 64 * 2048;
    const __nv_bfloat16* Vtlb = g_Vtl + (size_t)bh * 64 * 2048;
    float* Ab = alpha + ((size_t)bh * 2048 + q0) * 2048;

    const uint32_t smu = (uint32_t)__cvta_generic_to_shared(dsm);

    if (tid < 128) { sM[tid] = -3e38f; sL[tid] = 0.f; }

    #pragma unroll
    for (int r = 0; r < 4; r++) {
        int c = tid + r * 256;
        int row = c >> 3, q8 = (c & 7) * 8;
        uint32_t o = (uint32_t)(row * PQ + q8) * 2;
        size_t gi = (size_t)row * 64 + q8;
        cp16(smu + o,            Qhb + gi);
        cp16(smu + 9216 * 2 + o, Qlb + gi);
    }
    auto stageK = [&](int kt, int buf) {
        const uint32_t bh_off = (buf ? 36864u : 18432u) * 2;
        const uint32_t bl_off = (buf ? 46080u : 27648u) * 2;
        const size_t src = (size_t)kt * 128 * 64;
        #pragma unroll
        for (int r = 0; r < 4; r++) {
            int c = tid + r * 256;
            int row = c >> 3, q8 = (c & 7) * 8;
            uint32_t o = (uint32_t)(row * PQ + q8) * 2;
            cp16(smu + bh_off + o, Khb + src + (size_t)row * 64 + q8);
            cp16(smu + bl_off + o, Klb + src + (size_t)row * 64 + q8);
        }
    };
    stageK(0, 0);
    CP_COMMIT;

    // =================== PASS A ===================
    for (int kt = 0; kt < 16; kt++) {
        const __nv_bfloat16* pKh = (kt & 1) ? sKh1 : sKh0;
        const __nv_bfloat16* pKl = (kt & 1) ? sKl1 : sKl0;
        if (kt + 1 < 16) { stageK(kt + 1, (kt & 1) ^ 1); CP_COMMIT; CP_WAIT1; }
        else             { CP_WAIT0; }
        __syncthreads();

        float acc[4][4][4] = {};
        #pragma unroll
        for (int ks = 0; ks < 64; ks += 16) {
            uint32_t kh[4][2], kl[4][2];
            #pragma unroll
            for (int j = 0; j < 4; j++) {
                const int n = wc * 32 + j * 8 + g;
                kh[j][0] = *(const uint32_t*)&pKh[n * PQ + ks + 2 * t];
                kh[j][1] = *(const uint32_t*)&pKh[n * PQ + ks + 2 * t + 8];
                kl[j][0] = *(const uint32_t*)&pKl[n * PQ + ks + 2 * t];
                kl[j][1] = *(const uint32_t*)&pKl[n * PQ + ks + 2 * t + 8];
            }
            #pragma unroll
            for (int i = 0; i < 4; i++) {
                const int m = mw + i * 16 + g;
                uint32_t qh0 = *(const uint32_t*)&sQh[m * PQ + ks + 2 * t];
                uint32_t qh1 = *(const uint32_t*)&sQh[(m + 8) * PQ + ks + 2 * t];
                uint32_t qh2 = *(const uint32_t*)&sQh[m * PQ + ks + 2 * t + 8];
                uint32_t qh3 = *(const uint32_t*)&sQh[(m + 8) * PQ + ks + 2 * t + 8];
                uint32_t ql0 = *(const uint32_t*)&sQl[m * PQ + ks + 2 * t];
                uint32_t ql1 = *(const uint32_t*)&sQl[(m + 8) * PQ + ks + 2 * t];
                uint32_t ql2 = *(const uint32_t*)&sQl[m * PQ + ks + 2 * t + 8];
                uint32_t ql3 = *(const uint32_t*)&sQl[(m + 8) * PQ + ks + 2 * t + 8];
                #pragma unroll
                for (int j = 0; j < 4; j++) {
                    mma_bf16(acc[i][j], qh0, qh1, qh2, qh3, kh[j][0], kh[j][1]);
                    mma_bf16(acc[i][j], ql0, ql1, ql2, ql3, kh[j][0], kh[j][1]);
                    mma_bf16(acc[i][j], qh0, qh1, qh2, qh3, kl[j][0], kl[j][1]);
                }
            }
        }
        #pragma unroll
        for (int i = 0; i < 4; i++)
            #pragma unroll
            for (int j = 0; j < 4; j++)
                #pragma unroll
                for (int r = 0; r < 4; r++) acc[i][j][r] *= 0.125f;

        // ---- row max ----
        float rmax[8];
        #pragma unroll
        for (int i = 0; i < 4; i++) {
            float m0v = -3e38f, m1v = -3e38f;
            #pragma unroll
            for (int j = 0; j < 4; j++) {
                m0v = fmaxf(m0v, fmaxf(acc[i][j][0], acc[i][j][1]));
                m1v = fmaxf(m1v, fmaxf(acc[i][j][2], acc[i][j][3]));
            }
            rmax[i * 2] = m0v; rmax[i * 2 + 1] = m1v;
        }
        #pragma unroll
        for (int o = 1; o <= 2; o <<= 1)
            #pragma unroll
            for (int e = 0; e < 8; e++)
                rmax[e] = fmaxf(rmax[e], __shfl_xor_sync(0xffffffffu, rmax[e], o));
        if (t == 0) {
            #pragma unroll
            for (int i = 0; i < 4; i++) {
                sRed[wc * 128 + mw + i * 16 + g]     = rmax[i * 2];
                sRed[wc * 128 + mw + i * 16 + g + 8] = rmax[i * 2 + 1];
            }
        }
        __syncthreads();
        if (tid < 128) {
            float tm = fmaxf(fmaxf(sRed[tid], sRed[128 + tid]),
                             fmaxf(sRed[256 + tid], sRed[384 + tid]));
            float mo = sM[tid];
            float mn = fmaxf(mo, tm);
            sM[tid] = mn;
            sF[tid] = __expf(mo - mn);
            sMt[kt * 128 + tid] = mn;          // m_kt used for this tile's e
        }
        __syncthreads();

        // ---- e = exp(S - m_kt) (overwrite acc), accumulate row sum ----
        float rsum[8];
        #pragma unroll
        for (int i = 0; i < 4; i++) {
            const int row = mw + i * 16 + g;
            const float mn0 = sM[row], mn1 = sM[row + 8];
            float s0 = 0.f, s1 = 0.f;
            #pragma unroll
            for (int j = 0; j < 4; j++) {
                acc[i][j][0] = __expf(acc[i][j][0] - mn0);
                acc[i][j][1] = __expf(acc[i][j][1] - mn0);
                acc[i][j][2] = __expf(acc[i][j][2] - mn1);
                acc[i][j][3] = __expf(acc[i][j][3] - mn1);
                s0 += acc[i][j][0] + acc[i][j][1];
                s1 += acc[i][j][2] + acc[i][j][3];
            }
            rsum[i * 2] = s0; rsum[i * 2 + 1] = s1;
        }

        // write e to alpha (only exp values ever stored)
        #pragma unroll
        for (int i = 0; i < 4; i++) {
            const int row = mw + i * 16 + g;
            #pragma unroll
            for (int j = 0; j < 4; j++) {
                const int cc = kt * 128 + wc * 32 + j * 8 + t * 2;
                *(float2*)&Ab[(size_t)row * 2048 + cc]       = make_float2(acc[i][j][0], acc[i][j][1]);
                *(float2*)&Ab[(size_t)(row + 8) * 2048 + cc] = make_float2(acc[i][j][2], acc[i][j][3]);
            }
        }

        #pragma unroll
        for (int o = 1; o <= 2; o <<= 1)
            #pragma unroll
            for (int e = 0; e < 8; e++)
                rsum[e] += __shfl_xor_sync(0xffffffffu, rsum[e], o);
        if (t == 0) {
            #pragma unroll
            for (int i = 0; i < 4; i++) {
                sRed[wc * 128 + mw + i * 16 + g]     = rsum[i * 2];
                sRed[wc * 128 + mw + i * 16 + g + 8] = rsum[i * 2 + 1];
            }
        }
        __syncthreads();
        if (tid < 128) {
            sL[tid] = sL[tid] * sF[tid] +
                      (sRed[tid] + sRed[128 + tid] + sRed[256 + tid] + sRed[384 + tid]);
        }
        __syncthreads();
    }

    if (tid < 128) sL[tid] = 1.0f / sL[tid];
    __syncthreads();

    // =================== PASS B ===================
    __nv_bfloat16* sPh = sKh0;
    __nv_bfloat16* sPl = sKl0;
    __nv_bfloat16* sVh = sQh;
    __nv_bfloat16* sVl = sQl;

    float accO[4][2][4] = {};
    const int pr = tid & 127;
    const int pc = (tid >> 7) * 32;
    const float rmF = sM[pr];
    const float rl  = sL[pr];

    for (int ch = 0; ch < 32; ch++) {
        const int kb = ch * 64;
        #pragma unroll
        for (int r = 0; r < 2; r++) {
            int c = tid + r * 256;
            int d = c >> 3, q8 = (c & 7) * 8;
            uint32_t o = (uint32_t)(d * PV + q8) * 2;
            size_t gi = (size_t)d * 2048 + kb + q8;
            cp16(smu + o,            Vthb + gi);
            cp16(smu + 9216 * 2 + o, Vtlb + gi);
        }
        CP_COMMIT;

        // P = e * exp(m_kt - m_final) * invl  (one exp per row per tile)
        {
            const int tile = ch >> 1;
            const float scale = __expf(sMt[tile * 128 + pr] - rmF) * rl;
            float* rowp = Ab + (size_t)pr * 2048 + kb + pc;
            #pragma unroll
            for (int u = 0; u < 8; u++) {
                float4 s4 = *(const float4*)(rowp + u * 4);
                float4 p4;
                p4.x = s4.x * scale;
                p4.y = s4.y * scale;
                p4.z = s4.z * scale;
                p4.w = s4.w * scale;
                *(float4*)(rowp + u * 4) = p4;
                uint32_t hu, lu;
                sp2(p4.x, p4.y, hu, lu);
                *(uint32_t*)&sPh[pr * PQ + pc + u * 4]     = hu;
                *(uint32_t*)&sPl[pr * PQ + pc + u * 4]     = lu;
                sp2(p4.z, p4.w, hu, lu);
                *(uint32_t*)&sPh[pr * PQ + pc + u * 4 + 2] = hu;
                *(uint32_t*)&sPl[pr * PQ + pc + u * 4 + 2] = lu;
            }
        }
        CP_WAIT0;
        __syncthreads();

        #pragma unroll
        for (int ks = 0; ks < 64; ks += 16) {
            uint32_t vh[2][2], vl[2][2];
            #pragma unroll
            for (int j = 0; j < 2; j++) {
                const int n = wc * 16 + j * 8 + g;
                vh[j][0] = *(const uint32_t*)&sVh[n * PV + ks + 2 * t];
                vh[j][1] = *(const uint32_t*)&sVh[n * PV + ks + 2 * t + 8];
                vl[j][0] = *(const uint32_t*)&sVl[n * PV + ks + 2 * t];
                vl[j][1] = *(const uint32_t*)&sVl[n * PV + ks + 2 * t + 8];
            }
            #pragma unroll
            for (int i = 0; i < 4; i++) {
                const int m = mw + i * 16 + g;
                uint32_t ph0 = *(const uint32_t*)&sPh[m * PQ + ks + 2 * t];
                uint32_t ph1 = *(const uint32_t*)&sPh[(m + 8) * PQ + ks + 2 * t];
                uint32_t ph2 = *(const uint32_t*)&sPh[m * PQ + ks + 2 * t + 8];
                uint32_t ph3 = *(const uint32_t*)&sPh[(m + 8) * PQ + ks + 2 * t + 8];
                uint32_t pl0 = *(const uint32_t*)&sPl[m * PQ + ks + 2 * t];
                uint32_t pl1 = *(const uint32_t*)&sPl[(m + 8) * PQ + ks + 2 * t];
                uint32_t pl2 = *(const uint32_t*)&sPl[m * PQ + ks + 2 * t + 8];
                uint32_t pl3 = *(const uint32_t*)&sPl[(m + 8) * PQ + ks + 2 * t + 8];
                #pragma unroll
                for (int j = 0; j < 2; j++) {
                    mma_bf16(accO[i][j], ph0, ph1, ph2, ph3, vh[j][0], vh[j][1]);
                    mma_bf16(accO[i][j], pl0, pl1, pl2, pl3, vh[j][0], vh[j][1]);
                    mma_bf16(accO[i][j], ph0, ph1, ph2, ph3, vl[j][0], vl[j][1]);
                }
            }
        }
        __syncthreads();
    }

    const int b = bh >> 4, h = bh & 15;
    #pragma unroll
    for (int i = 0; i < 4; i++) {
        #pragma unroll
        for (int j = 0; j < 2; j++) {
            const int row = q0 + mw + i * 16 + g;
            const int col = h * 64 + wc * 16 + j * 8 + t * 2;
            uint32_t hu, lu;
            size_t d0 = ((size_t)(b * 2048 + row)) * 1024 + col;
            sp2(accO[i][j][0], accO[i][j][1], hu, lu);
            *(uint32_t*)&AOh[d0] = hu; *(uint32_t*)&AOl[d0] = lu;
            size_t d1 = ((size_t)(b * 2048 + row + 8)) * 1024 + col;
            sp2(accO[i][j][2], accO[i][j][3], hu, lu);
            *(uint32_t*)&AOh[d1] = hu; *(uint32_t*)&AOl[d1] = lu;
        }
    }
}

// ---------------------------------------------------------------------------
extern "C" void kernel_launch(void* const* d_in, const int* in_sizes, int n_in,
                              void* d_out, int out_size) {
    const float* q  = (const float*)d_in[0];
    const float* k  = (const float*)d_in[1];
    const float* v  = (const float*)d_in[2];
    const float* Wq = (const float*)d_in[3];
    const float* bq = (const float*)d_in[4];
    const float* Wk = (const float*)d_in[5];
    const float* bk = (const float*)d_in[6];
    const float* Wv = (const float*)d_in[7];
    const float* bv = (const float*)d_in[8];
    const float* Wo = (const float*)d_in[9];
    const float* bo = (const float*)d_in[10];

    float* out   = (float*)d_out;
    float* alpha = out + (size_t)B_ * S_ * D_;

    __nv_bfloat16 *qh,*ql,*kh,*kl,*vh,*vl;
    __nv_bfloat16 *Wqh,*Wql,*Wkh,*Wkl,*Wvh,*Wvl,*Woh,*Wol;
    __nv_bfloat16 *Qh,*Ql,*Kh,*Kl,*Vph,*Vpl,*Vth,*Vtl,*AOh,*AOl;
    cudaGetSymbolAddress((void**)&qh, g_qh);   cudaGetSymbolAddress((void**)&ql, g_ql);
    cudaGetSymbolAddress((void**)&kh, g_kh);   cudaGetSymbolAddress((void**)&kl, g_kl);
    cudaGetSymbolAddress((void**)&vh, g_vh);   cudaGetSymbolAddress((void**)&vl, g_vl);
    cudaGetSymbolAddress((void**)&Wqh, g_Wqh); cudaGetSymbolAddress((void**)&Wql, g_Wql);
    cudaGetSymbolAddress((void**)&Wkh, g_Wkh); cudaGetSymbolAddress((void**)&Wkl, g_Wkl);
    cudaGetSymbolAddress((void**)&Wvh, g_Wvh); cudaGetSymbolAddress((void**)&Wvl, g_Wvl);
    cudaGetSymbolAddress((void**)&Woh, g_Woh); cudaGetSymbolAddress((void**)&Wol, g_Wol);
    cudaGetSymbolAddress((void**)&Qh, g_Qh);   cudaGetSymbolAddress((void**)&Ql, g_Ql);
    cudaGetSymbolAddress((void**)&Kh, g_Kh);   cudaGetSymbolAddress((void**)&Kl, g_Kl);
    cudaGetSymbolAddress((void**)&Vph, g_Vph); cudaGetSymbolAddress((void**)&Vpl, g_Vpl);
    cudaGetSymbolAddress((void**)&Vth, g_Vth); cudaGetSymbolAddress((void**)&Vtl, g_Vtl);
    cudaGetSymbolAddress((void**)&AOh, g_AOh); cudaGetSymbolAddress((void**)&AOl, g_AOl);

    static bool attr_set = false;
    if (!attr_set) {
        cudaFuncSetAttribute(proj_bf16<0>, cudaFuncAttributeMaxDynamicSharedMemorySize, PROJ_SMEM);
        cudaFuncSetAttribute(proj_bf16<2>, cudaFuncAttributeMaxDynamicSharedMemorySize, PROJ_SMEM);
        cudaFuncSetAttribute(attn_bf16, cudaFuncAttributeMaxDynamicSharedMemorySize, ATTN_SMEM);
        attr_set = true;
    }

    const int n4 = BS_ * HD_ / 4;
    split_in<<<(n4 + 255) / 256, 256>>>(q, qh, ql, n4);
    split_in<<<(n4 + 255) / 256, 256>>>(k, kh, kl, n4);
    split_in<<<(n4 + 255) / 256, 256>>>(v, vh, vl, n4);

    dim3 gW(32, 32), bW(32, 8);
    wsplit<<<gW, bW>>>(Wq, Wqh, Wql);
    wsplit<<<gW, bW>>>(Wk, Wkh, Wkl);
    wsplit<<<gW, bW>>>(Wv, Wvh, Wvl);
    wsplit<<<gW, bW>>>(Wo, Woh, Wol);

    dim3 gProj(HD_ / 128, BS_ / 128);   // (8, 64)
    proj_bf16<0><<<gProj, 256, PROJ_SMEM>>>(qh, ql, Wqh, Wql, bq, Qh, Ql, nullptr);
    proj_bf16<0><<<gProj, 256, PROJ_SMEM>>>(kh, kl, Wkh, Wkl, bk, Kh, Kl, nullptr);
    proj_bf16<0><<<gProj, 256, PROJ_SMEM>>>(vh, vl, Wvh, Wvl, bv, Vph, Vpl, nullptr);

    vtrans<<<dim3(32, 64), 256>>>(Vph, Vpl, Vth, Vtl);

    dim3 gAttn(S_ / 128, B_ * H_);      // (16, 64)
    attn_bf16<<<gAttn, 256, ATTN_SMEM>>>(alpha, AOh, AOl);

    proj_bf16<2><<<gProj, 256, PROJ_SMEM>>>(AOh, AOl, Woh, Wol, bo, nullptr, nullptr, out);
}

// round 11
// speedup vs baseline: 1.3086x; 1.0449x over previous
#include <cuda_runtime.h>
#include <cuda_bf16.h>
#include <cstdint>

#define B_ 4
#define S_ 2048
#define D_ 1024
#define H_ 16
#define DH_ 64
#define BS_ 8192
#define HD_ 1024

// ---------------- scratch (bf16 hi/lo splits) ----------------
__device__ __nv_bfloat16 g_qh[BS_*HD_], g_ql[BS_*HD_];
__device__ __nv_bfloat16 g_kh[BS_*HD_], g_kl[BS_*HD_];
__device__ __nv_bfloat16 g_vh[BS_*HD_], g_vl[BS_*HD_];
__device__ __nv_bfloat16 g_Wqh[D_*HD_], g_Wql[D_*HD_];
__device__ __nv_bfloat16 g_Wkh[D_*HD_], g_Wkl[D_*HD_];
__device__ __nv_bfloat16 g_Wvh[D_*HD_], g_Wvl[D_*HD_];
__device__ __nv_bfloat16 g_Woh[HD_*D_], g_Wol[HD_*D_];
__device__ __nv_bfloat16 g_Qh[BS_*HD_], g_Ql[BS_*HD_];   // [bh][s][dh]
__device__ __nv_bfloat16 g_Kh[BS_*HD_], g_Kl[BS_*HD_];   // [bh][s][dh]
__device__ __nv_bfloat16 g_Vph[BS_*HD_], g_Vpl[BS_*HD_]; // [bh][s][dh]
__device__ __nv_bfloat16 g_Vth[BS_*HD_], g_Vtl[BS_*HD_]; // [bh][dh][s]
__device__ __nv_bfloat16 g_AOh[BS_*HD_], g_AOl[BS_*HD_]; // [row][1024]

// ---------------- helpers ----------------
__device__ __forceinline__ void sp2(float a, float b, uint32_t& h, uint32_t& l) {
    __nv_bfloat16 ha = __float2bfloat16(a), hb = __float2bfloat16(b);
    float la = a - __bfloat162float(ha);
    float lb = b - __bfloat162float(hb);
    __nv_bfloat162 hp(ha, hb);
    __nv_bfloat162 lp(__float2bfloat16(la), __float2bfloat16(lb));
    h = *reinterpret_cast<uint32_t*>(&hp);
    l = *reinterpret_cast<uint32_t*>(&lp);
}

__device__ __forceinline__ void mma_bf16(float* d, uint32_t a0, uint32_t a1,
                                         uint32_t a2, uint32_t a3,
                                         uint32_t b0, uint32_t b1) {
    asm volatile(
        "mma.sync.aligned.m16n8k16.row.col.f32.bf16.bf16.f32 "
        "{%0,%1,%2,%3}, {%4,%5,%6,%7}, {%8,%9}, {%0,%1,%2,%3};"
        : "+f"(d[0]), "+f"(d[1]), "+f"(d[2]), "+f"(d[3])
        : "r"(a0), "r"(a1), "r"(a2), "r"(a3), "r"(b0), "r"(b1));
}

__device__ __forceinline__ void ldsm4(uint32_t& r0, uint32_t& r1,
                                      uint32_t& r2, uint32_t& r3, uint32_t a) {
    asm volatile("ldmatrix.sync.aligned.m8n8.x4.shared.b16 {%0,%1,%2,%3}, [%4];"
                 : "=r"(r0), "=r"(r1), "=r"(r2), "=r"(r3) : "r"(a));
}
__device__ __forceinline__ void ldsm2(uint32_t& r0, uint32_t& r1, uint32_t a) {
    asm volatile("ldmatrix.sync.aligned.m8n8.x2.shared.b16 {%0,%1}, [%2];"
                 : "=r"(r0), "=r"(r1) : "r"(a));
}

__device__ __forceinline__ void cp16(uint32_t s, const void* g) {
    asm volatile("cp.async.cg.shared.global [%0], [%1], 16;" :: "r"(s), "l"(g));
}
#define CP_COMMIT asm volatile("cp.async.commit_group;")
#define CP_WAIT0  asm volatile("cp.async.wait_group 0;" ::: "memory")
#define CP_WAIT1  asm volatile("cp.async.wait_group 1;" ::: "memory")

// ---------------------------------------------------------------------------
__global__ void split_in(const float* __restrict__ x,
                         __nv_bfloat16* __restrict__ hi,
                         __nv_bfloat16* __restrict__ lo, int n4) {
    int i = blockIdx.x * blockDim.x + threadIdx.x;
    if (i < n4) {
        float4 v = ((const float4*)x)[i];
        uint2 hh, ll;
        sp2(v.x, v.y, hh.x, ll.x);
        sp2(v.z, v.w, hh.y, ll.y);
        ((uint2*)hi)[i] = hh;
        ((uint2*)lo)[i] = ll;
    }
}

// ---------------------------------------------------------------------------
__global__ void wsplit(const float* __restrict__ W,
                       __nv_bfloat16* __restrict__ th,
                       __nv_bfloat16* __restrict__ tl) {
    __shared__ float t[32][33];
    const int k0 = blockIdx.y * 32, n0 = blockIdx.x * 32;
    const int tx = threadIdx.x, ty = threadIdx.y;
    #pragma unroll
    for (int r = 0; r < 4; r++)
        t[ty + r * 8][tx] = W[(size_t)(k0 + ty + r * 8) * 1024 + n0 + tx];
    __syncthreads();
    #pragma unroll
    for (int r = 0; r < 4; r++) {
        int n = ty + r * 8;
        float v = t[tx][n];
        __nv_bfloat16 hb = __float2bfloat16(v);
        float l = v - __bfloat162float(hb);
        th[(size_t)(n0 + n) * 1024 + k0 + tx] = hb;
        tl[(size_t)(n0 + n) * 1024 + k0 + tx] = __float2bfloat16(l);
    }
}

// ---------------------------------------------------------------------------
// Projection GEMM (bf16 3-term), fragments via ldmatrix.
// ---------------------------------------------------------------------------
#define PK 40
#define PROJ_SMEM (2 * 4 * 128 * PK * 2)

template<int OUTMODE>
__global__ void __launch_bounds__(256, 2)
proj_bf16(const __nv_bfloat16* __restrict__ Ah, const __nv_bfloat16* __restrict__ Al,
          const __nv_bfloat16* __restrict__ Bh, const __nv_bfloat16* __restrict__ Bl,
          const float* __restrict__ bias,
          __nv_bfloat16* __restrict__ Ch, __nv_bfloat16* __restrict__ Cl,
          float* __restrict__ Cf) {
    extern __shared__ __nv_bfloat16 dsm[];
    const int BUF = 4 * 128 * PK;

    const int tid = threadIdx.x;
    const int m0 = blockIdx.y * 128, n0 = blockIdx.x * 128;
    const int w = tid >> 5, lane = tid & 31, g = lane >> 2, t = lane & 3;
    const int mw = (w & 1) * 64, nw = (w >> 1) * 32;

    const uint32_t smu = (uint32_t)__cvta_generic_to_shared(dsm);

    // ldmatrix lane addressing
    const int r8 = lane & 7, sel = lane >> 3;
    // A: row = mw + i*16 + (sel&1)*8 + r8, col = (sel>>1)*8 + ks
    const uint32_t aA0 = smu + (uint32_t)(((mw + (sel & 1) * 8 + r8) * PK + (sel >> 1) * 8) * 2);
    // B: row = nw + j*8 + r8, col = (sel&1)*8 + ks  (x2: lanes 0-15 used)
    uint32_t aB0[4];
    #pragma unroll
    for (int j = 0; j < 4; j++)
        aB0[j] = smu + (uint32_t)(((nw + j * 8 + r8) * PK + (sel & 1) * 8) * 2)
               + 2u * 128 * PK * 2;      // Bh region
    const uint32_t LO = 128u * PK * 2;   // hi->lo offset (both A and B)

    float acc[4][4][4] = {};

    auto stage = [&](int it, int buf) {
        const int k0 = it * 32;
        const uint32_t bu = smu + (uint32_t)buf * BUF * 2;
        #pragma unroll
        for (int r = 0; r < 2; r++) {
            int c = tid + r * 256;
            int row = c >> 2, q8 = (c & 3) * 8;
            uint32_t o = (uint32_t)(row * PK + q8) * 2;
            size_t gi = (size_t)(m0 + row) * 1024 + k0 + q8;
            cp16(bu + o,                       Ah + gi);
            cp16(bu + 128 * PK * 2 + o,        Al + gi);
            size_t gb = (size_t)(n0 + row) * 1024 + k0 + q8;
            cp16(bu + 2 * 128 * PK * 2 + o,    Bh + gb);
            cp16(bu + 3 * 128 * PK * 2 + o,    Bl + gb);
        }
    };

    stage(0, 0); CP_COMMIT;

    for (int it = 0; it < 32; it++) {
        const int buf = it & 1;
        if (it + 1 < 32) { stage(it + 1, buf ^ 1); CP_COMMIT; CP_WAIT1; }
        else             { CP_WAIT0; }
        __syncthreads();

        const uint32_t bufo = (uint32_t)buf * BUF * 2;

        #pragma unroll
        for (int ks = 0; ks < 32; ks += 16) {
            uint32_t bh[4][2], bl[4][2];
            #pragma unroll
            for (int j = 0; j < 4; j++) {
                ldsm2(bh[j][0], bh[j][1], aB0[j] + bufo + ks * 2);
                ldsm2(bl[j][0], bl[j][1], aB0[j] + bufo + LO + ks * 2);
            }
            #pragma unroll
            for (int i = 0; i < 4; i++) {
                uint32_t ah0, ah1, ah2, ah3, al0, al1, al2, al3;
                const uint32_t ao = aA0 + bufo + (uint32_t)(i * 16 * PK * 2) + ks * 2;
                ldsm4(ah0, ah1, ah2, ah3, ao);
                ldsm4(al0, al1, al2, al3, ao + LO);
                #pragma unroll
                for (int j = 0; j < 4; j++) {
                    mma_bf16(acc[i][j], ah0, ah1, ah2, ah3, bh[j][0], bh[j][1]);
                    mma_bf16(acc[i][j], al0, al1, al2, al3, bh[j][0], bh[j][1]);
                    mma_bf16(acc[i][j], ah0, ah1, ah2, ah3, bl[j][0], bl[j][1]);
                }
            }
        }
        __syncthreads();
    }

    #pragma unroll
    for (int i = 0; i < 4; i++) {
        #pragma unroll
        for (int j = 0; j < 4; j++) {
            const int row0 = m0 + mw + i * 16 + g;
            const int col  = n0 + nw + j * 8 + t * 2;
            const float b0 = bias[col], b1 = bias[col + 1];
            float c00 = acc[i][j][0] + b0, c01 = acc[i][j][1] + b1;
            float c10 = acc[i][j][2] + b0, c11 = acc[i][j][3] + b1;
            if (OUTMODE == 2) {
                *(float2*)&Cf[(size_t)row0 * 1024 + col]       = make_float2(c00, c01);
                *(float2*)&Cf[(size_t)(row0 + 8) * 1024 + col] = make_float2(c10, c11);
            } else {
                size_t d0, d1;
                if (OUTMODE == 0) {
                    int bI = row0 >> 11, s = row0 & 2047, h = col >> 6, d = col & 63;
                    d0 = (((size_t)(bI * 16 + h) * 2048 + s) * 64 + d);
                    d1 = d0 + 8 * 64;
                } else {
                    d0 = (size_t)row0 * 1024 + col;
                    d1 = d0 + 8 * 1024;
                }
                uint32_t hu, lu;
                sp2(c00, c01, hu, lu);
                *(uint32_t*)&Ch[d0] = hu; *(uint32_t*)&Cl[d0] = lu;
                sp2(c10, c11, hu, lu);
                *(uint32_t*)&Ch[d1] = hu; *(uint32_t*)&Cl[d1] = lu;
            }
        }
    }
}

// ---------------------------------------------------------------------------
__global__ void vtrans(const __nv_bfloat16* __restrict__ ih,
                       const __nv_bfloat16* __restrict__ il,
                       __nv_bfloat16* __restrict__ oh,
                       __nv_bfloat16* __restrict__ ol) {
    __shared__ __nv_bfloat16 t[64][72];
    const int s0 = blockIdx.x * 64;
    const int bh = blockIdx.y;
    const int tid = threadIdx.x;

    for (int pass = 0; pass < 2; pass++) {
        const __nv_bfloat16* src = pass ? il : ih;
        __nv_bfloat16* dst = pass ? ol : oh;
        #pragma unroll
        for (int r = 0; r < 8; r++) {
            int c = tid + r * 256;
            int row = c >> 5, c2 = (c & 31) * 2;
            *(uint32_t*)&t[row][c2] =
                *(const uint32_t*)&src[((size_t)bh * 2048 + s0 + row) * 64 + c2];
        }
        __syncthreads();
        #pragma unroll
        for (int r = 0; r < 8; r++) {
            int c = tid + r * 256;
            int d = c >> 5, s2 = (c & 31) * 2;
            __nv_bfloat162 p(t[s2][d], t[s2 + 1][d]);
            *(uint32_t*)&dst[((size_t)bh * 64 + d) * 2048 + s0 + s2] =
                *(uint32_t*)&p;
        }
        __syncthreads();
    }
}

// ---------------------------------------------------------------------------
// Fused attention (R4 structure + exp-once + ldmatrix fragments).
// ---------------------------------------------------------------------------
#define PQ 72
#define PV 72
#define ATTN_SMEM (55296 * 2 + 2944 * 4)

__global__ void __launch_bounds__(256, 1)
attn_bf16(float* __restrict__ alpha,
          __nv_bfloat16* __restrict__ AOh, __nv_bfloat16* __restrict__ AOl) {
    extern __shared__ __nv_bfloat16 dsm[];
    float* fsm  = (float*)(dsm + 55296);
    float* sM   = fsm;
    float* sF   = fsm + 128;
    float* sL   = fsm + 256;
    float* sRed = fsm + 384;
    float* sMt  = fsm + 896;          // [16][128]

    const int tid = threadIdx.x;
    const int w = tid >> 5, lane = tid & 31, g = lane >> 2, t = lane & 3;
    const int mw = (w & 1) * 64;
    const int wc = w >> 1;
    const int q0 = blockIdx.x * 128;
    const int bh = blockIdx.y;

    const __nv_bfloat16* Qhb = g_Qh + ((size_t)bh * 2048 + q0) * 64;
    const __nv_bfloat16* Qlb = g_Ql + ((size_t)bh * 2048 + q0) * 64;
    const __nv_bfloat16* Khb = g_Kh + (size_t)bh * 2048 * 64;
    const __nv_bfloat16* Klb = g_Kl + (size_t)bh * 2048 * 64;
    const __nv_bfloat16* Vthb = g_Vth + (size_t)bh * 64 * 2048;
    const __nv_bfloat16* Vtlb = g_Vtl + (size_t)bh * 64 * 2048;
    float* Ab = alpha + ((size_t)bh * 2048 + q0) * 2048;

    const uint32_t smu = (uint32_t)__cvta_generic_to_shared(dsm);

    // ldmatrix lane addressing
    const int r8 = lane & 7, sel = lane >> 3;
    // A-pattern (Q / P): row = base + i*16 + (sel&1)*8 + r8, col = (sel>>1)*8 + ks
    const uint32_t aQ0 = smu + (uint32_t)(((mw + (sel & 1) * 8 + r8) * PQ + (sel >> 1) * 8) * 2);
    // B-pattern (K): row = wc*32 + j*8 + r8, col = (sel&1)*8 + ks
    uint32_t aK0[4];
    #pragma unroll
    for (int j = 0; j < 4; j++)
        aK0[j] = (uint32_t)(((wc * 32 + j * 8 + r8) * PQ + (sel & 1) * 8) * 2);
    // B-pattern (V, pass B): row = wc*16 + j*8 + r8
    uint32_t aV0[2];
    #pragma unroll
    for (int j = 0; j < 2; j++)
        aV0[j] = smu + (uint32_t)(((wc * 16 + j * 8 + r8) * PV + (sel & 1) * 8) * 2);
    const uint32_t LOQ = 9216u * 2;   // hi->lo (all regions are +9216 elems)

    if (tid < 128) { sM[tid] = -3e38f; sL[tid] = 0.f; }

    #pragma unroll
    for (int r = 0; r < 4; r++) {
        int c = tid + r * 256;
        int row = c >> 3, q8 = (c & 7) * 8;
        uint32_t o = (uint32_t)(row * PQ + q8) * 2;
        size_t gi = (size_t)row * 64 + q8;
        cp16(smu + o,            Qhb + gi);
        cp16(smu + LOQ + o,      Qlb + gi);
    }
    auto stageK = [&](int kt, int buf) {
        const uint32_t bh_off = (buf ? 36864u : 18432u) * 2;
        const size_t src = (size_t)kt * 128 * 64;
        #pragma unroll
        for (int r = 0; r < 4; r++) {
            int c = tid + r * 256;
            int row = c >> 3, q8 = (c & 7) * 8;
            uint32_t o = (uint32_t)(row * PQ + q8) * 2;
            cp16(smu + bh_off + o,       Khb + src + (size_t)row * 64 + q8);
            cp16(smu + bh_off + LOQ + o, Klb + src + (size_t)row * 64 + q8);
        }
    };
    stageK(0, 0);
    CP_COMMIT;

    // =================== PASS A ===================
    for (int kt = 0; kt < 16; kt++) {
        const uint32_t kbase = smu + ((kt & 1) ? 36864u : 18432u) * 2;
        if (kt + 1 < 16) { stageK(kt + 1, (kt & 1) ^ 1); CP_COMMIT; CP_WAIT1; }
        else             { CP_WAIT0; }
        __syncthreads();

        float acc[4][4][4] = {};
        #pragma unroll
        for (int ks = 0; ks < 64; ks += 16) {
            uint32_t kh[4][2], kl[4][2];
            #pragma unroll
            for (int j = 0; j < 4; j++) {
                ldsm2(kh[j][0], kh[j][1], kbase + aK0[j] + ks * 2);
                ldsm2(kl[j][0], kl[j][1], kbase + LOQ + aK0[j] + ks * 2);
            }
            #pragma unroll
            for (int i = 0; i < 4; i++) {
                uint32_t qh0, qh1, qh2, qh3, ql0, ql1, ql2, ql3;
                const uint32_t ao = aQ0 + (uint32_t)(i * 16 * PQ * 2) + ks * 2;
                ldsm4(qh0, qh1, qh2, qh3, ao);
                ldsm4(ql0, ql1, ql2, ql3, ao + LOQ);
                #pragma unroll
                for (int j = 0; j < 4; j++) {
                    mma_bf16(acc[i][j], qh0, qh1, qh2, qh3, kh[j][0], kh[j][1]);
                    mma_bf16(acc[i][j], ql0, ql1, ql2, ql3, kh[j][0], kh[j][1]);
                    mma_bf16(acc[i][j], qh0, qh1, qh2, qh3, kl[j][0], kl[j][1]);
                }
            }
        }
        #pragma unroll
        for (int i = 0; i < 4; i++)
            #pragma unroll
            for (int j = 0; j < 4; j++)
                #pragma unroll
                for (int r = 0; r < 4; r++) acc[i][j][r] *= 0.125f;

        // ---- row max ----
        float rmax[8];
        #pragma unroll
        for (int i = 0; i < 4; i++) {
            float m0v = -3e38f, m1v = -3e38f;
            #pragma unroll
            for (int j = 0; j < 4; j++) {
                m0v = fmaxf(m0v, fmaxf(acc[i][j][0], acc[i][j][1]));
                m1v = fmaxf(m1v, fmaxf(acc[i][j][2], acc[i][j][3]));
            }
            rmax[i * 2] = m0v; rmax[i * 2 + 1] = m1v;
        }
        #pragma unroll
        for (int o = 1; o <= 2; o <<= 1)
            #pragma unroll
            for (int e = 0; e < 8; e++)
                rmax[e] = fmaxf(rmax[e], __shfl_xor_sync(0xffffffffu, rmax[e], o));
        if (t == 0) {
            #pragma unroll
            for (int i = 0; i < 4; i++) {
                sRed[wc * 128 + mw + i * 16 + g]     = rmax[i * 2];
                sRed[wc * 128 + mw + i * 16 + g + 8] = rmax[i * 2 + 1];
            }
        }
        __syncthreads();
        if (tid < 128) {
            float tm = fmaxf(fmaxf(sRed[tid], sRed[128 + tid]),
                             fmaxf(sRed[256 + tid], sRed[384 + tid]));
            float mo = sM[tid];
            float mn = fmaxf(mo, tm);
            sM[tid] = mn;
            sF[tid] = __expf(mo - mn);
            sMt[kt * 128 + tid] = mn;
        }
        __syncthreads();

        // ---- e = exp(S - m_kt), accumulate row sum, write e to alpha ----
        float rsum[8];
        #pragma unroll
        for (int i = 0; i < 4; i++) {
            const int row = mw + i * 16 + g;
            const float mn0 = sM[row], mn1 = sM[row + 8];
            float s0 = 0.f, s1 = 0.f;
            #pragma unroll
            for (int j = 0; j < 4; j++) {
                acc[i][j][0] = __expf(acc[i][j][0] - mn0);
                acc[i][j][1] = __expf(acc[i][j][1] - mn0);
                acc[i][j][2] = __expf(acc[i][j][2] - mn1);
                acc[i][j][3] = __expf(acc[i][j][3] - mn1);
                s0 += acc[i][j][0] + acc[i][j][1];
                s1 += acc[i][j][2] + acc[i][j][3];
            }
            rsum[i * 2] = s0; rsum[i * 2 + 1] = s1;
        }

        #pragma unroll
        for (int i = 0; i < 4; i++) {
            const int row = mw + i * 16 + g;
            #pragma unroll
            for (int j = 0; j < 4; j++) {
                const int cc = kt * 128 + wc * 32 + j * 8 + t * 2;
                *(float2*)&Ab[(size_t)row * 2048 + cc]       = make_float2(acc[i][j][0], acc[i][j][1]);
                *(float2*)&Ab[(size_t)(row + 8) * 2048 + cc] = make_float2(acc[i][j][2], acc[i][j][3]);
            }
        }

        #pragma unroll
        for (int o = 1; o <= 2; o <<= 1)
            #pragma unroll
            for (int e = 0; e < 8; e++)
                rsum[e] += __shfl_xor_sync(0xffffffffu, rsum[e], o);
        if (t == 0) {
            #pragma unroll
            for (int i = 0; i < 4; i++) {
                sRed[wc * 128 + mw + i * 16 + g]     = rsum[i * 2];
                sRed[wc * 128 + mw + i * 16 + g + 8] = rsum[i * 2 + 1];
            }
        }
        __syncthreads();
        if (tid < 128) {
            sL[tid] = sL[tid] * sF[tid] +
                      (sRed[tid] + sRed[128 + tid] + sRed[256 + tid] + sRed[384 + tid]);
        }
        __syncthreads();
    }

    if (tid < 128) sL[tid] = 1.0f / sL[tid];
    __syncthreads();

    // =================== PASS B ===================
    __nv_bfloat16* sPh = dsm + 18432;
    __nv_bfloat16* sPl = dsm + 27648;
    const uint32_t aP0 = smu + 18432u * 2 +
        (uint32_t)(((mw + (sel & 1) * 8 + r8) * PQ + (sel >> 1) * 8) * 2);

    float accO[4][2][4] = {};
    const int pr = tid & 127;
    const int pc = (tid >> 7) * 32;
    const float rmF = sM[pr];
    const float rl  = sL[pr];

    for (int ch = 0; ch < 32; ch++) {
        const int kb = ch * 64;
        #pragma unroll
        for (int r = 0; r < 2; r++) {
            int c = tid + r * 256;
            int d = c >> 3, q8 = (c & 7) * 8;
            uint32_t o = (uint32_t)(d * PV + q8) * 2;
            size_t gi = (size_t)d * 2048 + kb + q8;
            cp16(smu + o,       Vthb + gi);
            cp16(smu + LOQ + o, Vtlb + gi);
        }
        CP_COMMIT;

        // P = e * exp(m_kt - m_final) * invl
        {
            const int tile = ch >> 1;
            const float scale = __expf(sMt[tile * 128 + pr] - rmF) * rl;
            float* rowp = Ab + (size_t)pr * 2048 + kb + pc;
            #pragma unroll
            for (int u = 0; u < 8; u++) {
                float4 s4 = *(const float4*)(rowp + u * 4);
                float4 p4;
                p4.x = s4.x * scale;
                p4.y = s4.y * scale;
                p4.z = s4.z * scale;
                p4.w = s4.w * scale;
                *(float4*)(rowp + u * 4) = p4;
                uint32_t hu, lu;
                sp2(p4.x, p4.y, hu, lu);
                *(uint32_t*)&sPh[pr * PQ + pc + u * 4]     = hu;
                *(uint32_t*)&sPl[pr * PQ + pc + u * 4]     = lu;
                sp2(p4.z, p4.w, hu, lu);
                *(uint32_t*)&sPh[pr * PQ + pc + u * 4 + 2] = hu;
                *(uint32_t*)&sPl[pr * PQ + pc + u * 4 + 2] = lu;
            }
        }
        CP_WAIT0;
        __syncthreads();

        #pragma unroll
        for (int ks = 0; ks < 64; ks += 16) {
            uint32_t vh[2][2], vl[2][2];
            #pragma unroll
            for (int j = 0; j < 2; j++) {
                ldsm2(vh[j][0], vh[j][1], aV0[j] + ks * 2);
                ldsm2(vl[j][0], vl[j][1], aV0[j] + LOQ + ks * 2);
            }
            #pragma unroll
            for (int i = 0; i < 4; i++) {
                uint32_t ph0, ph1, ph2, ph3, pl0, pl1, pl2, pl3;
                const uint32_t ao = aP0 + (uint32_t)(i * 16 * PQ * 2) + ks * 2;
                ldsm4(ph0, ph1, ph2, ph3, ao);
                ldsm4(pl0, pl1, pl2, pl3, ao + 9216u * 2);
                #pragma unroll
                for (int j = 0; j < 2; j++) {
                    mma_bf16(accO[i][j], ph0, ph1, ph2, ph3, vh[j][0], vh[j][1]);
                    mma_bf16(accO[i][j], pl0, pl1, pl2, pl3, vh[j][0], vh[j][1]);
                    mma_bf16(accO[i][j], ph0, ph1, ph2, ph3, vl[j][0], vl[j][1]);
                }
            }
        }
        __syncthreads();
    }

    const int b = bh >> 4, h = bh & 15;
    #pragma unroll
    for (int i = 0; i < 4; i++) {
        #pragma unroll
        for (int j = 0; j < 2; j++) {
            const int row = q0 + mw + i * 16 + g;
            const int col = h * 64 + wc * 16 + j * 8 + t * 2;
            uint32_t hu, lu;
            size_t d0 = ((size_t)(b * 2048 + row)) * 1024 + col;
            sp2(accO[i][j][0], accO[i][j][1], hu, lu);
            *(uint32_t*)&AOh[d0] = hu; *(uint32_t*)&AOl[d0] = lu;
            size_t d1 = ((size_t)(b * 2048 + row + 8)) * 1024 + col;
            sp2(accO[i][j][2], accO[i][j][3], hu, lu);
            *(uint32_t*)&AOh[d1] = hu; *(uint32_t*)&AOl[d1] = lu;
        }
    }
}

// ---------------------------------------------------------------------------
extern "C" void kernel_launch(void* const* d_in, const int* in_sizes, int n_in,
                              void* d_out, int out_size) {
    const float* q  = (const float*)d_in[0];
    const float* k  = (const float*)d_in[1];
    const float* v  = (const float*)d_in[2];
    const float* Wq = (const float*)d_in[3];
    const float* bq = (const float*)d_in[4];
    const float* Wk = (const float*)d_in[5];
    const float* bk = (const float*)d_in[6];
    const float* Wv = (const float*)d_in[7];
    const float* bv = (const float*)d_in[8];
    const float* Wo = (const float*)d_in[9];
    const float* bo = (const float*)d_in[10];

    float* out   = (float*)d_out;
    float* alpha = out + (size_t)B_ * S_ * D_;

    __nv_bfloat16 *qh,*ql,*kh,*kl,*vh,*vl;
    __nv_bfloat16 *Wqh,*Wql,*Wkh,*Wkl,*Wvh,*Wvl,*Woh,*Wol;
    __nv_bfloat16 *Qh,*Ql,*Kh,*Kl,*Vph,*Vpl,*Vth,*Vtl,*AOh,*AOl;
    cudaGetSymbolAddress((void**)&qh, g_qh);   cudaGetSymbolAddress((void**)&ql, g_ql);
    cudaGetSymbolAddress((void**)&kh, g_kh);   cudaGetSymbolAddress((void**)&kl, g_kl);
    cudaGetSymbolAddress((void**)&vh, g_vh);   cudaGetSymbolAddress((void**)&vl, g_vl);
    cudaGetSymbolAddress((void**)&Wqh, g_Wqh); cudaGetSymbolAddress((void**)&Wql, g_Wql);
    cudaGetSymbolAddress((void**)&Wkh, g_Wkh); cudaGetSymbolAddress((void**)&Wkl, g_Wkl);
    cudaGetSymbolAddress((void**)&Wvh, g_Wvh); cudaGetSymbolAddress((void**)&Wvl, g_Wvl);
    cudaGetSymbolAddress((void**)&Woh, g_Woh); cudaGetSymbolAddress((void**)&Wol, g_Wol);
    cudaGetSymbolAddress((void**)&Qh, g_Qh);   cudaGetSymbolAddress((void**)&Ql, g_Ql);
    cudaGetSymbolAddress((void**)&Kh, g_Kh);   cudaGetSymbolAddress((void**)&Kl, g_Kl);
    cudaGetSymbolAddress((void**)&Vph, g_Vph); cudaGetSymbolAddress((void**)&Vpl, g_Vpl);
    cudaGetSymbolAddress((void**)&Vth, g_Vth); cudaGetSymbolAddress((void**)&Vtl, g_Vtl);
    cudaGetSymbolAddress((void**)&AOh, g_AOh); cudaGetSymbolAddress((void**)&AOl, g_AOl);

    static bool attr_set = false;
    if (!attr_set) {
        cudaFuncSetAttribute(proj_bf16<0>, cudaFuncAttributeMaxDynamicSharedMemorySize, PROJ_SMEM);
        cudaFuncSetAttribute(proj_bf16<2>, cudaFuncAttributeMaxDynamicSharedMemorySize, PROJ_SMEM);
        cudaFuncSetAttribute(attn_bf16, cudaFuncAttributeMaxDynamicSharedMemorySize, ATTN_SMEM);
        attr_set = true;
    }

    const int n4 = BS_ * HD_ / 4;
    split_in<<<(n4 + 255) / 256, 256>>>(q, qh, ql, n4);
    split_in<<<(n4 + 255) / 256, 256>>>(k, kh, kl, n4);
    split_in<<<(n4 + 255) / 256, 256>>>(v, vh, vl, n4);

    dim3 gW(32, 32), bW(32, 8);
    wsplit<<<gW, bW>>>(Wq, Wqh, Wql);
    wsplit<<<gW, bW>>>(Wk, Wkh, Wkl);
    wsplit<<<gW, bW>>>(Wv, Wvh, Wvl);
    wsplit<<<gW, bW>>>(Wo, Woh, Wol);

    dim3 gProj(HD_ / 128, BS_ / 128);   // (8, 64)
    proj_bf16<0><<<gProj, 256, PROJ_SMEM>>>(qh, ql, Wqh, Wql, bq, Qh, Ql, nullptr);
    proj_bf16<0><<<gProj, 256, PROJ_SMEM>>>(kh, kl, Wkh, Wkl, bk, Kh, Kl, nullptr);
    proj_bf16<0><<<gProj, 256, PROJ_SMEM>>>(vh, vl, Wvh, Wvl, bv, Vph, Vpl, nullptr);

    vtrans<<<dim3(32, 64), 256>>>(Vph, Vpl, Vth, Vtl);

    dim3 gAttn(S_ / 128, B_ * H_);      // (16, 64)
    attn_bf16<<<gAttn, 256, ATTN_SMEM>>>(alpha, AOh, AOl);

    proj_bf16<2><<<gProj, 256, PROJ_SMEM>>>(AOh, AOl, Woh, Wol, bo, nullptr, nullptr, out);
}

// round 13
// speedup vs baseline: 1.4601x; 1.1158x over previous
#include <cuda_runtime.h>
#include <cuda_bf16.h>
#include <cuda_fp16.h>
#include <cstdint>

#define B_ 4
#define S_ 2048
#define D_ 1024
#define H_ 16
#define DH_ 64
#define BS_ 8192
#define HD_ 1024

// ---------------- scratch ----------------
__device__ __nv_bfloat16 g_qh[BS_*HD_], g_ql[BS_*HD_];
__device__ __nv_bfloat16 g_kh[BS_*HD_], g_kl[BS_*HD_];
__device__ __nv_bfloat16 g_vh[BS_*HD_], g_vl[BS_*HD_];
__device__ __nv_bfloat16 g_Wqh[D_*HD_], g_Wql[D_*HD_];
__device__ __nv_bfloat16 g_Wkh[D_*HD_], g_Wkl[D_*HD_];
__device__ __nv_bfloat16 g_Wvh[D_*HD_], g_Wvl[D_*HD_];
__device__ __half        g_Wof[HD_*D_];                  // [N][K] fp16 single
__device__ __nv_bfloat16 g_Qh[BS_*HD_], g_Ql[BS_*HD_];   // [bh][s][dh]
__device__ __nv_bfloat16 g_Kh[BS_*HD_], g_Kl[BS_*HD_];   // [bh][s][dh]
__device__ __half        g_Vf[BS_*HD_];                  // [bh][s][dh] fp16
__device__ __half        g_Vtf[BS_*HD_];                 // [bh][dh][s] fp16
__device__ __half        g_AOf[BS_*HD_];                 // [row][1024] fp16

// ---------------- helpers ----------------
__device__ __forceinline__ void sp2(float a, float b, uint32_t& h, uint32_t& l) {
    __nv_bfloat16 ha = __float2bfloat16(a), hb = __float2bfloat16(b);
    float la = a - __bfloat162float(ha);
    float lb = b - __bfloat162float(hb);
    __nv_bfloat162 hp(ha, hb);
    __nv_bfloat162 lp(__float2bfloat16(la), __float2bfloat16(lb));
    h = *reinterpret_cast<uint32_t*>(&hp);
    l = *reinterpret_cast<uint32_t*>(&lp);
}

__device__ __forceinline__ void mma_bf16(float* d, uint32_t a0, uint32_t a1,
                                         uint32_t a2, uint32_t a3,
                                         uint32_t b0, uint32_t b1) {
    asm volatile(
        "mma.sync.aligned.m16n8k16.row.col.f32.bf16.bf16.f32 "
        "{%0,%1,%2,%3}, {%4,%5,%6,%7}, {%8,%9}, {%0,%1,%2,%3};"
        : "+f"(d[0]), "+f"(d[1]), "+f"(d[2]), "+f"(d[3])
        : "r"(a0), "r"(a1), "r"(a2), "r"(a3), "r"(b0), "r"(b1));
}

__device__ __forceinline__ void mma_f16(float* d, uint32_t a0, uint32_t a1,
                                        uint32_t a2, uint32_t a3,
                                        uint32_t b0, uint32_t b1) {
    asm volatile(
        "mma.sync.aligned.m16n8k16.row.col.f32.f16.f16.f32 "
        "{%0,%1,%2,%3}, {%4,%5,%6,%7}, {%8,%9}, {%0,%1,%2,%3};"
        : "+f"(d[0]), "+f"(d[1]), "+f"(d[2]), "+f"(d[3])
        : "r"(a0), "r"(a1), "r"(a2), "r"(a3), "r"(b0), "r"(b1));
}

__device__ __forceinline__ void ldsm4(uint32_t& r0, uint32_t& r1,
                                      uint32_t& r2, uint32_t& r3, uint32_t a) {
    asm volatile("ldmatrix.sync.aligned.m8n8.x4.shared.b16 {%0,%1,%2,%3}, [%4];"
                 : "=r"(r0), "=r"(r1), "=r"(r2), "=r"(r3) : "r"(a));
}
__device__ __forceinline__ void ldsm2(uint32_t& r0, uint32_t& r1, uint32_t a) {
    asm volatile("ldmatrix.sync.aligned.m8n8.x2.shared.b16 {%0,%1}, [%2];"
                 : "=r"(r0), "=r"(r1) : "r"(a));
}

__device__ __forceinline__ void cp16(uint32_t s, const void* g) {
    asm volatile("cp.async.cg.shared.global [%0], [%1], 16;" :: "r"(s), "l"(g));
}
#define CP_COMMIT asm volatile("cp.async.commit_group;")
#define CP_WAIT0  asm volatile("cp.async.wait_group 0;" ::: "memory")
#define CP_WAIT1  asm volatile("cp.async.wait_group 1;" ::: "memory")

// ---------------------------------------------------------------------------
__global__ void split_in(const float* __restrict__ x,
                         __nv_bfloat16* __restrict__ hi,
                         __nv_bfloat16* __restrict__ lo, int n4) {
    int i = blockIdx.x * blockDim.x + threadIdx.x;
    if (i < n4) {
        float4 v = ((const float4*)x)[i];
        uint2 hh, ll;
        sp2(v.x, v.y, hh.x, ll.x);
        sp2(v.z, v.w, hh.y, ll.y);
        ((uint2*)hi)[i] = hh;
        ((uint2*)lo)[i] = ll;
    }
}

// ---------------------------------------------------------------------------
__global__ void wsplit(const float* __restrict__ W,
                       __nv_bfloat16* __restrict__ th,
                       __nv_bfloat16* __restrict__ tl) {
    __shared__ float t[32][33];
    const int k0 = blockIdx.y * 32, n0 = blockIdx.x * 32;
    const int tx = threadIdx.x, ty = threadIdx.y;
    #pragma unroll
    for (int r = 0; r < 4; r++)
        t[ty + r * 8][tx] = W[(size_t)(k0 + ty + r * 8) * 1024 + n0 + tx];
    __syncthreads();
    #pragma unroll
    for (int r = 0; r < 4; r++) {
        int n = ty + r * 8;
        float v = t[tx][n];
        __nv_bfloat16 hb = __float2bfloat16(v);
        float l = v - __bfloat162float(hb);
        th[(size_t)(n0 + n) * 1024 + k0 + tx] = hb;
        tl[(size_t)(n0 + n) * 1024 + k0 + tx] = __float2bfloat16(l);
    }
}

// transpose + convert to single fp16 (for Wo)
__global__ void wsplit_f16(const float* __restrict__ W,
                           __half* __restrict__ tf) {
    __shared__ float t[32][33];
    const int k0 = blockIdx.y * 32, n0 = blockIdx.x * 32;
    const int tx = threadIdx.x, ty = threadIdx.y;
    #pragma unroll
    for (int r = 0; r < 4; r++)
        t[ty + r * 8][tx] = W[(size_t)(k0 + ty + r * 8) * 1024 + n0 + tx];
    __syncthreads();
    #pragma unroll
    for (int r = 0; r < 4; r++) {
        int n = ty + r * 8;
        tf[(size_t)(n0 + n) * 1024 + k0 + tx] = __float2half(t[tx][n]);
    }
}

// ---------------------------------------------------------------------------
// Projection GEMM (bf16 3-term), fragments via ldmatrix.
// OUTMODE 0: head-packed bf16 hi/lo; OUTMODE 3: head-packed fp16 single.
// ---------------------------------------------------------------------------
#define PK 40
#define PROJ_SMEM (2 * 4 * 128 * PK * 2)

template<int OUTMODE>
__global__ void __launch_bounds__(256, 2)
proj_bf16(const __nv_bfloat16* __restrict__ Ah, const __nv_bfloat16* __restrict__ Al,
          const __nv_bfloat16* __restrict__ Bh, const __nv_bfloat16* __restrict__ Bl,
          const float* __restrict__ bias,
          __nv_bfloat16* __restrict__ Ch, __nv_bfloat16* __restrict__ Cl) {
    extern __shared__ __nv_bfloat16 dsm[];
    const int BUF = 4 * 128 * PK;

    const int tid = threadIdx.x;
    const int m0 = blockIdx.y * 128, n0 = blockIdx.x * 128;
    const int w = tid >> 5, lane = tid & 31, g = lane >> 2, t = lane & 3;
    const int mw = (w & 1) * 64, nw = (w >> 1) * 32;

    const uint32_t smu = (uint32_t)__cvta_generic_to_shared(dsm);

    const int r8 = lane & 7, sel = lane >> 3;
    const uint32_t aA0 = smu + (uint32_t)(((mw + (sel & 1) * 8 + r8) * PK + (sel >> 1) * 8) * 2);
    uint32_t aB0[4];
    #pragma unroll
    for (int j = 0; j < 4; j++)
        aB0[j] = smu + (uint32_t)(((nw + j * 8 + r8) * PK + (sel & 1) * 8) * 2)
               + 2u * 128 * PK * 2;
    const uint32_t LO = 128u * PK * 2;

    float acc[4][4][4] = {};

    auto stage = [&](int it, int buf) {
        const int k0 = it * 32;
        const uint32_t bu = smu + (uint32_t)buf * BUF * 2;
        #pragma unroll
        for (int r = 0; r < 2; r++) {
            int c = tid + r * 256;
            int row = c >> 2, q8 = (c & 3) * 8;
            uint32_t o = (uint32_t)(row * PK + q8) * 2;
            size_t gi = (size_t)(m0 + row) * 1024 + k0 + q8;
            cp16(bu + o,                       Ah + gi);
            cp16(bu + 128 * PK * 2 + o,        Al + gi);
            size_t gb = (size_t)(n0 + row) * 1024 + k0 + q8;
            cp16(bu + 2 * 128 * PK * 2 + o,    Bh + gb);
            cp16(bu + 3 * 128 * PK * 2 + o,    Bl + gb);
        }
    };

    stage(0, 0); CP_COMMIT;

    for (int it = 0; it < 32; it++) {
        const int buf = it & 1;
        if (it + 1 < 32) { stage(it + 1, buf ^ 1); CP_COMMIT; CP_WAIT1; }
        else             { CP_WAIT0; }
        __syncthreads();

        const uint32_t bufo = (uint32_t)buf * BUF * 2;

        #pragma unroll
        for (int ks = 0; ks < 32; ks += 16) {
            uint32_t bh[4][2], bl[4][2];
            #pragma unroll
            for (int j = 0; j < 4; j++) {
                ldsm2(bh[j][0], bh[j][1], aB0[j] + bufo + ks * 2);
                ldsm2(bl[j][0], bl[j][1], aB0[j] + bufo + LO + ks * 2);
            }
            #pragma unroll
            for (int i = 0; i < 4; i++) {
                uint32_t ah0, ah1, ah2, ah3, al0, al1, al2, al3;
                const uint32_t ao = aA0 + bufo + (uint32_t)(i * 16 * PK * 2) + ks * 2;
                ldsm4(ah0, ah1, ah2, ah3, ao);
                ldsm4(al0, al1, al2, al3, ao + LO);
                #pragma unroll
                for (int j = 0; j < 4; j++) {
                    mma_bf16(acc[i][j], ah0, ah1, ah2, ah3, bh[j][0], bh[j][1]);
                    mma_bf16(acc[i][j], al0, al1, al2, al3, bh[j][0], bh[j][1]);
                    mma_bf16(acc[i][j], ah0, ah1, ah2, ah3, bl[j][0], bl[j][1]);
                }
            }
        }
        __syncthreads();
    }

    #pragma unroll
    for (int i = 0; i < 4; i++) {
        #pragma unroll
        for (int j = 0; j < 4; j++) {
            const int row0 = m0 + mw + i * 16 + g;
            const int col  = n0 + nw + j * 8 + t * 2;
            const float b0 = bias[col], b1 = bias[col + 1];
            float c00 = acc[i][j][0] + b0, c01 = acc[i][j][1] + b1;
            float c10 = acc[i][j][2] + b0, c11 = acc[i][j][3] + b1;
            int bI = row0 >> 11, s = row0 & 2047, h = col >> 6, d = col & 63;
            size_t d0 = (((size_t)(bI * 16 + h) * 2048 + s) * 64 + d);
            size_t d1 = d0 + 8 * 64;
            if (OUTMODE == 3) {
                __half* C16 = (__half*)Ch;
                __half2 h0 = __floats2half2_rn(c00, c01);
                __half2 h1 = __floats2half2_rn(c10, c11);
                *(uint32_t*)&C16[d0] = *(uint32_t*)&h0;
                *(uint32_t*)&C16[d1] = *(uint32_t*)&h1;
            } else {
                uint32_t hu, lu;
                sp2(c00, c01, hu, lu);
                *(uint32_t*)&Ch[d0] = hu; *(uint32_t*)&Cl[d0] = lu;
                sp2(c10, c11, hu, lu);
                *(uint32_t*)&Ch[d1] = hu; *(uint32_t*)&Cl[d1] = lu;
            }
        }
    }
}

// ---------------------------------------------------------------------------
// Out-projection: 1-term fp16 GEMM. out[8192,1024] = AOf @ Wof^T + bias (fp32 out)
// ---------------------------------------------------------------------------
#define PF_SMEM (2 * 2 * 128 * PK * 2)

__global__ void __launch_bounds__(256, 2)
proj_f16(const __half* __restrict__ Af, const __half* __restrict__ Bf,
         const float* __restrict__ bias, float* __restrict__ Cf) {
    extern __shared__ __half fsm16[];
    const int BUF = 2 * 128 * PK;

    const int tid = threadIdx.x;
    const int m0 = blockIdx.y * 128, n0 = blockIdx.x * 128;
    const int w = tid >> 5, lane = tid & 31, g = lane >> 2, t = lane & 3;
    const int mw = (w & 1) * 64, nw = (w >> 1) * 32;

    const uint32_t smu = (uint32_t)__cvta_generic_to_shared(fsm16);

    const int r8 = lane & 7, sel = lane >> 3;
    const uint32_t aA0 = smu + (uint32_t)(((mw + (sel & 1) * 8 + r8) * PK + (sel >> 1) * 8) * 2);
    uint32_t aB0[4];
    #pragma unroll
    for (int j = 0; j < 4; j++)
        aB0[j] = smu + (uint32_t)(((nw + j * 8 + r8) * PK + (sel & 1) * 8) * 2)
               + 128u * PK * 2;

    float acc[4][4][4] = {};

    auto stage = [&](int it, int buf) {
        const int k0 = it * 32;
        const uint32_t bu = smu + (uint32_t)buf * BUF * 2;
        #pragma unroll
        for (int r = 0; r < 2; r++) {
            int c = tid + r * 256;
            int row = c >> 2, q8 = (c & 3) * 8;
            uint32_t o = (uint32_t)(row * PK + q8) * 2;
            cp16(bu + o,                Af + (size_t)(m0 + row) * 1024 + k0 + q8);
            cp16(bu + 128 * PK * 2 + o, Bf + (size_t)(n0 + row) * 1024 + k0 + q8);
        }
    };

    stage(0, 0); CP_COMMIT;

    for (int it = 0; it < 32; it++) {
        const int buf = it & 1;
        if (it + 1 < 32) { stage(it + 1, buf ^ 1); CP_COMMIT; CP_WAIT1; }
        else             { CP_WAIT0; }
        __syncthreads();

        const uint32_t bufo = (uint32_t)buf * BUF * 2;

        #pragma unroll
        for (int ks = 0; ks < 32; ks += 16) {
            uint32_t bf[4][2];
            #pragma unroll
            for (int j = 0; j < 4; j++)
                ldsm2(bf[j][0], bf[j][1], aB0[j] + bufo + ks * 2);
            #pragma unroll
            for (int i = 0; i < 4; i++) {
                uint32_t a0, a1, a2, a3;
                ldsm4(a0, a1, a2, a3, aA0 + bufo + (uint32_t)(i * 16 * PK * 2) + ks * 2);
                #pragma unroll
                for (int j = 0; j < 4; j++)
                    mma_f16(acc[i][j], a0, a1, a2, a3, bf[j][0], bf[j][1]);
            }
        }
        __syncthreads();
    }

    #pragma unroll
    for (int i = 0; i < 4; i++) {
        #pragma unroll
        for (int j = 0; j < 4; j++) {
            const int row0 = m0 + mw + i * 16 + g;
            const int col  = n0 + nw + j * 8 + t * 2;
            const float b0 = bias[col], b1 = bias[col + 1];
            *(float2*)&Cf[(size_t)row0 * 1024 + col] =
                make_float2(acc[i][j][0] + b0, acc[i][j][1] + b1);
            *(float2*)&Cf[(size_t)(row0 + 8) * 1024 + col] =
                make_float2(acc[i][j][2] + b0, acc[i][j][3] + b1);
        }
    }
}

// ---------------------------------------------------------------------------
__global__ void vtrans_f16(const __half* __restrict__ in,
                           __half* __restrict__ outp) {
    __shared__ __half t[64][72];
    const int s0 = blockIdx.x * 64;
    const int bh = blockIdx.y;
    const int tid = threadIdx.x;

    #pragma unroll
    for (int r = 0; r < 8; r++) {
        int c = tid + r * 256;
        int row = c >> 5, c2 = (c & 31) * 2;
        *(uint32_t*)&t[row][c2] =
            *(const uint32_t*)&in[((size_t)bh * 2048 + s0 + row) * 64 + c2];
    }
    __syncthreads();
    #pragma unroll
    for (int r = 0; r < 8; r++) {
        int c = tid + r * 256;
        int d = c >> 5, s2 = (c & 31) * 2;
        __half2 p(t[s2][d], t[s2 + 1][d]);
        *(uint32_t*)&outp[((size_t)bh * 64 + d) * 2048 + s0 + s2] = *(uint32_t*)&p;
    }
}

// ---------------------------------------------------------------------------
// Fused attention: pass A bf16 3-term (unchanged), pass B fp16 1-term.
// ---------------------------------------------------------------------------
#define PQ 72
#define PV 72
#define ATTN_SMEM (55296 * 2 + 2944 * 4)

__global__ void __launch_bounds__(256, 1)
attn_bf16(float* __restrict__ alpha, __half* __restrict__ AOf) {
    extern __shared__ __nv_bfloat16 dsm[];
    float* fsm  = (float*)(dsm + 55296);
    float* sM   = fsm;
    float* sF   = fsm + 128;
    float* sL   = fsm + 256;
    float* sRed = fsm + 384;
    float* sMt  = fsm + 896;          // [16][128]

    const int tid = threadIdx.x;
    const int w = tid >> 5, lane = tid & 31, g = lane >> 2, t = lane & 3;
    const int mw = (w & 1) * 64;
    const int wc = w >> 1;
    const int q0 = blockIdx.x * 128;
    const int bh = blockIdx.y;

    const __nv_bfloat16* Qhb = g_Qh + ((size_t)bh * 2048 + q0) * 64;
    const __nv_bfloat16* Qlb = g_Ql + ((size_t)bh * 2048 + q0) * 64;
    const __nv_bfloat16* Khb = g_Kh + (size_t)bh * 2048 * 64;
    const __nv_bfloat16* Klb = g_Kl + (size_t)bh * 2048 * 64;
    const __half* Vtfb = g_Vtf + (size_t)bh * 64 * 2048;
    float* Ab = alpha + ((size_t)bh * 2048 + q0) * 2048;

    const uint32_t smu = (uint32_t)__cvta_generic_to_shared(dsm);

    const int r8 = lane & 7, sel = lane >> 3;
    const uint32_t aQ0 = smu + (uint32_t)(((mw + (sel & 1) * 8 + r8) * PQ + (sel >> 1) * 8) * 2);
    uint32_t aK0[4];
    #pragma unroll
    for (int j = 0; j < 4; j++)
        aK0[j] = (uint32_t)(((wc * 32 + j * 8 + r8) * PQ + (sel & 1) * 8) * 2);
    uint32_t aV0[2];
    #pragma unroll
    for (int j = 0; j < 2; j++)
        aV0[j] = smu + (uint32_t)(((wc * 16 + j * 8 + r8) * PV + (sel & 1) * 8) * 2);
    const uint32_t LOQ = 9216u * 2;

    if (tid < 128) { sM[tid] = -3e38f; sL[tid] = 0.f; }

    #pragma unroll
    for (int r = 0; r < 4; r++) {
        int c = tid + r * 256;
        int row = c >> 3, q8 = (c & 7) * 8;
        uint32_t o = (uint32_t)(row * PQ + q8) * 2;
        size_t gi = (size_t)row * 64 + q8;
        cp16(smu + o,       Qhb + gi);
        cp16(smu + LOQ + o, Qlb + gi);
    }
    auto stageK = [&](int kt, int buf) {
        const uint32_t bh_off = (buf ? 36864u : 18432u) * 2;
        const size_t src = (size_t)kt * 128 * 64;
        #pragma unroll
        for (int r = 0; r < 4; r++) {
            int c = tid + r * 256;
            int row = c >> 3, q8 = (c & 7) * 8;
            uint32_t o = (uint32_t)(row * PQ + q8) * 2;
            cp16(smu + bh_off + o,       Khb + src + (size_t)row * 64 + q8);
            cp16(smu + bh_off + LOQ + o, Klb + src + (size_t)row * 64 + q8);
        }
    };
    stageK(0, 0);
    CP_COMMIT;

    // =================== PASS A (bf16 3-term, unchanged) ===================
    for (int kt = 0; kt < 16; kt++) {
        const uint32_t kbase = smu + ((kt & 1) ? 36864u : 18432u) * 2;
        if (kt + 1 < 16) { stageK(kt + 1, (kt & 1) ^ 1); CP_COMMIT; CP_WAIT1; }
        else             { CP_WAIT0; }
        __syncthreads();

        float acc[4][4][4] = {};
        #pragma unroll
        for (int ks = 0; ks < 64; ks += 16) {
            uint32_t kh[4][2], kl[4][2];
            #pragma unroll
            for (int j = 0; j < 4; j++) {
                ldsm2(kh[j][0], kh[j][1], kbase + aK0[j] + ks * 2);
                ldsm2(kl[j][0], kl[j][1], kbase + LOQ + aK0[j] + ks * 2);
            }
            #pragma unroll
            for (int i = 0; i < 4; i++) {
                uint32_t qh0, qh1, qh2, qh3, ql0, ql1, ql2, ql3;
                const uint32_t ao = aQ0 + (uint32_t)(i * 16 * PQ * 2) + ks * 2;
                ldsm4(qh0, qh1, qh2, qh3, ao);
                ldsm4(ql0, ql1, ql2, ql3, ao + LOQ);
                #pragma unroll
                for (int j = 0; j < 4; j++) {
                    mma_bf16(acc[i][j], qh0, qh1, qh2, qh3, kh[j][0], kh[j][1]);
                    mma_bf16(acc[i][j], ql0, ql1, ql2, ql3, kh[j][0], kh[j][1]);
                    mma_bf16(acc[i][j], qh0, qh1, qh2, qh3, kl[j][0], kl[j][1]);
                }
            }
        }
        #pragma unroll
        for (int i = 0; i < 4; i++)
            #pragma unroll
            for (int j = 0; j < 4; j++)
                #pragma unroll
                for (int r = 0; r < 4; r++) acc[i][j][r] *= 0.125f;

        float rmax[8];
        #pragma unroll
        for (int i = 0; i < 4; i++) {
            float m0v = -3e38f, m1v = -3e38f;
            #pragma unroll
            for (int j = 0; j < 4; j++) {
                m0v = fmaxf(m0v, fmaxf(acc[i][j][0], acc[i][j][1]));
                m1v = fmaxf(m1v, fmaxf(acc[i][j][2], acc[i][j][3]));
            }
            rmax[i * 2] = m0v; rmax[i * 2 + 1] = m1v;
        }
        #pragma unroll
        for (int o = 1; o <= 2; o <<= 1)
            #pragma unroll
            for (int e = 0; e < 8; e++)
                rmax[e] = fmaxf(rmax[e], __shfl_xor_sync(0xffffffffu, rmax[e], o));
        if (t == 0) {
            #pragma unroll
            for (int i = 0; i < 4; i++) {
                sRed[wc * 128 + mw + i * 16 + g]     = rmax[i * 2];
                sRed[wc * 128 + mw + i * 16 + g + 8] = rmax[i * 2 + 1];
            }
        }
        __syncthreads();
        if (tid < 128) {
            float tm = fmaxf(fmaxf(sRed[tid], sRed[128 + tid]),
                             fmaxf(sRed[256 + tid], sRed[384 + tid]));
            float mo = sM[tid];
            float mn = fmaxf(mo, tm);
            sM[tid] = mn;
            sF[tid] = __expf(mo - mn);
            sMt[kt * 128 + tid] = mn;
        }
        __syncthreads();

        float rsum[8];
        #pragma unroll
        for (int i = 0; i < 4; i++) {
            const int row = mw + i * 16 + g;
            const float mn0 = sM[row], mn1 = sM[row + 8];
            float s0 = 0.f, s1 = 0.f;
            #pragma unroll
            for (int j = 0; j < 4; j++) {
                acc[i][j][0] = __expf(acc[i][j][0] - mn0);
                acc[i][j][1] = __expf(acc[i][j][1] - mn0);
                acc[i][j][2] = __expf(acc[i][j][2] - mn1);
                acc[i][j][3] = __expf(acc[i][j][3] - mn1);
                s0 += acc[i][j][0] + acc[i][j][1];
                s1 += acc[i][j][2] + acc[i][j][3];
            }
            rsum[i * 2] = s0; rsum[i * 2 + 1] = s1;
        }

        #pragma unroll
        for (int i = 0; i < 4; i++) {
            const int row = mw + i * 16 + g;
            #pragma unroll
            for (int j = 0; j < 4; j++) {
                const int cc = kt * 128 + wc * 32 + j * 8 + t * 2;
                *(float2*)&Ab[(size_t)row * 2048 + cc]       = make_float2(acc[i][j][0], acc[i][j][1]);
                *(float2*)&Ab[(size_t)(row + 8) * 2048 + cc] = make_float2(acc[i][j][2], acc[i][j][3]);
            }
        }

        #pragma unroll
        for (int o = 1; o <= 2; o <<= 1)
            #pragma unroll
            for (int e = 0; e < 8; e++)
                rsum[e] += __shfl_xor_sync(0xffffffffu, rsum[e], o);
        if (t == 0) {
            #pragma unroll
            for (int i = 0; i < 4; i++) {
                sRed[wc * 128 + mw + i * 16 + g]     = rsum[i * 2];
                sRed[wc * 128 + mw + i * 16 + g + 8] = rsum[i * 2 + 1];
            }
        }
        __syncthreads();
        if (tid < 128) {
            sL[tid] = sL[tid] * sF[tid] +
                      (sRed[tid] + sRed[128 + tid] + sRed[256 + tid] + sRed[384 + tid]);
        }
        __syncthreads();
    }

    if (tid < 128) sL[tid] = 1.0f / sL[tid];
    __syncthreads();

    // =================== PASS B (fp16 1-term) ===================
    __half* pVf = (__half*)dsm;            // 64 x PV
    __half* sPf = (__half*)(dsm + 18432);  // 128 x PQ
    const uint32_t aPf0 = smu + 18432u * 2 +
        (uint32_t)(((mw + (sel & 1) * 8 + r8) * PQ + (sel >> 1) * 8) * 2);

    float accO[4][2][4] = {};
    const int pr = tid & 127;
    const int pc = (tid >> 7) * 32;
    const float rmF = sM[pr];
    const float rl  = sL[pr];

    for (int ch = 0; ch < 32; ch++) {
        const int kb = ch * 64;
        // stage Vt fp16: 64 d-rows x 64 kv
        #pragma unroll
        for (int r = 0; r < 2; r++) {
            int c = tid + r * 256;
            int d = c >> 3, q8 = (c & 7) * 8;
            cp16(smu + (uint32_t)(d * PV + q8) * 2,
                 Vtfb + (size_t)d * 2048 + kb + q8);
        }
        CP_COMMIT;

        // P = e * exp(m_kt - m_final) * invl ; write alpha fp32 + smem fp16
        {
            const int tile = ch >> 1;
            const float scale = __expf(sMt[tile * 128 + pr] - rmF) * rl;
            float* rowp = Ab + (size_t)pr * 2048 + kb + pc;
            #pragma unroll
            for (int u = 0; u < 8; u++) {
                float4 s4 = *(const float4*)(rowp + u * 4);
                float4 p4;
                p4.x = s4.x * scale;
                p4.y = s4.y * scale;
                p4.z = s4.z * scale;
                p4.w = s4.w * scale;
                *(float4*)(rowp + u * 4) = p4;
                __half2 h0 = __floats2half2_rn(p4.x, p4.y);
                __half2 h1 = __floats2half2_rn(p4.z, p4.w);
                *(uint32_t*)&sPf[pr * PQ + pc + u * 4]     = *(uint32_t*)&h0;
                *(uint32_t*)&sPf[pr * PQ + pc + u * 4 + 2] = *(uint32_t*)&h1;
            }
        }
        CP_WAIT0;
        __syncthreads();

        #pragma unroll
        for (int ks = 0; ks < 64; ks += 16) {
            uint32_t vf[2][2];
            #pragma unroll
            for (int j = 0; j < 2; j++)
                ldsm2(vf[j][0], vf[j][1], aV0[j] + ks * 2);
            #pragma unroll
            for (int i = 0; i < 4; i++) {
                uint32_t p0, p1, p2, p3;
                ldsm4(p0, p1, p2, p3, aPf0 + (uint32_t)(i * 16 * PQ * 2) + ks * 2);
                #pragma unroll
                for (int j = 0; j < 2; j++)
                    mma_f16(accO[i][j], p0, p1, p2, p3, vf[j][0], vf[j][1]);
            }
        }
        __syncthreads();
    }

    const int b = bh >> 4, h = bh & 15;
    #pragma unroll
    for (int i = 0; i < 4; i++) {
        #pragma unroll
        for (int j = 0; j < 2; j++) {
            const int row = q0 + mw + i * 16 + g;
            const int col = h * 64 + wc * 16 + j * 8 + t * 2;
            size_t d0 = ((size_t)(b * 2048 + row)) * 1024 + col;
            size_t d1 = ((size_t)(b * 2048 + row + 8)) * 1024 + col;
            __half2 h0 = __floats2half2_rn(accO[i][j][0], accO[i][j][1]);
            __half2 h1 = __floats2half2_rn(accO[i][j][2], accO[i][j][3]);
            *(uint32_t*)&AOf[d0] = *(uint32_t*)&h0;
            *(uint32_t*)&AOf[d1] = *(uint32_t*)&h1;
        }
    }
}

// ---------------------------------------------------------------------------
extern "C" void kernel_launch(void* const* d_in, const int* in_sizes, int n_in,
                              void* d_out, int out_size) {
    const float* q  = (const float*)d_in[0];
    const float* k  = (const float*)d_in[1];
    const float* v  = (const float*)d_in[2];
    const float* Wq = (const float*)d_in[3];
    const float* bq = (const float*)d_in[4];
    const float* Wk = (const float*)d_in[5];
    const float* bk = (const float*)d_in[6];
    const float* Wv = (const float*)d_in[7];
    const float* bv = (const float*)d_in[8];
    const float* Wo = (const float*)d_in[9];
    const float* bo = (const float*)d_in[10];

    float* out   = (float*)d_out;
    float* alpha = out + (size_t)B_ * S_ * D_;

    __nv_bfloat16 *qh,*ql,*kh,*kl,*vh,*vl;
    __nv_bfloat16 *Wqh,*Wql,*Wkh,*Wkl,*Wvh,*Wvl;
    __nv_bfloat16 *Qh,*Ql,*Kh,*Kl;
    __half *Wof,*Vf,*Vtf,*AOf;
    cudaGetSymbolAddress((void**)&qh, g_qh);   cudaGetSymbolAddress((void**)&ql, g_ql);
    cudaGetSymbolAddress((void**)&kh, g_kh);   cudaGetSymbolAddress((void**)&kl, g_kl);
    cudaGetSymbolAddress((void**)&vh, g_vh);   cudaGetSymbolAddress((void**)&vl, g_vl);
    cudaGetSymbolAddress((void**)&Wqh, g_Wqh); cudaGetSymbolAddress((void**)&Wql, g_Wql);
    cudaGetSymbolAddress((void**)&Wkh, g_Wkh); cudaGetSymbolAddress((void**)&Wkl, g_Wkl);
    cudaGetSymbolAddress((void**)&Wvh, g_Wvh); cudaGetSymbolAddress((void**)&Wvl, g_Wvl);
    cudaGetSymbolAddress((void**)&Wof, g_Wof);
    cudaGetSymbolAddress((void**)&Qh, g_Qh);   cudaGetSymbolAddress((void**)&Ql, g_Ql);
    cudaGetSymbolAddress((void**)&Kh, g_Kh);   cudaGetSymbolAddress((void**)&Kl, g_Kl);
    cudaGetSymbolAddress((void**)&Vf, g_Vf);   cudaGetSymbolAddress((void**)&Vtf, g_Vtf);
    cudaGetSymbolAddress((void**)&AOf, g_AOf);

    static bool attr_set = false;
    if (!attr_set) {
        cudaFuncSetAttribute(proj_bf16<0>, cudaFuncAttributeMaxDynamicSharedMemorySize, PROJ_SMEM);
        cudaFuncSetAttribute(proj_bf16<3>, cudaFuncAttributeMaxDynamicSharedMemorySize, PROJ_SMEM);
        cudaFuncSetAttribute(proj_f16, cudaFuncAttributeMaxDynamicSharedMemorySize, PF_SMEM);
        cudaFuncSetAttribute(attn_bf16, cudaFuncAttributeMaxDynamicSharedMemorySize, ATTN_SMEM);
        attr_set = true;
    }

    const int n4 = BS_ * HD_ / 4;
    split_in<<<(n4 + 255) / 256, 256>>>(q, qh, ql, n4);
    split_in<<<(n4 + 255) / 256, 256>>>(k, kh, kl, n4);
    split_in<<<(n4 + 255) / 256, 256>>>(v, vh, vl, n4);

    dim3 gW(32, 32), bW(32, 8);
    wsplit<<<gW, bW>>>(Wq, Wqh, Wql);
    wsplit<<<gW, bW>>>(Wk, Wkh, Wkl);
    wsplit<<<gW, bW>>>(Wv, Wvh, Wvl);
    wsplit_f16<<<gW, bW>>>(Wo, Wof);

    dim3 gProj(HD_ / 128, BS_ / 128);   // (8, 64)
    proj_bf16<0><<<gProj, 256, PROJ_SMEM>>>(qh, ql, Wqh, Wql, bq, Qh, Ql);
    proj_bf16<0><<<gProj, 256, PROJ_SMEM>>>(kh, kl, Wkh, Wkl, bk, Kh, Kl);
    proj_bf16<3><<<gProj, 256, PROJ_SMEM>>>(vh, vl, Wvh, Wvl, bv,
                                            (__nv_bfloat16*)Vf, nullptr);

    vtrans_f16<<<dim3(32, 64), 256>>>(Vf, Vtf);

    dim3 gAttn(S_ / 128, B_ * H_);      // (16, 64)
    attn_bf16<<<gAttn, 256, ATTN_SMEM>>>(alpha, AOf);

    proj_f16<<<gProj, 256, PF_SMEM>>>(AOf, Wof, bo, out);
}

// round 14
// speedup vs baseline: 1.5364x; 1.0523x over previous
#include <cuda_runtime.h>
#include <cuda_bf16.h>
#include <cuda_fp16.h>
#include <cstdint>

#define B_ 4
#define S_ 2048
#define D_ 1024
#define H_ 16
#define DH_ 64
#define BS_ 8192
#define HD_ 1024

// ---------------- scratch ----------------
__device__ __nv_bfloat16 g_qh[BS_*HD_], g_ql[BS_*HD_];
__device__ __nv_bfloat16 g_kh[BS_*HD_], g_kl[BS_*HD_];
__device__ __half        g_vf[BS_*HD_];                  // v fp16 flat
__device__ __nv_bfloat16 g_Wqh[D_*HD_], g_Wql[D_*HD_];
__device__ __nv_bfloat16 g_Wkh[D_*HD_], g_Wkl[D_*HD_];
__device__ __half        g_Wvf[D_*HD_];                  // [N][K] fp16
__device__ __half        g_Wof[HD_*D_];                  // [N][K] fp16
__device__ __nv_bfloat16 g_Qh[BS_*HD_], g_Ql[BS_*HD_];   // [bh][s][dh]
__device__ __nv_bfloat16 g_Kh[BS_*HD_], g_Kl[BS_*HD_];   // [bh][s][dh]
__device__ __half        g_Vf[BS_*HD_];                  // [bh][s][dh] fp16
__device__ __half        g_Vtf[BS_*HD_];                 // [bh][dh][s] fp16
__device__ __half        g_AOf[BS_*HD_];                 // [row][1024] fp16

// ---------------- helpers ----------------
__device__ __forceinline__ void sp2(float a, float b, uint32_t& h, uint32_t& l) {
    __nv_bfloat16 ha = __float2bfloat16(a), hb = __float2bfloat16(b);
    float la = a - __bfloat162float(ha);
    float lb = b - __bfloat162float(hb);
    __nv_bfloat162 hp(ha, hb);
    __nv_bfloat162 lp(__float2bfloat16(la), __float2bfloat16(lb));
    h = *reinterpret_cast<uint32_t*>(&hp);
    l = *reinterpret_cast<uint32_t*>(&lp);
}

__device__ __forceinline__ void mma_bf16(float* d, uint32_t a0, uint32_t a1,
                                         uint32_t a2, uint32_t a3,
                                         uint32_t b0, uint32_t b1) {
    asm volatile(
        "mma.sync.aligned.m16n8k16.row.col.f32.bf16.bf16.f32 "
        "{%0,%1,%2,%3}, {%4,%5,%6,%7}, {%8,%9}, {%0,%1,%2,%3};"
        : "+f"(d[0]), "+f"(d[1]), "+f"(d[2]), "+f"(d[3])
        : "r"(a0), "r"(a1), "r"(a2), "r"(a3), "r"(b0), "r"(b1));
}

__device__ __forceinline__ void mma_f16(float* d, uint32_t a0, uint32_t a1,
                                        uint32_t a2, uint32_t a3,
                                        uint32_t b0, uint32_t b1) {
    asm volatile(
        "mma.sync.aligned.m16n8k16.row.col.f32.f16.f16.f32 "
        "{%0,%1,%2,%3}, {%4,%5,%6,%7}, {%8,%9}, {%0,%1,%2,%3};"
        : "+f"(d[0]), "+f"(d[1]), "+f"(d[2]), "+f"(d[3])
        : "r"(a0), "r"(a1), "r"(a2), "r"(a3), "r"(b0), "r"(b1));
}

__device__ __forceinline__ void ldsm4(uint32_t& r0, uint32_t& r1,
                                      uint32_t& r2, uint32_t& r3, uint32_t a) {
    asm volatile("ldmatrix.sync.aligned.m8n8.x4.shared.b16 {%0,%1,%2,%3}, [%4];"
                 : "=r"(r0), "=r"(r1), "=r"(r2), "=r"(r3) : "r"(a));
}
__device__ __forceinline__ void ldsm2(uint32_t& r0, uint32_t& r1, uint32_t a) {
    asm volatile("ldmatrix.sync.aligned.m8n8.x2.shared.b16 {%0,%1}, [%2];"
                 : "=r"(r0), "=r"(r1) : "r"(a));
}

__device__ __forceinline__ void cp16(uint32_t s, const void* g) {
    asm volatile("cp.async.cg.shared.global [%0], [%1], 16;" :: "r"(s), "l"(g));
}
#define CP_COMMIT asm volatile("cp.async.commit_group;")
#define CP_WAIT0  asm volatile("cp.async.wait_group 0;" ::: "memory")
#define CP_WAIT1  asm volatile("cp.async.wait_group 1;" ::: "memory")

// ---------------------------------------------------------------------------
__global__ void split_in(const float* __restrict__ x,
                         __nv_bfloat16* __restrict__ hi,
                         __nv_bfloat16* __restrict__ lo, int n4) {
    int i = blockIdx.x * blockDim.x + threadIdx.x;
    if (i < n4) {
        float4 v = ((const float4*)x)[i];
        uint2 hh, ll;
        sp2(v.x, v.y, hh.x, ll.x);
        sp2(v.z, v.w, hh.y, ll.y);
        ((uint2*)hi)[i] = hh;
        ((uint2*)lo)[i] = ll;
    }
}

__global__ void split_in_f16(const float* __restrict__ x,
                             __half* __restrict__ f, int n4) {
    int i = blockIdx.x * blockDim.x + threadIdx.x;
    if (i < n4) {
        float4 v = ((const float4*)x)[i];
        __half2 h0 = __floats2half2_rn(v.x, v.y);
        __half2 h1 = __floats2half2_rn(v.z, v.w);
        uint2 o = { *(uint32_t*)&h0, *(uint32_t*)&h1 };
        ((uint2*)f)[i] = o;
    }
}

// ---------------------------------------------------------------------------
__global__ void wsplit(const float* __restrict__ W,
                       __nv_bfloat16* __restrict__ th,
                       __nv_bfloat16* __restrict__ tl) {
    __shared__ float t[32][33];
    const int k0 = blockIdx.y * 32, n0 = blockIdx.x * 32;
    const int tx = threadIdx.x, ty = threadIdx.y;
    #pragma unroll
    for (int r = 0; r < 4; r++)
        t[ty + r * 8][tx] = W[(size_t)(k0 + ty + r * 8) * 1024 + n0 + tx];
    __syncthreads();
    #pragma unroll
    for (int r = 0; r < 4; r++) {
        int n = ty + r * 8;
        float v = t[tx][n];
        __nv_bfloat16 hb = __float2bfloat16(v);
        float l = v - __bfloat162float(hb);
        th[(size_t)(n0 + n) * 1024 + k0 + tx] = hb;
        tl[(size_t)(n0 + n) * 1024 + k0 + tx] = __float2bfloat16(l);
    }
}

__global__ void wsplit_f16(const float* __restrict__ W,
                           __half* __restrict__ tf) {
    __shared__ float t[32][33];
    const int k0 = blockIdx.y * 32, n0 = blockIdx.x * 32;
    const int tx = threadIdx.x, ty = threadIdx.y;
    #pragma unroll
    for (int r = 0; r < 4; r++)
        t[ty + r * 8][tx] = W[(size_t)(k0 + ty + r * 8) * 1024 + n0 + tx];
    __syncthreads();
    #pragma unroll
    for (int r = 0; r < 4; r++) {
        int n = ty + r * 8;
        tf[(size_t)(n0 + n) * 1024 + k0 + tx] = __float2half(t[tx][n]);
    }
}

// ---------------------------------------------------------------------------
// Projection GEMM (bf16 3-term), fragments via ldmatrix. Head-packed bf16 out.
// ---------------------------------------------------------------------------
#define PK 40
#define PROJ_SMEM (2 * 4 * 128 * PK * 2)

__global__ void __launch_bounds__(256, 2)
proj_bf16(const __nv_bfloat16* __restrict__ Ah, const __nv_bfloat16* __restrict__ Al,
          const __nv_bfloat16* __restrict__ Bh, const __nv_bfloat16* __restrict__ Bl,
          const float* __restrict__ bias,
          __nv_bfloat16* __restrict__ Ch, __nv_bfloat16* __restrict__ Cl) {
    extern __shared__ __nv_bfloat16 dsm[];
    const int BUF = 4 * 128 * PK;

    const int tid = threadIdx.x;
    const int m0 = blockIdx.y * 128, n0 = blockIdx.x * 128;
    const int w = tid >> 5, lane = tid & 31, g = lane >> 2, t = lane & 3;
    const int mw = (w & 1) * 64, nw = (w >> 1) * 32;

    const uint32_t smu = (uint32_t)__cvta_generic_to_shared(dsm);

    const int r8 = lane & 7, sel = lane >> 3;
    const uint32_t aA0 = smu + (uint32_t)(((mw + (sel & 1) * 8 + r8) * PK + (sel >> 1) * 8) * 2);
    uint32_t aB0[4];
    #pragma unroll
    for (int j = 0; j < 4; j++)
        aB0[j] = smu + (uint32_t)(((nw + j * 8 + r8) * PK + (sel & 1) * 8) * 2)
               + 2u * 128 * PK * 2;
    const uint32_t LO = 128u * PK * 2;

    float acc[4][4][4] = {};

    auto stage = [&](int it, int buf) {
        const int k0 = it * 32;
        const uint32_t bu = smu + (uint32_t)buf * BUF * 2;
        #pragma unroll
        for (int r = 0; r < 2; r++) {
            int c = tid + r * 256;
            int row = c >> 2, q8 = (c & 3) * 8;
            uint32_t o = (uint32_t)(row * PK + q8) * 2;
            size_t gi = (size_t)(m0 + row) * 1024 + k0 + q8;
            cp16(bu + o,                       Ah + gi);
            cp16(bu + 128 * PK * 2 + o,        Al + gi);
            size_t gb = (size_t)(n0 + row) * 1024 + k0 + q8;
            cp16(bu + 2 * 128 * PK * 2 + o,    Bh + gb);
            cp16(bu + 3 * 128 * PK * 2 + o,    Bl + gb);
        }
    };

    stage(0, 0); CP_COMMIT;

    for (int it = 0; it < 32; it++) {
        const int buf = it & 1;
        if (it + 1 < 32) { stage(it + 1, buf ^ 1); CP_COMMIT; CP_WAIT1; }
        else             { CP_WAIT0; }
        __syncthreads();

        const uint32_t bufo = (uint32_t)buf * BUF * 2;

        #pragma unroll
        for (int ks = 0; ks < 32; ks += 16) {
            uint32_t bh[4][2], bl[4][2];
            #pragma unroll
            for (int j = 0; j < 4; j++) {
                ldsm2(bh[j][0], bh[j][1], aB0[j] + bufo + ks * 2);
                ldsm2(bl[j][0], bl[j][1], aB0[j] + bufo + LO + ks * 2);
            }
            #pragma unroll
            for (int i = 0; i < 4; i++) {
                uint32_t ah0, ah1, ah2, ah3, al0, al1, al2, al3;
                const uint32_t ao = aA0 + bufo + (uint32_t)(i * 16 * PK * 2) + ks * 2;
                ldsm4(ah0, ah1, ah2, ah3, ao);
                ldsm4(al0, al1, al2, al3, ao + LO);
                #pragma unroll
                for (int j = 0; j < 4; j++) {
                    mma_bf16(acc[i][j], ah0, ah1, ah2, ah3, bh[j][0], bh[j][1]);
                    mma_bf16(acc[i][j], al0, al1, al2, al3, bh[j][0], bh[j][1]);
                    mma_bf16(acc[i][j], ah0, ah1, ah2, ah3, bl[j][0], bl[j][1]);
                }
            }
        }
        __syncthreads();
    }

    #pragma unroll
    for (int i = 0; i < 4; i++) {
        #pragma unroll
        for (int j = 0; j < 4; j++) {
            const int row0 = m0 + mw + i * 16 + g;
            const int col  = n0 + nw + j * 8 + t * 2;
            const float b0 = bias[col], b1 = bias[col + 1];
            float c00 = acc[i][j][0] + b0, c01 = acc[i][j][1] + b1;
            float c10 = acc[i][j][2] + b0, c11 = acc[i][j][3] + b1;
            int bI = row0 >> 11, s = row0 & 2047, h = col >> 6, d = col & 63;
            size_t d0 = (((size_t)(bI * 16 + h) * 2048 + s) * 64 + d);
            size_t d1 = d0 + 8 * 64;
            uint32_t hu, lu;
            sp2(c00, c01, hu, lu);
            *(uint32_t*)&Ch[d0] = hu; *(uint32_t*)&Cl[d0] = lu;
            sp2(c10, c11, hu, lu);
            *(uint32_t*)&Ch[d1] = hu; *(uint32_t*)&Cl[d1] = lu;
        }
    }
}

// ---------------------------------------------------------------------------
// 1-term fp16 GEMM: C = A @ B^T + bias
// OUTMODE 0: head-packed fp16 (V-proj); OUTMODE 1: flat fp32 (out-proj).
// ---------------------------------------------------------------------------
#define PF_SMEM (2 * 2 * 128 * PK * 2)

template<int OUTMODE>
__global__ void __launch_bounds__(256, 2)
proj_f16(const __half* __restrict__ Af, const __half* __restrict__ Bf,
         const float* __restrict__ bias, void* __restrict__ Cout) {
    extern __shared__ __half fsm16[];
    const int BUF = 2 * 128 * PK;

    const int tid = threadIdx.x;
    const int m0 = blockIdx.y * 128, n0 = blockIdx.x * 128;
    const int w = tid >> 5, lane = tid & 31, g = lane >> 2, t = lane & 3;
    const int mw = (w & 1) * 64, nw = (w >> 1) * 32;

    const uint32_t smu = (uint32_t)__cvta_generic_to_shared(fsm16);

    const int r8 = lane & 7, sel = lane >> 3;
    const uint32_t aA0 = smu + (uint32_t)(((mw + (sel & 1) * 8 + r8) * PK + (sel >> 1) * 8) * 2);
    uint32_t aB0[4];
    #pragma unroll
    for (int j = 0; j < 4; j++)
        aB0[j] = smu + (uint32_t)(((nw + j * 8 + r8) * PK + (sel & 1) * 8) * 2)
               + 128u * PK * 2;

    float acc[4][4][4] = {};

    auto stage = [&](int it, int buf) {
        const int k0 = it * 32;
        const uint32_t bu = smu + (uint32_t)buf * BUF * 2;
        #pragma unroll
        for (int r = 0; r < 2; r++) {
            int c = tid + r * 256;
            int row = c >> 2, q8 = (c & 3) * 8;
            uint32_t o = (uint32_t)(row * PK + q8) * 2;
            cp16(bu + o,                Af + (size_t)(m0 + row) * 1024 + k0 + q8);
            cp16(bu + 128 * PK * 2 + o, Bf + (size_t)(n0 + row) * 1024 + k0 + q8);
        }
    };

    stage(0, 0); CP_COMMIT;

    for (int it = 0; it < 32; it++) {
        const int buf = it & 1;
        if (it + 1 < 32) { stage(it + 1, buf ^ 1); CP_COMMIT; CP_WAIT1; }
        else             { CP_WAIT0; }
        __syncthreads();

        const uint32_t bufo = (uint32_t)buf * BUF * 2;

        #pragma unroll
        for (int ks = 0; ks < 32; ks += 16) {
            uint32_t bf[4][2];
            #pragma unroll
            for (int j = 0; j < 4; j++)
                ldsm2(bf[j][0], bf[j][1], aB0[j] + bufo + ks * 2);
            #pragma unroll
            for (int i = 0; i < 4; i++) {
                uint32_t a0, a1, a2, a3;
                ldsm4(a0, a1, a2, a3, aA0 + bufo + (uint32_t)(i * 16 * PK * 2) + ks * 2);
                #pragma unroll
                for (int j = 0; j < 4; j++)
                    mma_f16(acc[i][j], a0, a1, a2, a3, bf[j][0], bf[j][1]);
            }
        }
        __syncthreads();
    }

    #pragma unroll
    for (int i = 0; i < 4; i++) {
        #pragma unroll
        for (int j = 0; j < 4; j++) {
            const int row0 = m0 + mw + i * 16 + g;
            const int col  = n0 + nw + j * 8 + t * 2;
            const float b0 = bias[col], b1 = bias[col + 1];
            float c00 = acc[i][j][0] + b0, c01 = acc[i][j][1] + b1;
            float c10 = acc[i][j][2] + b0, c11 = acc[i][j][3] + b1;
            if (OUTMODE == 1) {
                float* Cf = (float*)Cout;
                *(float2*)&Cf[(size_t)row0 * 1024 + col]       = make_float2(c00, c01);
                *(float2*)&Cf[(size_t)(row0 + 8) * 1024 + col] = make_float2(c10, c11);
            } else {
                __half* C16 = (__half*)Cout;
                int bI = row0 >> 11, s = row0 & 2047, h = col >> 6, d = col & 63;
                size_t d0 = (((size_t)(bI * 16 + h) * 2048 + s) * 64 + d);
                size_t d1 = d0 + 8 * 64;
                __half2 h0 = __floats2half2_rn(c00, c01);
                __half2 h1 = __floats2half2_rn(c10, c11);
                *(uint32_t*)&C16[d0] = *(uint32_t*)&h0;
                *(uint32_t*)&C16[d1] = *(uint32_t*)&h1;
            }
        }
    }
}

// ---------------------------------------------------------------------------
__global__ void vtrans_f16(const __half* __restrict__ in,
                           __half* __restrict__ outp) {
    __shared__ __half t[64][72];
    const int s0 = blockIdx.x * 64;
    const int bh = blockIdx.y;
    const int tid = threadIdx.x;

    #pragma unroll
    for (int r = 0; r < 8; r++) {
        int c = tid + r * 256;
        int row = c >> 5, c2 = (c & 31) * 2;
        *(uint32_t*)&t[row][c2] =
            *(const uint32_t*)&in[((size_t)bh * 2048 + s0 + row) * 64 + c2];
    }
    __syncthreads();
    #pragma unroll
    for (int r = 0; r < 8; r++) {
        int c = tid + r * 256;
        int d = c >> 5, s2 = (c & 31) * 2;
        __half2 p(t[s2][d], t[s2 + 1][d]);
        *(uint32_t*)&outp[((size_t)bh * 64 + d) * 2048 + s0 + s2] = *(uint32_t*)&p;
    }
}

// ---------------------------------------------------------------------------
// Fused attention: pass A bf16 3-term, pass B fp16 1-term. (unchanged from R12)
// ---------------------------------------------------------------------------
#define PQ 72
#define PV 72
#define ATTN_SMEM (55296 * 2 + 2944 * 4)

__global__ void __launch_bounds__(256, 1)
attn_bf16(float* __restrict__ alpha, __half* __restrict__ AOf) {
    extern __shared__ __nv_bfloat16 dsm[];
    float* fsm  = (float*)(dsm + 55296);
    float* sM   = fsm;
    float* sF   = fsm + 128;
    float* sL   = fsm + 256;
    float* sRed = fsm + 384;
    float* sMt  = fsm + 896;          // [16][128]

    const int tid = threadIdx.x;
    const int w = tid >> 5, lane = tid & 31, g = lane >> 2, t = lane & 3;
    const int mw = (w & 1) * 64;
    const int wc = w >> 1;
    const int q0 = blockIdx.x * 128;
    const int bh = blockIdx.y;

    const __nv_bfloat16* Qhb = g_Qh + ((size_t)bh * 2048 + q0) * 64;
    const __nv_bfloat16* Qlb = g_Ql + ((size_t)bh * 2048 + q0) * 64;
    const __nv_bfloat16* Khb = g_Kh + (size_t)bh * 2048 * 64;
    const __nv_bfloat16* Klb = g_Kl + (size_t)bh * 2048 * 64;
    const __half* Vtfb = g_Vtf + (size_t)bh * 64 * 2048;
    float* Ab = alpha + ((size_t)bh * 2048 + q0) * 2048;

    const uint32_t smu = (uint32_t)__cvta_generic_to_shared(dsm);

    const int r8 = lane & 7, sel = lane >> 3;
    const uint32_t aQ0 = smu + (uint32_t)(((mw + (sel & 1) * 8 + r8) * PQ + (sel >> 1) * 8) * 2);
    uint32_t aK0[4];
    #pragma unroll
    for (int j = 0; j < 4; j++)
        aK0[j] = (uint32_t)(((wc * 32 + j * 8 + r8) * PQ + (sel & 1) * 8) * 2);
    uint32_t aV0[2];
    #pragma unroll
    for (int j = 0; j < 2; j++)
        aV0[j] = smu + (uint32_t)(((wc * 16 + j * 8 + r8) * PV + (sel & 1) * 8) * 2);
    const uint32_t LOQ = 9216u * 2;

    if (tid < 128) { sM[tid] = -3e38f; sL[tid] = 0.f; }

    #pragma unroll
    for (int r = 0; r < 4; r++) {
        int c = tid + r * 256;
        int row = c >> 3, q8 = (c & 7) * 8;
        uint32_t o = (uint32_t)(row * PQ + q8) * 2;
        size_t gi = (size_t)row * 64 + q8;
        cp16(smu + o,       Qhb + gi);
        cp16(smu + LOQ + o, Qlb + gi);
    }
    auto stageK = [&](int kt, int buf) {
        const uint32_t bh_off = (buf ? 36864u : 18432u) * 2;
        const size_t src = (size_t)kt * 128 * 64;
        #pragma unroll
        for (int r = 0; r < 4; r++) {
            int c = tid + r * 256;
            int row = c >> 3, q8 = (c & 7) * 8;
            uint32_t o = (uint32_t)(row * PQ + q8) * 2;
            cp16(smu + bh_off + o,       Khb + src + (size_t)row * 64 + q8);
            cp16(smu + bh_off + LOQ + o, Klb + src + (size_t)row * 64 + q8);
        }
    };
    stageK(0, 0);
    CP_COMMIT;

    // =================== PASS A (bf16 3-term) ===================
    for (int kt = 0; kt < 16; kt++) {
        const uint32_t kbase = smu + ((kt & 1) ? 36864u : 18432u) * 2;
        if (kt + 1 < 16) { stageK(kt + 1, (kt & 1) ^ 1); CP_COMMIT; CP_WAIT1; }
        else             { CP_WAIT0; }
        __syncthreads();

        float acc[4][4][4] = {};
        #pragma unroll
        for (int ks = 0; ks < 64; ks += 16) {
            uint32_t kh[4][2], kl[4][2];
            #pragma unroll
            for (int j = 0; j < 4; j++) {
                ldsm2(kh[j][0], kh[j][1], kbase + aK0[j] + ks * 2);
                ldsm2(kl[j][0], kl[j][1], kbase + LOQ + aK0[j] + ks * 2);
            }
            #pragma unroll
            for (int i = 0; i < 4; i++) {
                uint32_t qh0, qh1, qh2, qh3, ql0, ql1, ql2, ql3;
                const uint32_t ao = aQ0 + (uint32_t)(i * 16 * PQ * 2) + ks * 2;
                ldsm4(qh0, qh1, qh2, qh3, ao);
                ldsm4(ql0, ql1, ql2, ql3, ao + LOQ);
                #pragma unroll
                for (int j = 0; j < 4; j++) {
                    mma_bf16(acc[i][j], qh0, qh1, qh2, qh3, kh[j][0], kh[j][1]);
                    mma_bf16(acc[i][j], ql0, ql1, ql2, ql3, kh[j][0], kh[j][1]);
                    mma_bf16(acc[i][j], qh0, qh1, qh2, qh3, kl[j][0], kl[j][1]);
                }
            }
        }
        #pragma unroll
        for (int i = 0; i < 4; i++)
            #pragma unroll
            for (int j = 0; j < 4; j++)
                #pragma unroll
                for (int r = 0; r < 4; r++) acc[i][j][r] *= 0.125f;

        float rmax[8];
        #pragma unroll
        for (int i = 0; i < 4; i++) {
            float m0v = -3e38f, m1v = -3e38f;
            #pragma unroll
            for (int j = 0; j < 4; j++) {
                m0v = fmaxf(m0v, fmaxf(acc[i][j][0], acc[i][j][1]));
                m1v = fmaxf(m1v, fmaxf(acc[i][j][2], acc[i][j][3]));
            }
            rmax[i * 2] = m0v; rmax[i * 2 + 1] = m1v;
        }
        #pragma unroll
        for (int o = 1; o <= 2; o <<= 1)
            #pragma unroll
            for (int e = 0; e < 8; e++)
                rmax[e] = fmaxf(rmax[e], __shfl_xor_sync(0xffffffffu, rmax[e], o));
        if (t == 0) {
            #pragma unroll
            for (int i = 0; i < 4; i++) {
                sRed[wc * 128 + mw + i * 16 + g]     = rmax[i * 2];
                sRed[wc * 128 + mw + i * 16 + g + 8] = rmax[i * 2 + 1];
            }
        }
        __syncthreads();
        if (tid < 128) {
            float tm = fmaxf(fmaxf(sRed[tid], sRed[128 + tid]),
                             fmaxf(sRed[256 + tid], sRed[384 + tid]));
            float mo = sM[tid];
            float mn = fmaxf(mo, tm);
            sM[tid] = mn;
            sF[tid] = __expf(mo - mn);
            sMt[kt * 128 + tid] = mn;
        }
        __syncthreads();

        float rsum[8];
        #pragma unroll
        for (int i = 0; i < 4; i++) {
            const int row = mw + i * 16 + g;
            const float mn0 = sM[row], mn1 = sM[row + 8];
            float s0 = 0.f, s1 = 0.f;
            #pragma unroll
            for (int j = 0; j < 4; j++) {
                acc[i][j][0] = __expf(acc[i][j][0] - mn0);
                acc[i][j][1] = __expf(acc[i][j][1] - mn0);
                acc[i][j][2] = __expf(acc[i][j][2] - mn1);
                acc[i][j][3] = __expf(acc[i][j][3] - mn1);
                s0 += acc[i][j][0] + acc[i][j][1];
                s1 += acc[i][j][2] + acc[i][j][3];
            }
            rsum[i * 2] = s0; rsum[i * 2 + 1] = s1;
        }

        #pragma unroll
        for (int i = 0; i < 4; i++) {
            const int row = mw + i * 16 + g;
            #pragma unroll
            for (int j = 0; j < 4; j++) {
                const int cc = kt * 128 + wc * 32 + j * 8 + t * 2;
                *(float2*)&Ab[(size_t)row * 2048 + cc]       = make_float2(acc[i][j][0], acc[i][j][1]);
                *(float2*)&Ab[(size_t)(row + 8) * 2048 + cc] = make_float2(acc[i][j][2], acc[i][j][3]);
            }
        }

        #pragma unroll
        for (int o = 1; o <= 2; o <<= 1)
            #pragma unroll
            for (int e = 0; e < 8; e++)
                rsum[e] += __shfl_xor_sync(0xffffffffu, rsum[e], o);
        if (t == 0) {
            #pragma unroll
            for (int i = 0; i < 4; i++) {
                sRed[wc * 128 + mw + i * 16 + g]     = rsum[i * 2];
                sRed[wc * 128 + mw + i * 16 + g + 8] = rsum[i * 2 + 1];
            }
        }
        __syncthreads();
        if (tid < 128) {
            sL[tid] = sL[tid] * sF[tid] +
                      (sRed[tid] + sRed[128 + tid] + sRed[256 + tid] + sRed[384 + tid]);
        }
        __syncthreads();
    }

    if (tid < 128) sL[tid] = 1.0f / sL[tid];
    __syncthreads();

    // =================== PASS B (fp16 1-term) ===================
    __half* sPf = (__half*)(dsm + 18432);  // 128 x PQ
    const uint32_t aPf0 = smu + 18432u * 2 +
        (uint32_t)(((mw + (sel & 1) * 8 + r8) * PQ + (sel >> 1) * 8) * 2);

    float accO[4][2][4] = {};
    const int pr = tid & 127;
    const int pc = (tid >> 7) * 32;
    const float rmF = sM[pr];
    const float rl  = sL[pr];

    for (int ch = 0; ch < 32; ch++) {
        const int kb = ch * 64;
        #pragma unroll
        for (int r = 0; r < 2; r++) {
            int c = tid + r * 256;
            int d = c >> 3, q8 = (c & 7) * 8;
            cp16(smu + (uint32_t)(d * PV + q8) * 2,
                 Vtfb + (size_t)d * 2048 + kb + q8);
        }
        CP_COMMIT;

        {
            const int tile = ch >> 1;
            const float scale = __expf(sMt[tile * 128 + pr] - rmF) * rl;
            float* rowp = Ab + (size_t)pr * 2048 + kb + pc;
            #pragma unroll
            for (int u = 0; u < 8; u++) {
                float4 s4 = *(const float4*)(rowp + u * 4);
                float4 p4;
                p4.x = s4.x * scale;
                p4.y = s4.y * scale;
                p4.z = s4.z * scale;
                p4.w = s4.w * scale;
                *(float4*)(rowp + u * 4) = p4;
                __half2 h0 = __floats2half2_rn(p4.x, p4.y);
                __half2 h1 = __floats2half2_rn(p4.z, p4.w);
                *(uint32_t*)&sPf[pr * PQ + pc + u * 4]     = *(uint32_t*)&h0;
                *(uint32_t*)&sPf[pr * PQ + pc + u * 4 + 2] = *(uint32_t*)&h1;
            }
        }
        CP_WAIT0;
        __syncthreads();

        #pragma unroll
        for (int ks = 0; ks < 64; ks += 16) {
            uint32_t vf[2][2];
            #pragma unroll
            for (int j = 0; j < 2; j++)
                ldsm2(vf[j][0], vf[j][1], aV0[j] + ks * 2);
            #pragma unroll
            for (int i = 0; i < 4; i++) {
                uint32_t p0, p1, p2, p3;
                ldsm4(p0, p1, p2, p3, aPf0 + (uint32_t)(i * 16 * PQ * 2) + ks * 2);
                #pragma unroll
                for (int j = 0; j < 2; j++)
                    mma_f16(accO[i][j], p0, p1, p2, p3, vf[j][0], vf[j][1]);
            }
        }
        __syncthreads();
    }

    const int b = bh >> 4, h = bh & 15;
    #pragma unroll
    for (int i = 0; i < 4; i++) {
        #pragma unroll
        for (int j = 0; j < 2; j++) {
            const int row = q0 + mw + i * 16 + g;
            const int col = h * 64 + wc * 16 + j * 8 + t * 2;
            size_t d0 = ((size_t)(b * 2048 + row)) * 1024 + col;
            size_t d1 = ((size_t)(b * 2048 + row + 8)) * 1024 + col;
            __half2 h0 = __floats2half2_rn(accO[i][j][0], accO[i][j][1]);
            __half2 h1 = __floats2half2_rn(accO[i][j][2], accO[i][j][3]);
            *(uint32_t*)&AOf[d0] = *(uint32_t*)&h0;
            *(uint32_t*)&AOf[d1] = *(uint32_t*)&h1;
        }
    }
}

// ---------------------------------------------------------------------------
extern "C" void kernel_launch(void* const* d_in, const int* in_sizes, int n_in,
                              void* d_out, int out_size) {
    const float* q  = (const float*)d_in[0];
    const float* k  = (const float*)d_in[1];
    const float* v  = (const float*)d_in[2];
    const float* Wq = (const float*)d_in[3];
    const float* bq = (const float*)d_in[4];
    const float* Wk = (const float*)d_in[5];
    const float* bk = (const float*)d_in[6];
    const float* Wv = (const float*)d_in[7];
    const float* bv = (const float*)d_in[8];
    const float* Wo = (const float*)d_in[9];
    const float* bo = (const float*)d_in[10];

    float* out   = (float*)d_out;
    float* alpha = out + (size_t)B_ * S_ * D_;

    __nv_bfloat16 *qh,*ql,*kh,*kl;
    __nv_bfloat16 *Wqh,*Wql,*Wkh,*Wkl;
    __nv_bfloat16 *Qh,*Ql,*Kh,*Kl;
    __half *vf,*Wvf,*Wof,*Vf,*Vtf,*AOf;
    cudaGetSymbolAddress((void**)&qh, g_qh);   cudaGetSymbolAddress((void**)&ql, g_ql);
    cudaGetSymbolAddress((void**)&kh, g_kh);   cudaGetSymbolAddress((void**)&kl, g_kl);
    cudaGetSymbolAddress((void**)&vf, g_vf);
    cudaGetSymbolAddress((void**)&Wqh, g_Wqh); cudaGetSymbolAddress((void**)&Wql, g_Wql);
    cudaGetSymbolAddress((void**)&Wkh, g_Wkh); cudaGetSymbolAddress((void**)&Wkl, g_Wkl);
    cudaGetSymbolAddress((void**)&Wvf, g_Wvf);
    cudaGetSymbolAddress((void**)&Wof, g_Wof);
    cudaGetSymbolAddress((void**)&Qh, g_Qh);   cudaGetSymbolAddress((void**)&Ql, g_Ql);
    cudaGetSymbolAddress((void**)&Kh, g_Kh);   cudaGetSymbolAddress((void**)&Kl, g_Kl);
    cudaGetSymbolAddress((void**)&Vf, g_Vf);   cudaGetSymbolAddress((void**)&Vtf, g_Vtf);
    cudaGetSymbolAddress((void**)&AOf, g_AOf);

    static bool attr_set = false;
    if (!attr_set) {
        cudaFuncSetAttribute(proj_bf16, cudaFuncAttributeMaxDynamicSharedMemorySize, PROJ_SMEM);
        cudaFuncSetAttribute(proj_f16<0>, cudaFuncAttributeMaxDynamicSharedMemorySize, PF_SMEM);
        cudaFuncSetAttribute(proj_f16<1>, cudaFuncAttributeMaxDynamicSharedMemorySize, PF_SMEM);
        cudaFuncSetAttribute(attn_bf16, cudaFuncAttributeMaxDynamicSharedMemorySize, ATTN_SMEM);
        attr_set = true;
    }

    const int n4 = BS_ * HD_ / 4;
    split_in<<<(n4 + 255) / 256, 256>>>(q, qh, ql, n4);
    split_in<<<(n4 + 255) / 256, 256>>>(k, kh, kl, n4);
    split_in_f16<<<(n4 + 255) / 256, 256>>>(v, vf, n4);

    dim3 gW(32, 32), bW(32, 8);
    wsplit<<<gW, bW>>>(Wq, Wqh, Wql);
    wsplit<<<gW, bW>>>(Wk, Wkh, Wkl);
    wsplit_f16<<<gW, bW>>>(Wv, Wvf);
    wsplit_f16<<<gW, bW>>>(Wo, Wof);

    dim3 gProj(HD_ / 128, BS_ / 128);   // (8, 64)
    proj_bf16<<<gProj, 256, PROJ_SMEM>>>(qh, ql, Wqh, Wql, bq, Qh, Ql);
    proj_bf16<<<gProj, 256, PROJ_SMEM>>>(kh, kl, Wkh, Wkl, bk, Kh, Kl);
    proj_f16<0><<<gProj, 256, PF_SMEM>>>(vf, Wvf, bv, Vf);

    vtrans_f16<<<dim3(32, 64), 256>>>(Vf, Vtf);

    dim3 gAttn(S_ / 128, B_ * H_);      // (16, 64)
    attn_bf16<<<gAttn, 256, ATTN_SMEM>>>(alpha, AOf);

    proj_f16<1><<<gProj, 256, PF_SMEM>>>(AOf, Wof, bo, out);
}

// round 16
// speedup vs baseline: 1.7150x; 1.1162x over previous
#include <cuda_runtime.h>
#include <cuda_bf16.h>
#include <cuda_fp16.h>
#include <cstdint>

#define B_ 4
#define S_ 2048
#define D_ 1024
#define H_ 16
#define DH_ 64
#define BS_ 8192
#define HD_ 1024

// ---------------- scratch ----------------
__device__ __nv_bfloat16 g_qh[BS_*HD_], g_ql[BS_*HD_];
__device__ __nv_bfloat16 g_kh[BS_*HD_], g_kl[BS_*HD_];
__device__ __half        g_vf[BS_*HD_];                  // v fp16 flat
__device__ __nv_bfloat16 g_Wqh[D_*HD_], g_Wql[D_*HD_];
__device__ __nv_bfloat16 g_Wkh[D_*HD_], g_Wkl[D_*HD_];
__device__ __half        g_Wvf[D_*HD_];                  // [N][K] fp16
__device__ __half        g_Wof[HD_*D_];                  // [N][K] fp16
__device__ __nv_bfloat16 g_Qh[BS_*HD_], g_Ql[BS_*HD_];   // [bh][s][dh]
__device__ __nv_bfloat16 g_Kh[BS_*HD_], g_Kl[BS_*HD_];   // [bh][s][dh]
__device__ __half        g_Vf[BS_*HD_];                  // [bh][s][dh] fp16
__device__ __half        g_Vtf[BS_*HD_];                 // [bh][dh][s] fp16
__device__ __half        g_AOf[BS_*HD_];                 // [row][1024] fp16

// ---------------- helpers ----------------
__device__ __forceinline__ void sp2(float a, float b, uint32_t& h, uint32_t& l) {
    __nv_bfloat16 ha = __float2bfloat16(a), hb = __float2bfloat16(b);
    float la = a - __bfloat162float(ha);
    float lb = b - __bfloat162float(hb);
    __nv_bfloat162 hp(ha, hb);
    __nv_bfloat162 lp(__float2bfloat16(la), __float2bfloat16(lb));
    h = *reinterpret_cast<uint32_t*>(&hp);
    l = *reinterpret_cast<uint32_t*>(&lp);
}

__device__ __forceinline__ void mma_bf16(float* d, uint32_t a0, uint32_t a1,
                                         uint32_t a2, uint32_t a3,
                                         uint32_t b0, uint32_t b1) {
    asm volatile(
        "mma.sync.aligned.m16n8k16.row.col.f32.bf16.bf16.f32 "
        "{%0,%1,%2,%3}, {%4,%5,%6,%7}, {%8,%9}, {%0,%1,%2,%3};"
        : "+f"(d[0]), "+f"(d[1]), "+f"(d[2]), "+f"(d[3])
        : "r"(a0), "r"(a1), "r"(a2), "r"(a3), "r"(b0), "r"(b1));
}

__device__ __forceinline__ void mma_f16(float* d, uint32_t a0, uint32_t a1,
                                        uint32_t a2, uint32_t a3,
                                        uint32_t b0, uint32_t b1) {
    asm volatile(
        "mma.sync.aligned.m16n8k16.row.col.f32.f16.f16.f32 "
        "{%0,%1,%2,%3}, {%4,%5,%6,%7}, {%8,%9}, {%0,%1,%2,%3};"
        : "+f"(d[0]), "+f"(d[1]), "+f"(d[2]), "+f"(d[3])
        : "r"(a0), "r"(a1), "r"(a2), "r"(a3), "r"(b0), "r"(b1));
}

__device__ __forceinline__ void ldsm4(uint32_t& r0, uint32_t& r1,
                                      uint32_t& r2, uint32_t& r3, uint32_t a) {
    asm volatile("ldmatrix.sync.aligned.m8n8.x4.shared.b16 {%0,%1,%2,%3}, [%4];"
                 : "=r"(r0), "=r"(r1), "=r"(r2), "=r"(r3) : "r"(a));
}
__device__ __forceinline__ void ldsm2(uint32_t& r0, uint32_t& r1, uint32_t a) {
    asm volatile("ldmatrix.sync.aligned.m8n8.x2.shared.b16 {%0,%1}, [%2];"
                 : "=r"(r0), "=r"(r1) : "r"(a));
}

__device__ __forceinline__ void cp16(uint32_t s, const void* g) {
    asm volatile("cp.async.cg.shared.global [%0], [%1], 16;" :: "r"(s), "l"(g));
}
#define CP_COMMIT asm volatile("cp.async.commit_group;")
#define CP_WAIT0  asm volatile("cp.async.wait_group 0;" ::: "memory")
#define CP_WAIT1  asm volatile("cp.async.wait_group 1;" ::: "memory")

// ---------------------------------------------------------------------------
__global__ void split_in(const float* __restrict__ x,
                         __nv_bfloat16* __restrict__ hi,
                         __nv_bfloat16* __restrict__ lo, int n4) {
    int i = blockIdx.x * blockDim.x + threadIdx.x;
    if (i < n4) {
        float4 v = ((const float4*)x)[i];
        uint2 hh, ll;
        sp2(v.x, v.y, hh.x, ll.x);
        sp2(v.z, v.w, hh.y, ll.y);
        ((uint2*)hi)[i] = hh;
        ((uint2*)lo)[i] = ll;
    }
}

__global__ void split_in_f16(const float* __restrict__ x,
                             __half* __restrict__ f, int n4) {
    int i = blockIdx.x * blockDim.x + threadIdx.x;
    if (i < n4) {
        float4 v = ((const float4*)x)[i];
        __half2 h0 = __floats2half2_rn(v.x, v.y);
        __half2 h1 = __floats2half2_rn(v.z, v.w);
        uint2 o = { *(uint32_t*)&h0, *(uint32_t*)&h1 };
        ((uint2*)f)[i] = o;
    }
}

// ---------------------------------------------------------------------------
__global__ void wsplit(const float* __restrict__ W,
                       __nv_bfloat16* __restrict__ th,
                       __nv_bfloat16* __restrict__ tl) {
    __shared__ float t[32][33];
    const int k0 = blockIdx.y * 32, n0 = blockIdx.x * 32;
    const int tx = threadIdx.x, ty = threadIdx.y;
    #pragma unroll
    for (int r = 0; r < 4; r++)
        t[ty + r * 8][tx] = W[(size_t)(k0 + ty + r * 8) * 1024 + n0 + tx];
    __syncthreads();
    #pragma unroll
    for (int r = 0; r < 4; r++) {
        int n = ty + r * 8;
        float v = t[tx][n];
        __nv_bfloat16 hb = __float2bfloat16(v);
        float l = v - __bfloat162float(hb);
        th[(size_t)(n0 + n) * 1024 + k0 + tx] = hb;
        tl[(size_t)(n0 + n) * 1024 + k0 + tx] = __float2bfloat16(l);
    }
}

__global__ void wsplit_f16(const float* __restrict__ W,
                           __half* __restrict__ tf) {
    __shared__ float t[32][33];
    const int k0 = blockIdx.y * 32, n0 = blockIdx.x * 32;
    const int tx = threadIdx.x, ty = threadIdx.y;
    #pragma unroll
    for (int r = 0; r < 4; r++)
        t[ty + r * 8][tx] = W[(size_t)(k0 + ty + r * 8) * 1024 + n0 + tx];
    __syncthreads();
    #pragma unroll
    for (int r = 0; r < 4; r++) {
        int n = ty + r * 8;
        tf[(size_t)(n0 + n) * 1024 + k0 + tx] = __float2half(t[tx][n]);
    }
}

// ---------------------------------------------------------------------------
// Projection GEMM (bf16 3-term), fragments via ldmatrix. Head-packed bf16 out.
// ---------------------------------------------------------------------------
#define PK 40
#define PROJ_SMEM (2 * 4 * 128 * PK * 2)

__global__ void __launch_bounds__(256, 2)
proj_bf16(const __nv_bfloat16* __restrict__ Ah, const __nv_bfloat16* __restrict__ Al,
          const __nv_bfloat16* __restrict__ Bh, const __nv_bfloat16* __restrict__ Bl,
          const float* __restrict__ bias,
          __nv_bfloat16* __restrict__ Ch, __nv_bfloat16* __restrict__ Cl) {
    extern __shared__ __nv_bfloat16 dsm[];
    const int BUF = 4 * 128 * PK;

    const int tid = threadIdx.x;
    const int m0 = blockIdx.y * 128, n0 = blockIdx.x * 128;
    const int w = tid >> 5, lane = tid & 31, g = lane >> 2, t = lane & 3;
    const int mw = (w & 1) * 64, nw = (w >> 1) * 32;

    const uint32_t smu = (uint32_t)__cvta_generic_to_shared(dsm);

    const int r8 = lane & 7, sel = lane >> 3;
    const uint32_t aA0 = smu + (uint32_t)(((mw + (sel & 1) * 8 + r8) * PK + (sel >> 1) * 8) * 2);
    uint32_t aB0[4];
    #pragma unroll
    for (int j = 0; j < 4; j++)
        aB0[j] = smu + (uint32_t)(((nw + j * 8 + r8) * PK + (sel & 1) * 8) * 2)
               + 2u * 128 * PK * 2;
    const uint32_t LO = 128u * PK * 2;

    float acc[4][4][4] = {};

    auto stage = [&](int it, int buf) {
        const int k0 = it * 32;
        const uint32_t bu = smu + (uint32_t)buf * BUF * 2;
        #pragma unroll
        for (int r = 0; r < 2; r++) {
            int c = tid + r * 256;
            int row = c >> 2, q8 = (c & 3) * 8;
            uint32_t o = (uint32_t)(row * PK + q8) * 2;
            size_t gi = (size_t)(m0 + row) * 1024 + k0 + q8;
            cp16(bu + o,                       Ah + gi);
            cp16(bu + 128 * PK * 2 + o,        Al + gi);
            size_t gb = (size_t)(n0 + row) * 1024 + k0 + q8;
            cp16(bu + 2 * 128 * PK * 2 + o,    Bh + gb);
            cp16(bu + 3 * 128 * PK * 2 + o,    Bl + gb);
        }
    };

    stage(0, 0); CP_COMMIT;

    for (int it = 0; it < 32; it++) {
        const int buf = it & 1;
        if (it + 1 < 32) { stage(it + 1, buf ^ 1); CP_COMMIT; CP_WAIT1; }
        else             { CP_WAIT0; }
        __syncthreads();

        const uint32_t bufo = (uint32_t)buf * BUF * 2;

        #pragma unroll
        for (int ks = 0; ks < 32; ks += 16) {
            uint32_t bh[4][2], bl[4][2];
            #pragma unroll
            for (int j = 0; j < 4; j++) {
                ldsm2(bh[j][0], bh[j][1], aB0[j] + bufo + ks * 2);
                ldsm2(bl[j][0], bl[j][1], aB0[j] + bufo + LO + ks * 2);
            }
            #pragma unroll
            for (int i = 0; i < 4; i++) {
                uint32_t ah0, ah1, ah2, ah3, al0, al1, al2, al3;
                const uint32_t ao = aA0 + bufo + (uint32_t)(i * 16 * PK * 2) + ks * 2;
                ldsm4(ah0, ah1, ah2, ah3, ao);
                ldsm4(al0, al1, al2, al3, ao + LO);
                #pragma unroll
                for (int j = 0; j < 4; j++) {
                    mma_bf16(acc[i][j], ah0, ah1, ah2, ah3, bh[j][0], bh[j][1]);
                    mma_bf16(acc[i][j], al0, al1, al2, al3, bh[j][0], bh[j][1]);
                    mma_bf16(acc[i][j], ah0, ah1, ah2, ah3, bl[j][0], bl[j][1]);
                }
            }
        }
        __syncthreads();
    }

    #pragma unroll
    for (int i = 0; i < 4; i++) {
        #pragma unroll
        for (int j = 0; j < 4; j++) {
            const int row0 = m0 + mw + i * 16 + g;
            const int col  = n0 + nw + j * 8 + t * 2;
            const float b0 = bias[col], b1 = bias[col + 1];
            float c00 = acc[i][j][0] + b0, c01 = acc[i][j][1] + b1;
            float c10 = acc[i][j][2] + b0, c11 = acc[i][j][3] + b1;
            int bI = row0 >> 11, s = row0 & 2047, h = col >> 6, d = col & 63;
            size_t d0 = (((size_t)(bI * 16 + h) * 2048 + s) * 64 + d);
            size_t d1 = d0 + 8 * 64;
            uint32_t hu, lu;
            sp2(c00, c01, hu, lu);
            *(uint32_t*)&Ch[d0] = hu; *(uint32_t*)&Cl[d0] = lu;
            sp2(c10, c11, hu, lu);
            *(uint32_t*)&Ch[d1] = hu; *(uint32_t*)&Cl[d1] = lu;
        }
    }
}

// ---------------------------------------------------------------------------
// 1-term fp16 GEMM: C = A @ B^T + bias
// OUTMODE 0: head-packed fp16 (V-proj); OUTMODE 1: flat fp32 (out-proj).
// ---------------------------------------------------------------------------
#define PF_SMEM (2 * 2 * 128 * PK * 2)

template<int OUTMODE>
__global__ void __launch_bounds__(256, 2)
proj_f16(const __half* __restrict__ Af, const __half* __restrict__ Bf,
         const float* __restrict__ bias, void* __restrict__ Cout) {
    extern __shared__ __half fsm16[];
    const int BUF = 2 * 128 * PK;

    const int tid = threadIdx.x;
    const int m0 = blockIdx.y * 128, n0 = blockIdx.x * 128;
    const int w = tid >> 5, lane = tid & 31, g = lane >> 2, t = lane & 3;
    const int mw = (w & 1) * 64, nw = (w >> 1) * 32;

    const uint32_t smu = (uint32_t)__cvta_generic_to_shared(fsm16);

    const int r8 = lane & 7, sel = lane >> 3;
    const uint32_t aA0 = smu + (uint32_t)(((mw + (sel & 1) * 8 + r8) * PK + (sel >> 1) * 8) * 2);
    uint32_t aB0[4];
    #pragma unroll
    for (int j = 0; j < 4; j++)
        aB0[j] = smu + (uint32_t)(((nw + j * 8 + r8) * PK + (sel & 1) * 8) * 2)
               + 128u * PK * 2;

    float acc[4][4][4] = {};

    auto stage = [&](int it, int buf) {
        const int k0 = it * 32;
        const uint32_t bu = smu + (uint32_t)buf * BUF * 2;
        #pragma unroll
        for (int r = 0; r < 2; r++) {
            int c = tid + r * 256;
            int row = c >> 2, q8 = (c & 3) * 8;
            uint32_t o = (uint32_t)(row * PK + q8) * 2;
            cp16(bu + o,                Af + (size_t)(m0 + row) * 1024 + k0 + q8);
            cp16(bu + 128 * PK * 2 + o, Bf + (size_t)(n0 + row) * 1024 + k0 + q8);
        }
    };

    stage(0, 0); CP_COMMIT;

    for (int it = 0; it < 32; it++) {
        const int buf = it & 1;
        if (it + 1 < 32) { stage(it + 1, buf ^ 1); CP_COMMIT; CP_WAIT1; }
        else             { CP_WAIT0; }
        __syncthreads();

        const uint32_t bufo = (uint32_t)buf * BUF * 2;

        #pragma unroll
        for (int ks = 0; ks < 32; ks += 16) {
            uint32_t bf[4][2];
            #pragma unroll
            for (int j = 0; j < 4; j++)
                ldsm2(bf[j][0], bf[j][1], aB0[j] + bufo + ks * 2);
            #pragma unroll
            for (int i = 0; i < 4; i++) {
                uint32_t a0, a1, a2, a3;
                ldsm4(a0, a1, a2, a3, aA0 + bufo + (uint32_t)(i * 16 * PK * 2) + ks * 2);
                #pragma unroll
                for (int j = 0; j < 4; j++)
                    mma_f16(acc[i][j], a0, a1, a2, a3, bf[j][0], bf[j][1]);
            }
        }
        __syncthreads();
    }

    #pragma unroll
    for (int i = 0; i < 4; i++) {
        #pragma unroll
        for (int j = 0; j < 4; j++) {
            const int row0 = m0 + mw + i * 16 + g;
            const int col  = n0 + nw + j * 8 + t * 2;
            const float b0 = bias[col], b1 = bias[col + 1];
            float c00 = acc[i][j][0] + b0, c01 = acc[i][j][1] + b1;
            float c10 = acc[i][j][2] + b0, c11 = acc[i][j][3] + b1;
            if (OUTMODE == 1) {
                float* Cf = (float*)Cout;
                *(float2*)&Cf[(size_t)row0 * 1024 + col]       = make_float2(c00, c01);
                *(float2*)&Cf[(size_t)(row0 + 8) * 1024 + col] = make_float2(c10, c11);
            } else {
                __half* C16 = (__half*)Cout;
                int bI = row0 >> 11, s = row0 & 2047, h = col >> 6, d = col & 63;
                size_t d0 = (((size_t)(bI * 16 + h) * 2048 + s) * 64 + d);
                size_t d1 = d0 + 8 * 64;
                __half2 h0 = __floats2half2_rn(c00, c01);
                __half2 h1 = __floats2half2_rn(c10, c11);
                *(uint32_t*)&C16[d0] = *(uint32_t*)&h0;
                *(uint32_t*)&C16[d1] = *(uint32_t*)&h1;
            }
        }
    }
}

// ---------------------------------------------------------------------------
__global__ void vtrans_f16(const __half* __restrict__ in,
                           __half* __restrict__ outp) {
    __shared__ __half t[64][72];
    const int s0 = blockIdx.x * 64;
    const int bh = blockIdx.y;
    const int tid = threadIdx.x;

    #pragma unroll
    for (int r = 0; r < 8; r++) {
        int c = tid + r * 256;
        int row = c >> 5, c2 = (c & 31) * 2;
        *(uint32_t*)&t[row][c2] =
            *(const uint32_t*)&in[((size_t)bh * 2048 + s0 + row) * 64 + c2];
    }
    __syncthreads();
    #pragma unroll
    for (int r = 0; r < 8; r++) {
        int c = tid + r * 256;
        int d = c >> 5, s2 = (c & 31) * 2;
        __half2 p(t[s2][d], t[s2 + 1][d]);
        *(uint32_t*)&outp[((size_t)bh * 64 + d) * 2048 + s0 + s2] = *(uint32_t*)&p;
    }
}

// ---------------------------------------------------------------------------
// Fused attention: pass A bf16 3-term, pass B fp16 1-term with cp.async
// double-buffered prefetch of BOTH the V tiles and the S/e chunks.
// smem bytes:
//   [0, 9216)        V buf0 (64 x 72 fp16)
//   [9216, 18432)    V buf1
//   [36864, 55296)   sPf (128 x 72 fp16)           (elem 18432)
//   ... pass A regions as before (Q at 0 overlays V bufs; K bufs at 36864+)
//   [110592, 122368) float region (sM/sF/sL/sRed/sMt)
//   [122368, 157184) S buf0 (128 x 68 fp32, pitch-padded)
//   [157184, 192000) S buf1
// total 192000 B -> 1 CTA/SM.
// ---------------------------------------------------------------------------
#define PQ 72
#define PV 72
#define SBUF_OFF 122368
#define SBUF_SZ  34816
#define ATTN_SMEM (SBUF_OFF + 2 * SBUF_SZ)

__global__ void __launch_bounds__(256, 1)
attn_bf16(float* __restrict__ alpha, __half* __restrict__ AOf) {
    extern __shared__ __nv_bfloat16 dsm[];
    float* fsm  = (float*)(dsm + 55296);
    float* sM   = fsm;
    float* sF   = fsm + 128;
    float* sL   = fsm + 256;
    float* sRed = fsm + 384;
    float* sMt  = fsm + 896;          // [16][128]

    const int tid = threadIdx.x;
    const int w = tid >> 5, lane = tid & 31, g = lane >> 2, t = lane & 3;
    const int mw = (w & 1) * 64;
    const int wc = w >> 1;
    const int q0 = blockIdx.x * 128;
    const int bh = blockIdx.y;

    const __nv_bfloat16* Qhb = g_Qh + ((size_t)bh * 2048 + q0) * 64;
    const __nv_bfloat16* Qlb = g_Ql + ((size_t)bh * 2048 + q0) * 64;
    const __nv_bfloat16* Khb = g_Kh + (size_t)bh * 2048 * 64;
    const __nv_bfloat16* Klb = g_Kl + (size_t)bh * 2048 * 64;
    const __half* Vtfb = g_Vtf + (size_t)bh * 64 * 2048;
    float* Ab = alpha + ((size_t)bh * 2048 + q0) * 2048;

    const uint32_t smu = (uint32_t)__cvta_generic_to_shared(dsm);

    const int r8 = lane & 7, sel = lane >> 3;
    const uint32_t aQ0 = smu + (uint32_t)(((mw + (sel & 1) * 8 + r8) * PQ + (sel >> 1) * 8) * 2);
    uint32_t aK0[4];
    #pragma unroll
    for (int j = 0; j < 4; j++)
        aK0[j] = (uint32_t)(((wc * 32 + j * 8 + r8) * PQ + (sel & 1) * 8) * 2);
    uint32_t aV0[2];
    #pragma unroll
    for (int j = 0; j < 2; j++)
        aV0[j] = smu + (uint32_t)(((wc * 16 + j * 8 + r8) * PV + (sel & 1) * 8) * 2);
    const uint32_t LOQ = 9216u * 2;

    if (tid < 128) { sM[tid] = -3e38f; sL[tid] = 0.f; }

    #pragma unroll
    for (int r = 0; r < 4; r++) {
        int c = tid + r * 256;
        int row = c >> 3, q8 = (c & 7) * 8;
        uint32_t o = (uint32_t)(row * PQ + q8) * 2;
        size_t gi = (size_t)row * 64 + q8;
        cp16(smu + o,       Qhb + gi);
        cp16(smu + LOQ + o, Qlb + gi);
    }
    auto stageK = [&](int kt, int buf) {
        const uint32_t bh_off = (buf ? 36864u : 18432u) * 2;
        const size_t src = (size_t)kt * 128 * 64;
        #pragma unroll
        for (int r = 0; r < 4; r++) {
            int c = tid + r * 256;
            int row = c >> 3, q8 = (c & 7) * 8;
            uint32_t o = (uint32_t)(row * PQ + q8) * 2;
            cp16(smu + bh_off + o,       Khb + src + (size_t)row * 64 + q8);
            cp16(smu + bh_off + LOQ + o, Klb + src + (size_t)row * 64 + q8);
        }
    };
    stageK(0, 0);
    CP_COMMIT;

    // =================== PASS A (bf16 3-term) ===================
    for (int kt = 0; kt < 16; kt++) {
        const uint32_t kbase = smu + ((kt & 1) ? 36864u : 18432u) * 2;
        if (kt + 1 < 16) { stageK(kt + 1, (kt & 1) ^ 1); CP_COMMIT; CP_WAIT1; }
        else             { CP_WAIT0; }
        __syncthreads();

        float acc[4][4][4] = {};
        #pragma unroll
        for (int ks = 0; ks < 64; ks += 16) {
            uint32_t kh[4][2], kl[4][2];
            #pragma unroll
            for (int j = 0; j < 4; j++) {
                ldsm2(kh[j][0], kh[j][1], kbase + aK0[j] + ks * 2);
                ldsm2(kl[j][0], kl[j][1], kbase + LOQ + aK0[j] + ks * 2);
            }
            #pragma unroll
            for (int i = 0; i < 4; i++) {
                uint32_t qh0, qh1, qh2, qh3, ql0, ql1, ql2, ql3;
                const uint32_t ao = aQ0 + (uint32_t)(i * 16 * PQ * 2) + ks * 2;
                ldsm4(qh0, qh1, qh2, qh3, ao);
                ldsm4(ql0, ql1, ql2, ql3, ao + LOQ);
                #pragma unroll
                for (int j = 0; j < 4; j++) {
                    mma_bf16(acc[i][j], qh0, qh1, qh2, qh3, kh[j][0], kh[j][1]);
                    mma_bf16(acc[i][j], ql0, ql1, ql2, ql3, kh[j][0], kh[j][1]);
                    mma_bf16(acc[i][j], qh0, qh1, qh2, qh3, kl[j][0], kl[j][1]);
                }
            }
        }
        #pragma unroll
        for (int i = 0; i < 4; i++)
            #pragma unroll
            for (int j = 0; j < 4; j++)
                #pragma unroll
                for (int r = 0; r < 4; r++) acc[i][j][r] *= 0.125f;

        float rmax[8];
        #pragma unroll
        for (int i = 0; i < 4; i++) {
            float m0v = -3e38f, m1v = -3e38f;
            #pragma unroll
            for (int j = 0; j < 4; j++) {
                m0v = fmaxf(m0v, fmaxf(acc[i][j][0], acc[i][j][1]));
                m1v = fmaxf(m1v, fmaxf(acc[i][j][2], acc[i][j][3]));
            }
            rmax[i * 2] = m0v; rmax[i * 2 + 1] = m1v;
        }
        #pragma unroll
        for (int o = 1; o <= 2; o <<= 1)
            #pragma unroll
            for (int e = 0; e < 8; e++)
                rmax[e] = fmaxf(rmax[e], __shfl_xor_sync(0xffffffffu, rmax[e], o));
        if (t == 0) {
            #pragma unroll
            for (int i = 0; i < 4; i++) {
                sRed[wc * 128 + mw + i * 16 + g]     = rmax[i * 2];
                sRed[wc * 128 + mw + i * 16 + g + 8] = rmax[i * 2 + 1];
            }
        }
        __syncthreads();
        if (tid < 128) {
            float tm = fmaxf(fmaxf(sRed[tid], sRed[128 + tid]),
                             fmaxf(sRed[256 + tid], sRed[384 + tid]));
            float mo = sM[tid];
            float mn = fmaxf(mo, tm);
            sM[tid] = mn;
            sF[tid] = __expf(mo - mn);
            sMt[kt * 128 + tid] = mn;
        }
        __syncthreads();

        float rsum[8];
        #pragma unroll
        for (int i = 0; i < 4; i++) {
            const int row = mw + i * 16 + g;
            const float mn0 = sM[row], mn1 = sM[row + 8];
            float s0 = 0.f, s1 = 0.f;
            #pragma unroll
            for (int j = 0; j < 4; j++) {
                acc[i][j][0] = __expf(acc[i][j][0] - mn0);
                acc[i][j][1] = __expf(acc[i][j][1] - mn0);
                acc[i][j][2] = __expf(acc[i][j][2] - mn1);
                acc[i][j][3] = __expf(acc[i][j][3] - mn1);
                s0 += acc[i][j][0] + acc[i][j][1];
                s1 += acc[i][j][2] + acc[i][j][3];
            }
            rsum[i * 2] = s0; rsum[i * 2 + 1] = s1;
        }

        #pragma unroll
        for (int i = 0; i < 4; i++) {
            const int row = mw + i * 16 + g;
            #pragma unroll
            for (int j = 0; j < 4; j++) {
                const int cc = kt * 128 + wc * 32 + j * 8 + t * 2;
                *(float2*)&Ab[(size_t)row * 2048 + cc]       = make_float2(acc[i][j][0], acc[i][j][1]);
                *(float2*)&Ab[(size_t)(row + 8) * 2048 + cc] = make_float2(acc[i][j][2], acc[i][j][3]);
            }
        }

        #pragma unroll
        for (int o = 1; o <= 2; o <<= 1)
            #pragma unroll
            for (int e = 0; e < 8; e++)
                rsum[e] += __shfl_xor_sync(0xffffffffu, rsum[e], o);
        if (t == 0) {
            #pragma unroll
            for (int i = 0; i < 4; i++) {
                sRed[wc * 128 + mw + i * 16 + g]     = rsum[i * 2];
                sRed[wc * 128 + mw + i * 16 + g + 8] = rsum[i * 2 + 1];
            }
        }
        __syncthreads();
        if (tid < 128) {
            sL[tid] = sL[tid] * sF[tid] +
                      (sRed[tid] + sRed[128 + tid] + sRed[256 + tid] + sRed[384 + tid]);
        }
        __syncthreads();
    }

    if (tid < 128) sL[tid] = 1.0f / sL[tid];
    __syncthreads();

    // =================== PASS B (fp16 1-term, S+V prefetched) ===============
    __half* sPf = (__half*)(dsm + 18432);  // byte 36864, 128 x PQ fp16
    const uint32_t aPf0 = smu + 18432u * 2 +
        (uint32_t)(((mw + (sel & 1) * 8 + r8) * PQ + (sel >> 1) * 8) * 2);

    float accO[4][2][4] = {};
    const int pr = tid & 127;
    const int pc = (tid >> 7) * 32;
    const float rmF = sM[pr];
    const float rl  = sL[pr];

    // stage V tile (fp16, 64x72) into V buf
    auto stageV = [&](int ch2, int buf) {
        const int kb2 = ch2 * 64;
        const uint32_t vb = smu + (uint32_t)buf * 9216u;
        #pragma unroll
        for (int r = 0; r < 2; r++) {
            int c = tid + r * 256;
            int d = c >> 3, q8 = (c & 7) * 8;
            cp16(vb + (uint32_t)(d * PV + q8) * 2,
                 Vtfb + (size_t)d * 2048 + kb2 + q8);
        }
    };
    // stage S/e chunk (fp32, 128 rows x 64, padded pitch 68 floats)
    auto stageS = [&](int ch2, int buf) {
        const int kb2 = ch2 * 64;
        const uint32_t sb = smu + SBUF_OFF + (uint32_t)buf * SBUF_SZ;
        #pragma unroll
        for (int r = 0; r < 8; r++) {
            int c = tid + r * 256;
            int row = c >> 4, cq = (c & 15) * 4;
            cp16(sb + (uint32_t)(row * 272 + cq * 4),
                 Ab + (size_t)row * 2048 + kb2 + cq);
        }
    };

    stageV(0, 0);
    stageS(0, 0);
    CP_COMMIT;

    for (int ch = 0; ch < 32; ch++) {
        const int buf = ch & 1;
        const int kb = ch * 64;
        if (ch + 1 < 32) { stageV(ch + 1, buf ^ 1); stageS(ch + 1, buf ^ 1);
                           CP_COMMIT; CP_WAIT1; }
        else             { CP_WAIT0; }
        __syncthreads();

        // normalize from smem S, write P to alpha, fill sPf
        {
            const int tile = ch >> 1;
            const float scale = __expf(sMt[tile * 128 + pr] - rmF) * rl;
            const float* srow = (const float*)((char*)dsm + SBUF_OFF + buf * SBUF_SZ)
                                + pr * 68 + pc;
            float* grow = Ab + (size_t)pr * 2048 + kb + pc;
            #pragma unroll
            for (int u = 0; u < 8; u++) {
                float4 s4 = *(const float4*)(srow + u * 4);
                float4 p4;
                p4.x = s4.x * scale;
                p4.y = s4.y * scale;
                p4.z = s4.z * scale;
                p4.w = s4.w * scale;
                *(float4*)(grow + u * 4) = p4;
                __half2 h0 = __floats2half2_rn(p4.x, p4.y);
                __half2 h1 = __floats2half2_rn(p4.z, p4.w);
                *(uint32_t*)&sPf[pr * PQ + pc + u * 4]     = *(uint32_t*)&h0;
                *(uint32_t*)&sPf[pr * PQ + pc + u * 4 + 2] = *(uint32_t*)&h1;
            }
        }
        __syncthreads();

        const uint32_t vbo = (uint32_t)buf * 9216u;
        #pragma unroll
        for (int ks = 0; ks < 64; ks += 16) {
            uint32_t vf[2][2];
            #pragma unroll
            for (int j = 0; j < 2; j++)
                ldsm2(vf[j][0], vf[j][1], aV0[j] + vbo + ks * 2);
            #pragma unroll
            for (int i = 0; i < 4; i++) {
                uint32_t p0, p1, p2, p3;
                ldsm4(p0, p1, p2, p3, aPf0 + (uint32_t)(i * 16 * PQ * 2) + ks * 2);
                #pragma unroll
                for (int j = 0; j < 2; j++)
                    mma_f16(accO[i][j], p0, p1, p2, p3, vf[j][0], vf[j][1]);
            }
        }
        __syncthreads();
    }

    const int b = bh >> 4, h = bh & 15;
    #pragma unroll
    for (int i = 0; i < 4; i++) {
        #pragma unroll
        for (int j = 0; j < 2; j++) {
            const int row = q0 + mw + i * 16 + g;
            const int col = h * 64 + wc * 16 + j * 8 + t * 2;
            size_t d0 = ((size_t)(b * 2048 + row)) * 1024 + col;
            size_t d1 = ((size_t)(b * 2048 + row + 8)) * 1024 + col;
            __half2 h0 = __floats2half2_rn(accO[i][j][0], accO[i][j][1]);
            __half2 h1 = __floats2half2_rn(accO[i][j][2], accO[i][j][3]);
            *(uint32_t*)&AOf[d0] = *(uint32_t*)&h0;
            *(uint32_t*)&AOf[d1] = *(uint32_t*)&h1;
        }
    }
}

// ---------------------------------------------------------------------------
extern "C" void kernel_launch(void* const* d_in, const int* in_sizes, int n_in,
                              void* d_out, int out_size) {
    const float* q  = (const float*)d_in[0];
    const float* k  = (const float*)d_in[1];
    const float* v  = (const float*)d_in[2];
    const float* Wq = (const float*)d_in[3];
    const float* bq = (const float*)d_in[4];
    const float* Wk = (const float*)d_in[5];
    const float* bk = (const float*)d_in[6];
    const float* Wv = (const float*)d_in[7];
    const float* bv = (const float*)d_in[8];
    const float* Wo = (const float*)d_in[9];
    const float* bo = (const float*)d_in[10];

    float* out   = (float*)d_out;
    float* alpha = out + (size_t)B_ * S_ * D_;

    __nv_bfloat16 *qh,*ql,*kh,*kl;
    __nv_bfloat16 *Wqh,*Wql,*Wkh,*Wkl;
    __nv_bfloat16 *Qh,*Ql,*Kh,*Kl;
    __half *vf,*Wvf,*Wof,*Vf,*Vtf,*AOf;
    cudaGetSymbolAddress((void**)&qh, g_qh);   cudaGetSymbolAddress((void**)&ql, g_ql);
    cudaGetSymbolAddress((void**)&kh, g_kh);   cudaGetSymbolAddress((void**)&kl, g_kl);
    cudaGetSymbolAddress((void**)&vf, g_vf);
    cudaGetSymbolAddress((void**)&Wqh, g_Wqh); cudaGetSymbolAddress((void**)&Wql, g_Wql);
    cudaGetSymbolAddress((void**)&Wkh, g_Wkh); cudaGetSymbolAddress((void**)&Wkl, g_Wkl);
    cudaGetSymbolAddress((void**)&Wvf, g_Wvf);
    cudaGetSymbolAddress((void**)&Wof, g_Wof);
    cudaGetSymbolAddress((void**)&Qh, g_Qh);   cudaGetSymbolAddress((void**)&Ql, g_Ql);
    cudaGetSymbolAddress((void**)&Kh, g_Kh);   cudaGetSymbolAddress((void**)&Kl, g_Kl);
    cudaGetSymbolAddress((void**)&Vf, g_Vf);   cudaGetSymbolAddress((void**)&Vtf, g_Vtf);
    cudaGetSymbolAddress((void**)&AOf, g_AOf);

    static bool attr_set = false;
    if (!attr_set) {
        cudaFuncSetAttribute(proj_bf16, cudaFuncAttributeMaxDynamicSharedMemorySize, PROJ_SMEM);
        cudaFuncSetAttribute(proj_f16<0>, cudaFuncAttributeMaxDynamicSharedMemorySize, PF_SMEM);
        cudaFuncSetAttribute(proj_f16<1>, cudaFuncAttributeMaxDynamicSharedMemorySize, PF_SMEM);
        cudaFuncSetAttribute(attn_bf16, cudaFuncAttributeMaxDynamicSharedMemorySize, ATTN_SMEM);
        attr_set = true;
    }

    const int n4 = BS_ * HD_ / 4;
    split_in<<<(n4 + 255) / 256, 256>>>(q, qh, ql, n4);
    split_in<<<(n4 + 255) / 256, 256>>>(k, kh, kl, n4);
    split_in_f16<<<(n4 + 255) / 256, 256>>>(v, vf, n4);

    dim3 gW(32, 32), bW(32, 8);
    wsplit<<<gW, bW>>>(Wq, Wqh, Wql);
    wsplit<<<gW, bW>>>(Wk, Wkh, Wkl);
    wsplit_f16<<<gW, bW>>>(Wv, Wvf);
    wsplit_f16<<<gW, bW>>>(Wo, Wof);

    dim3 gProj(HD_ / 128, BS_ / 128);   // (8, 64)
    proj_bf16<<<gProj, 256, PROJ_SMEM>>>(qh, ql, Wqh, Wql, bq, Qh, Ql);
    proj_bf16<<<gProj, 256, PROJ_SMEM>>>(kh, kl, Wkh, Wkl, bk, Kh, Kl);
    proj_f16<0><<<gProj, 256, PF_SMEM>>>(vf, Wvf, bv, Vf);

    vtrans_f16<<<dim3(32, 64), 256>>>(Vf, Vtf);

    dim3 gAttn(S_ / 128, B_ * H_);      // (16, 64)
    attn_bf16<<<gAttn, 256, ATTN_SMEM>>>(alpha, AOf);

    proj_f16<1><<<gProj, 256, PF_SMEM>>>(AOf, Wof, bo, out);
}

// round 17
// speedup vs baseline: 1.8117x; 1.0564x over previous
#include <cuda_runtime.h>
#include <cuda_bf16.h>
#include <cuda_fp16.h>
#include <cstdint>

#define B_ 4
#define S_ 2048
#define D_ 1024
#define H_ 16
#define DH_ 64
#define BS_ 8192
#define HD_ 1024

// ---------------- scratch ----------------
__device__ __nv_bfloat16 g_qh[BS_*HD_], g_ql[BS_*HD_];
__device__ __nv_bfloat16 g_kh[BS_*HD_], g_kl[BS_*HD_];
__device__ __half        g_vf[BS_*HD_];                  // v fp16 flat
__device__ __nv_bfloat16 g_Wqh[D_*HD_], g_Wql[D_*HD_];
__device__ __nv_bfloat16 g_Wkh[D_*HD_], g_Wkl[D_*HD_];
__device__ __half        g_Wvf[D_*HD_];                  // [N][K] fp16
__device__ __half        g_Wof[HD_*D_];                  // [N][K] fp16
__device__ __nv_bfloat16 g_Qh[BS_*HD_], g_Ql[BS_*HD_];   // [bh][s][dh]
__device__ __nv_bfloat16 g_Kh[BS_*HD_], g_Kl[BS_*HD_];   // [bh][s][dh]
__device__ __half        g_Vf[BS_*HD_];                  // [bh][s][dh] fp16
__device__ __half        g_Vtf[BS_*HD_];                 // [bh][dh][s] fp16
__device__ __half        g_AOf[BS_*HD_];                 // [row][1024] fp16
__device__ __half        g_Ef[268435456];                // e-values fp16 [bh][s][2048]

// ---------------- helpers ----------------
__device__ __forceinline__ void sp2(float a, float b, uint32_t& h, uint32_t& l) {
    __nv_bfloat16 ha = __float2bfloat16(a), hb = __float2bfloat16(b);
    float la = a - __bfloat162float(ha);
    float lb = b - __bfloat162float(hb);
    __nv_bfloat162 hp(ha, hb);
    __nv_bfloat162 lp(__float2bfloat16(la), __float2bfloat16(lb));
    h = *reinterpret_cast<uint32_t*>(&hp);
    l = *reinterpret_cast<uint32_t*>(&lp);
}

__device__ __forceinline__ void mma_bf16(float* d, uint32_t a0, uint32_t a1,
                                         uint32_t a2, uint32_t a3,
                                         uint32_t b0, uint32_t b1) {
    asm volatile(
        "mma.sync.aligned.m16n8k16.row.col.f32.bf16.bf16.f32 "
        "{%0,%1,%2,%3}, {%4,%5,%6,%7}, {%8,%9}, {%0,%1,%2,%3};"
        : "+f"(d[0]), "+f"(d[1]), "+f"(d[2]), "+f"(d[3])
        : "r"(a0), "r"(a1), "r"(a2), "r"(a3), "r"(b0), "r"(b1));
}

__device__ __forceinline__ void mma_f16(float* d, uint32_t a0, uint32_t a1,
                                        uint32_t a2, uint32_t a3,
                                        uint32_t b0, uint32_t b1) {
    asm volatile(
        "mma.sync.aligned.m16n8k16.row.col.f32.f16.f16.f32 "
        "{%0,%1,%2,%3}, {%4,%5,%6,%7}, {%8,%9}, {%0,%1,%2,%3};"
        : "+f"(d[0]), "+f"(d[1]), "+f"(d[2]), "+f"(d[3])
        : "r"(a0), "r"(a1), "r"(a2), "r"(a3), "r"(b0), "r"(b1));
}

__device__ __forceinline__ void ldsm4(uint32_t& r0, uint32_t& r1,
                                      uint32_t& r2, uint32_t& r3, uint32_t a) {
    asm volatile("ldmatrix.sync.aligned.m8n8.x4.shared.b16 {%0,%1,%2,%3}, [%4];"
                 : "=r"(r0), "=r"(r1), "=r"(r2), "=r"(r3) : "r"(a));
}
__device__ __forceinline__ void ldsm2(uint32_t& r0, uint32_t& r1, uint32_t a) {
    asm volatile("ldmatrix.sync.aligned.m8n8.x2.shared.b16 {%0,%1}, [%2];"
                 : "=r"(r0), "=r"(r1) : "r"(a));
}

__device__ __forceinline__ void cp16(uint32_t s, const void* g) {
    asm volatile("cp.async.cg.shared.global [%0], [%1], 16;" :: "r"(s), "l"(g));
}
#define CP_COMMIT asm volatile("cp.async.commit_group;")
#define CP_WAIT0  asm volatile("cp.async.wait_group 0;" ::: "memory")
#define CP_WAIT1  asm volatile("cp.async.wait_group 1;" ::: "memory")

// ---------------------------------------------------------------------------
__global__ void split_in(const float* __restrict__ x,
                         __nv_bfloat16* __restrict__ hi,
                         __nv_bfloat16* __restrict__ lo, int n4) {
    int i = blockIdx.x * blockDim.x + threadIdx.x;
    if (i < n4) {
        float4 v = ((const float4*)x)[i];
        uint2 hh, ll;
        sp2(v.x, v.y, hh.x, ll.x);
        sp2(v.z, v.w, hh.y, ll.y);
        ((uint2*)hi)[i] = hh;
        ((uint2*)lo)[i] = ll;
    }
}

__global__ void split_in_f16(const float* __restrict__ x,
                             __half* __restrict__ f, int n4) {
    int i = blockIdx.x * blockDim.x + threadIdx.x;
    if (i < n4) {
        float4 v = ((const float4*)x)[i];
        __half2 h0 = __floats2half2_rn(v.x, v.y);
        __half2 h1 = __floats2half2_rn(v.z, v.w);
        uint2 o = { *(uint32_t*)&h0, *(uint32_t*)&h1 };
        ((uint2*)f)[i] = o;
    }
}

// ---------------------------------------------------------------------------
__global__ void wsplit(const float* __restrict__ W,
                       __nv_bfloat16* __restrict__ th,
                       __nv_bfloat16* __restrict__ tl) {
    __shared__ float t[32][33];
    const int k0 = blockIdx.y * 32, n0 = blockIdx.x * 32;
    const int tx = threadIdx.x, ty = threadIdx.y;
    #pragma unroll
    for (int r = 0; r < 4; r++)
        t[ty + r * 8][tx] = W[(size_t)(k0 + ty + r * 8) * 1024 + n0 + tx];
    __syncthreads();
    #pragma unroll
    for (int r = 0; r < 4; r++) {
        int n = ty + r * 8;
        float v = t[tx][n];
        __nv_bfloat16 hb = __float2bfloat16(v);
        float l = v - __bfloat162float(hb);
        th[(size_t)(n0 + n) * 1024 + k0 + tx] = hb;
        tl[(size_t)(n0 + n) * 1024 + k0 + tx] = __float2bfloat16(l);
    }
}

__global__ void wsplit_f16(const float* __restrict__ W,
                           __half* __restrict__ tf) {
    __shared__ float t[32][33];
    const int k0 = blockIdx.y * 32, n0 = blockIdx.x * 32;
    const int tx = threadIdx.x, ty = threadIdx.y;
    #pragma unroll
    for (int r = 0; r < 4; r++)
        t[ty + r * 8][tx] = W[(size_t)(k0 + ty + r * 8) * 1024 + n0 + tx];
    __syncthreads();
    #pragma unroll
    for (int r = 0; r < 4; r++) {
        int n = ty + r * 8;
        tf[(size_t)(n0 + n) * 1024 + k0 + tx] = __float2half(t[tx][n]);
    }
}

// ---------------------------------------------------------------------------
// Projection GEMM (bf16 3-term), fragments via ldmatrix. Head-packed bf16 out.
// ---------------------------------------------------------------------------
#define PK 40
#define PROJ_SMEM (2 * 4 * 128 * PK * 2)

__global__ void __launch_bounds__(256, 2)
proj_bf16(const __nv_bfloat16* __restrict__ Ah, const __nv_bfloat16* __restrict__ Al,
          const __nv_bfloat16* __restrict__ Bh, const __nv_bfloat16* __restrict__ Bl,
          const float* __restrict__ bias,
          __nv_bfloat16* __restrict__ Ch, __nv_bfloat16* __restrict__ Cl) {
    extern __shared__ __nv_bfloat16 dsm[];
    const int BUF = 4 * 128 * PK;

    const int tid = threadIdx.x;
    const int m0 = blockIdx.y * 128, n0 = blockIdx.x * 128;
    const int w = tid >> 5, lane = tid & 31, g = lane >> 2, t = lane & 3;
    const int mw = (w & 1) * 64, nw = (w >> 1) * 32;

    const uint32_t smu = (uint32_t)__cvta_generic_to_shared(dsm);

    const int r8 = lane & 7, sel = lane >> 3;
    const uint32_t aA0 = smu + (uint32_t)(((mw + (sel & 1) * 8 + r8) * PK + (sel >> 1) * 8) * 2);
    uint32_t aB0[4];
    #pragma unroll
    for (int j = 0; j < 4; j++)
        aB0[j] = smu + (uint32_t)(((nw + j * 8 + r8) * PK + (sel & 1) * 8) * 2)
               + 2u * 128 * PK * 2;
    const uint32_t LO = 128u * PK * 2;

    float acc[4][4][4] = {};

    auto stage = [&](int it, int buf) {
        const int k0 = it * 32;
        const uint32_t bu = smu + (uint32_t)buf * BUF * 2;
        #pragma unroll
        for (int r = 0; r < 2; r++) {
            int c = tid + r * 256;
            int row = c >> 2, q8 = (c & 3) * 8;
            uint32_t o = (uint32_t)(row * PK + q8) * 2;
            size_t gi = (size_t)(m0 + row) * 1024 + k0 + q8;
            cp16(bu + o,                       Ah + gi);
            cp16(bu + 128 * PK * 2 + o,        Al + gi);
            size_t gb = (size_t)(n0 + row) * 1024 + k0 + q8;
            cp16(bu + 2 * 128 * PK * 2 + o,    Bh + gb);
            cp16(bu + 3 * 128 * PK * 2 + o,    Bl + gb);
        }
    };

    stage(0, 0); CP_COMMIT;

    for (int it = 0; it < 32; it++) {
        const int buf = it & 1;
        if (it + 1 < 32) { stage(it + 1, buf ^ 1); CP_COMMIT; CP_WAIT1; }
        else             { CP_WAIT0; }
        __syncthreads();

        const uint32_t bufo = (uint32_t)buf * BUF * 2;

        #pragma unroll
        for (int ks = 0; ks < 32; ks += 16) {
            uint32_t bh[4][2], bl[4][2];
            #pragma unroll
            for (int j = 0; j < 4; j++) {
                ldsm2(bh[j][0], bh[j][1], aB0[j] + bufo + ks * 2);
                ldsm2(bl[j][0], bl[j][1], aB0[j] + bufo + LO + ks * 2);
            }
            #pragma unroll
            for (int i = 0; i < 4; i++) {
                uint32_t ah0, ah1, ah2, ah3, al0, al1, al2, al3;
                const uint32_t ao = aA0 + bufo + (uint32_t)(i * 16 * PK * 2) + ks * 2;
                ldsm4(ah0, ah1, ah2, ah3, ao);
                ldsm4(al0, al1, al2, al3, ao + LO);
                #pragma unroll
                for (int j = 0; j < 4; j++) {
                    mma_bf16(acc[i][j], ah0, ah1, ah2, ah3, bh[j][0], bh[j][1]);
                    mma_bf16(acc[i][j], al0, al1, al2, al3, bh[j][0], bh[j][1]);
                    mma_bf16(acc[i][j], ah0, ah1, ah2, ah3, bl[j][0], bl[j][1]);
                }
            }
        }
        __syncthreads();
    }

    #pragma unroll
    for (int i = 0; i < 4; i++) {
        #pragma unroll
        for (int j = 0; j < 4; j++) {
            const int row0 = m0 + mw + i * 16 + g;
            const int col  = n0 + nw + j * 8 + t * 2;
            const float b0 = bias[col], b1 = bias[col + 1];
            float c00 = acc[i][j][0] + b0, c01 = acc[i][j][1] + b1;
            float c10 = acc[i][j][2] + b0, c11 = acc[i][j][3] + b1;
            int bI = row0 >> 11, s = row0 & 2047, h = col >> 6, d = col & 63;
            size_t d0 = (((size_t)(bI * 16 + h) * 2048 + s) * 64 + d);
            size_t d1 = d0 + 8 * 64;
            uint32_t hu, lu;
            sp2(c00, c01, hu, lu);
            *(uint32_t*)&Ch[d0] = hu; *(uint32_t*)&Cl[d0] = lu;
            sp2(c10, c11, hu, lu);
            *(uint32_t*)&Ch[d1] = hu; *(uint32_t*)&Cl[d1] = lu;
        }
    }
}

// ---------------------------------------------------------------------------
// 1-term fp16 GEMM: C = A @ B^T + bias
// OUTMODE 0: head-packed fp16 (V-proj); OUTMODE 1: flat fp32 (out-proj).
// ---------------------------------------------------------------------------
#define PF_SMEM (2 * 2 * 128 * PK * 2)

template<int OUTMODE>
__global__ void __launch_bounds__(256, 2)
proj_f16(const __half* __restrict__ Af, const __half* __restrict__ Bf,
         const float* __restrict__ bias, void* __restrict__ Cout) {
    extern __shared__ __half fsm16[];
    const int BUF = 2 * 128 * PK;

    const int tid = threadIdx.x;
    const int m0 = blockIdx.y * 128, n0 = blockIdx.x * 128;
    const int w = tid >> 5, lane = tid & 31, g = lane >> 2, t = lane & 3;
    const int mw = (w & 1) * 64, nw = (w >> 1) * 32;

    const uint32_t smu = (uint32_t)__cvta_generic_to_shared(fsm16);

    const int r8 = lane & 7, sel = lane >> 3;
    const uint32_t aA0 = smu + (uint32_t)(((mw + (sel & 1) * 8 + r8) * PK + (sel >> 1) * 8) * 2);
    uint32_t aB0[4];
    #pragma unroll
    for (int j = 0; j < 4; j++)
        aB0[j] = smu + (uint32_t)(((nw + j * 8 + r8) * PK + (sel & 1) * 8) * 2)
               + 128u * PK * 2;

    float acc[4][4][4] = {};

    auto stage = [&](int it, int buf) {
        const int k0 = it * 32;
        const uint32_t bu = smu + (uint32_t)buf * BUF * 2;
        #pragma unroll
        for (int r = 0; r < 2; r++) {
            int c = tid + r * 256;
            int row = c >> 2, q8 = (c & 3) * 8;
            uint32_t o = (uint32_t)(row * PK + q8) * 2;
            cp16(bu + o,                Af + (size_t)(m0 + row) * 1024 + k0 + q8);
            cp16(bu + 128 * PK * 2 + o, Bf + (size_t)(n0 + row) * 1024 + k0 + q8);
        }
    };

    stage(0, 0); CP_COMMIT;

    for (int it = 0; it < 32; it++) {
        const int buf = it & 1;
        if (it + 1 < 32) { stage(it + 1, buf ^ 1); CP_COMMIT; CP_WAIT1; }
        else             { CP_WAIT0; }
        __syncthreads();

        const uint32_t bufo = (uint32_t)buf * BUF * 2;

        #pragma unroll
        for (int ks = 0; ks < 32; ks += 16) {
            uint32_t bf[4][2];
            #pragma unroll
            for (int j = 0; j < 4; j++)
                ldsm2(bf[j][0], bf[j][1], aB0[j] + bufo + ks * 2);
            #pragma unroll
            for (int i = 0; i < 4; i++) {
                uint32_t a0, a1, a2, a3;
                ldsm4(a0, a1, a2, a3, aA0 + bufo + (uint32_t)(i * 16 * PK * 2) + ks * 2);
                #pragma unroll
                for (int j = 0; j < 4; j++)
                    mma_f16(acc[i][j], a0, a1, a2, a3, bf[j][0], bf[j][1]);
            }
        }
        __syncthreads();
    }

    #pragma unroll
    for (int i = 0; i < 4; i++) {
        #pragma unroll
        for (int j = 0; j < 4; j++) {
            const int row0 = m0 + mw + i * 16 + g;
            const int col  = n0 + nw + j * 8 + t * 2;
            const float b0 = bias[col], b1 = bias[col + 1];
            float c00 = acc[i][j][0] + b0, c01 = acc[i][j][1] + b1;
            float c10 = acc[i][j][2] + b0, c11 = acc[i][j][3] + b1;
            if (OUTMODE == 1) {
                float* Cf = (float*)Cout;
                *(float2*)&Cf[(size_t)row0 * 1024 + col]       = make_float2(c00, c01);
                *(float2*)&Cf[(size_t)(row0 + 8) * 1024 + col] = make_float2(c10, c11);
            } else {
                __half* C16 = (__half*)Cout;
                int bI = row0 >> 11, s = row0 & 2047, h = col >> 6, d = col & 63;
                size_t d0 = (((size_t)(bI * 16 + h) * 2048 + s) * 64 + d);
                size_t d1 = d0 + 8 * 64;
                __half2 h0 = __floats2half2_rn(c00, c01);
                __half2 h1 = __floats2half2_rn(c10, c11);
                *(uint32_t*)&C16[d0] = *(uint32_t*)&h0;
                *(uint32_t*)&C16[d1] = *(uint32_t*)&h1;
            }
        }
    }
}

// ---------------------------------------------------------------------------
__global__ void vtrans_f16(const __half* __restrict__ in,
                           __half* __restrict__ outp) {
    __shared__ __half t[64][72];
    const int s0 = blockIdx.x * 64;
    const int bh = blockIdx.y;
    const int tid = threadIdx.x;

    #pragma unroll
    for (int r = 0; r < 8; r++) {
        int c = tid + r * 256;
        int row = c >> 5, c2 = (c & 31) * 2;
        *(uint32_t*)&t[row][c2] =
            *(const uint32_t*)&in[((size_t)bh * 2048 + s0 + row) * 64 + c2];
    }
    __syncthreads();
    #pragma unroll
    for (int r = 0; r < 8; r++) {
        int c = tid + r * 256;
        int d = c >> 5, s2 = (c & 31) * 2;
        __half2 p(t[s2][d], t[s2 + 1][d]);
        *(uint32_t*)&outp[((size_t)bh * 64 + d) * 2048 + s0 + s2] = *(uint32_t*)&p;
    }
}

// ---------------------------------------------------------------------------
// Fused attention: pass A bf16 3-term writing e as fp16 to g_Ef; pass B fp16
// 1-term with cp.async double-buffered prefetch of V tiles and fp16 e chunks.
// smem bytes:
//   [0, 9216)        V buf0 (64 x 72 fp16)       (pass A: Q region)
//   [9216, 18432)    V buf1
//   [36864, 55296)   sPf (128 x 72 fp16)         (pass A: K buf0 region)
//   [110592, 122368) float region (sM/sF/sL/sRed/sMt)
//   [122368, 140800) E buf0 (128 x 72 fp16)
//   [140800, 159232) E buf1
// total 159232 B -> 1 CTA/SM.
// ---------------------------------------------------------------------------
#define PQ 72
#define PV 72
#define SBUF_OFF 122368
#define SBUF_SZ  18432
#define ATTN_SMEM (SBUF_OFF + 2 * SBUF_SZ)

__global__ void __launch_bounds__(256, 1)
attn_bf16(float* __restrict__ alpha, __half* __restrict__ AOf) {
    extern __shared__ __nv_bfloat16 dsm[];
    float* fsm  = (float*)(dsm + 55296);
    float* sM   = fsm;
    float* sF   = fsm + 128;
    float* sL   = fsm + 256;
    float* sRed = fsm + 384;
    float* sMt  = fsm + 896;          // [16][128]

    const int tid = threadIdx.x;
    const int w = tid >> 5, lane = tid & 31, g = lane >> 2, t = lane & 3;
    const int mw = (w & 1) * 64;
    const int wc = w >> 1;
    const int q0 = blockIdx.x * 128;
    const int bh = blockIdx.y;

    const __nv_bfloat16* Qhb = g_Qh + ((size_t)bh * 2048 + q0) * 64;
    const __nv_bfloat16* Qlb = g_Ql + ((size_t)bh * 2048 + q0) * 64;
    const __nv_bfloat16* Khb = g_Kh + (size_t)bh * 2048 * 64;
    const __nv_bfloat16* Klb = g_Kl + (size_t)bh * 2048 * 64;
    const __half* Vtfb = g_Vtf + (size_t)bh * 64 * 2048;
    float* Ab = alpha + ((size_t)bh * 2048 + q0) * 2048;
    __half* Eb = g_Ef + ((size_t)bh * 2048 + q0) * 2048;

    const uint32_t smu = (uint32_t)__cvta_generic_to_shared(dsm);

    const int r8 = lane & 7, sel = lane >> 3;
    const uint32_t aQ0 = smu + (uint32_t)(((mw + (sel & 1) * 8 + r8) * PQ + (sel >> 1) * 8) * 2);
    uint32_t aK0[4];
    #pragma unroll
    for (int j = 0; j < 4; j++)
        aK0[j] = (uint32_t)(((wc * 32 + j * 8 + r8) * PQ + (sel & 1) * 8) * 2);
    uint32_t aV0[2];
    #pragma unroll
    for (int j = 0; j < 2; j++)
        aV0[j] = smu + (uint32_t)(((wc * 16 + j * 8 + r8) * PV + (sel & 1) * 8) * 2);
    const uint32_t LOQ = 9216u * 2;

    if (tid < 128) { sM[tid] = -3e38f; sL[tid] = 0.f; }

    #pragma unroll
    for (int r = 0; r < 4; r++) {
        int c = tid + r * 256;
        int row = c >> 3, q8 = (c & 7) * 8;
        uint32_t o = (uint32_t)(row * PQ + q8) * 2;
        size_t gi = (size_t)row * 64 + q8;
        cp16(smu + o,       Qhb + gi);
        cp16(smu + LOQ + o, Qlb + gi);
    }
    auto stageK = [&](int kt, int buf) {
        const uint32_t bh_off = (buf ? 36864u : 18432u) * 2;
        const size_t src = (size_t)kt * 128 * 64;
        #pragma unroll
        for (int r = 0; r < 4; r++) {
            int c = tid + r * 256;
            int row = c >> 3, q8 = (c & 7) * 8;
            uint32_t o = (uint32_t)(row * PQ + q8) * 2;
            cp16(smu + bh_off + o,       Khb + src + (size_t)row * 64 + q8);
            cp16(smu + bh_off + LOQ + o, Klb + src + (size_t)row * 64 + q8);
        }
    };
    stageK(0, 0);
    CP_COMMIT;

    // =================== PASS A (bf16 3-term) ===================
    for (int kt = 0; kt < 16; kt++) {
        const uint32_t kbase = smu + ((kt & 1) ? 36864u : 18432u) * 2;
        if (kt + 1 < 16) { stageK(kt + 1, (kt & 1) ^ 1); CP_COMMIT; CP_WAIT1; }
        else             { CP_WAIT0; }
        __syncthreads();

        float acc[4][4][4] = {};
        #pragma unroll
        for (int ks = 0; ks < 64; ks += 16) {
            uint32_t kh[4][2], kl[4][2];
            #pragma unroll
            for (int j = 0; j < 4; j++) {
                ldsm2(kh[j][0], kh[j][1], kbase + aK0[j] + ks * 2);
                ldsm2(kl[j][0], kl[j][1], kbase + LOQ + aK0[j] + ks * 2);
            }
            #pragma unroll
            for (int i = 0; i < 4; i++) {
                uint32_t qh0, qh1, qh2, qh3, ql0, ql1, ql2, ql3;
                const uint32_t ao = aQ0 + (uint32_t)(i * 16 * PQ * 2) + ks * 2;
                ldsm4(qh0, qh1, qh2, qh3, ao);
                ldsm4(ql0, ql1, ql2, ql3, ao + LOQ);
                #pragma unroll
                for (int j = 0; j < 4; j++) {
                    mma_bf16(acc[i][j], qh0, qh1, qh2, qh3, kh[j][0], kh[j][1]);
                    mma_bf16(acc[i][j], ql0, ql1, ql2, ql3, kh[j][0], kh[j][1]);
                    mma_bf16(acc[i][j], qh0, qh1, qh2, qh3, kl[j][0], kl[j][1]);
                }
            }
        }
        #pragma unroll
        for (int i = 0; i < 4; i++)
            #pragma unroll
            for (int j = 0; j < 4; j++)
                #pragma unroll
                for (int r = 0; r < 4; r++) acc[i][j][r] *= 0.125f;

        float rmax[8];
        #pragma unroll
        for (int i = 0; i < 4; i++) {
            float m0v = -3e38f, m1v = -3e38f;
            #pragma unroll
            for (int j = 0; j < 4; j++) {
                m0v = fmaxf(m0v, fmaxf(acc[i][j][0], acc[i][j][1]));
                m1v = fmaxf(m1v, fmaxf(acc[i][j][2], acc[i][j][3]));
            }
            rmax[i * 2] = m0v; rmax[i * 2 + 1] = m1v;
        }
        #pragma unroll
        for (int o = 1; o <= 2; o <<= 1)
            #pragma unroll
            for (int e = 0; e < 8; e++)
                rmax[e] = fmaxf(rmax[e], __shfl_xor_sync(0xffffffffu, rmax[e], o));
        if (t == 0) {
            #pragma unroll
            for (int i = 0; i < 4; i++) {
                sRed[wc * 128 + mw + i * 16 + g]     = rmax[i * 2];
                sRed[wc * 128 + mw + i * 16 + g + 8] = rmax[i * 2 + 1];
            }
        }
        __syncthreads();
        if (tid < 128) {
            float tm = fmaxf(fmaxf(sRed[tid], sRed[128 + tid]),
                             fmaxf(sRed[256 + tid], sRed[384 + tid]));
            float mo = sM[tid];
            float mn = fmaxf(mo, tm);
            sM[tid] = mn;
            sF[tid] = __expf(mo - mn);
            sMt[kt * 128 + tid] = mn;
        }
        __syncthreads();

        float rsum[8];
        #pragma unroll
        for (int i = 0; i < 4; i++) {
            const int row = mw + i * 16 + g;
            const float mn0 = sM[row], mn1 = sM[row + 8];
            float s0 = 0.f, s1 = 0.f;
            #pragma unroll
            for (int j = 0; j < 4; j++) {
                acc[i][j][0] = __expf(acc[i][j][0] - mn0);
                acc[i][j][1] = __expf(acc[i][j][1] - mn0);
                acc[i][j][2] = __expf(acc[i][j][2] - mn1);
                acc[i][j][3] = __expf(acc[i][j][3] - mn1);
                s0 += acc[i][j][0] + acc[i][j][1];
                s1 += acc[i][j][2] + acc[i][j][3];
            }
            rsum[i * 2] = s0; rsum[i * 2 + 1] = s1;
        }

        // write e (fp16) to scratch — halved store traffic
        #pragma unroll
        for (int i = 0; i < 4; i++) {
            const int row = mw + i * 16 + g;
            #pragma unroll
            for (int j = 0; j < 4; j++) {
                const int cc = kt * 128 + wc * 32 + j * 8 + t * 2;
                __half2 e0 = __floats2half2_rn(acc[i][j][0], acc[i][j][1]);
                __half2 e1 = __floats2half2_rn(acc[i][j][2], acc[i][j][3]);
                *(uint32_t*)&Eb[(size_t)row * 2048 + cc]       = *(uint32_t*)&e0;
                *(uint32_t*)&Eb[(size_t)(row + 8) * 2048 + cc] = *(uint32_t*)&e1;
            }
        }

        #pragma unroll
        for (int o = 1; o <= 2; o <<= 1)
            #pragma unroll
            for (int e = 0; e < 8; e++)
                rsum[e] += __shfl_xor_sync(0xffffffffu, rsum[e], o);
        if (t == 0) {
            #pragma unroll
            for (int i = 0; i < 4; i++) {
                sRed[wc * 128 + mw + i * 16 + g]     = rsum[i * 2];
                sRed[wc * 128 + mw + i * 16 + g + 8] = rsum[i * 2 + 1];
            }
        }
        __syncthreads();
        if (tid < 128) {
            sL[tid] = sL[tid] * sF[tid] +
                      (sRed[tid] + sRed[128 + tid] + sRed[256 + tid] + sRed[384 + tid]);
        }
        __syncthreads();
    }

    if (tid < 128) sL[tid] = 1.0f / sL[tid];
    __syncthreads();

    // =================== PASS B (fp16 1-term, E+V prefetched) ===============
    __half* sPf = (__half*)(dsm + 18432);  // byte 36864, 128 x PQ fp16
    const uint32_t aPf0 = smu + 18432u * 2 +
        (uint32_t)(((mw + (sel & 1) * 8 + r8) * PQ + (sel >> 1) * 8) * 2);

    float accO[4][2][4] = {};
    const int pr = tid & 127;
    const int pc = (tid >> 7) * 32;
    const float rmF = sM[pr];
    const float rl  = sL[pr];

    auto stageV = [&](int ch2, int buf) {
        const int kb2 = ch2 * 64;
        const uint32_t vb = smu + (uint32_t)buf * 9216u;
        #pragma unroll
        for (int r = 0; r < 2; r++) {
            int c = tid + r * 256;
            int d = c >> 3, q8 = (c & 7) * 8;
            cp16(vb + (uint32_t)(d * PV + q8) * 2,
                 Vtfb + (size_t)d * 2048 + kb2 + q8);
        }
    };
    // stage e chunk (fp16, 128 rows x 64, pitch 72 halves)
    auto stageE = [&](int ch2, int buf) {
        const int kb2 = ch2 * 64;
        const uint32_t sb = smu + SBUF_OFF + (uint32_t)buf * SBUF_SZ;
        #pragma unroll
        for (int r = 0; r < 4; r++) {
            int c = tid + r * 256;
            int row = c >> 3, q8 = (c & 7) * 8;
            cp16(sb + (uint32_t)(row * PQ + q8) * 2,
                 Eb + (size_t)row * 2048 + kb2 + q8);
        }
    };

    stageV(0, 0);
    stageE(0, 0);
    CP_COMMIT;

    for (int ch = 0; ch < 32; ch++) {
        const int buf = ch & 1;
        const int kb = ch * 64;
        if (ch + 1 < 32) { stageV(ch + 1, buf ^ 1); stageE(ch + 1, buf ^ 1);
                           CP_COMMIT; CP_WAIT1; }
        else             { CP_WAIT0; }
        __syncthreads();

        // normalize from smem e (fp16), write fp32 P to alpha, fill sPf
        {
            const int tile = ch >> 1;
            const float scale = __expf(sMt[tile * 128 + pr] - rmF) * rl;
            const __half* srow = (const __half*)((char*)dsm + SBUF_OFF + buf * SBUF_SZ)
                                 + pr * PQ + pc;
            float* grow = Ab + (size_t)pr * 2048 + kb + pc;
            #pragma unroll
            for (int u = 0; u < 8; u++) {
                uint2 ee = *(const uint2*)(srow + u * 4);
                __half2 e01 = *(__half2*)&ee.x;
                __half2 e23 = *(__half2*)&ee.y;
                float2 f01 = __half22float2(e01);
                float2 f23 = __half22float2(e23);
                float4 p4;
                p4.x = f01.x * scale;
                p4.y = f01.y * scale;
                p4.z = f23.x * scale;
                p4.w = f23.y * scale;
                *(float4*)(grow + u * 4) = p4;
                __half2 h0 = __floats2half2_rn(p4.x, p4.y);
                __half2 h1 = __floats2half2_rn(p4.z, p4.w);
                *(uint32_t*)&sPf[pr * PQ + pc + u * 4]     = *(uint32_t*)&h0;
                *(uint32_t*)&sPf[pr * PQ + pc + u * 4 + 2] = *(uint32_t*)&h1;
            }
        }
        __syncthreads();

        const uint32_t vbo = (uint32_t)buf * 9216u;
        #pragma unroll
        for (int ks = 0; ks < 64; ks += 16) {
            uint32_t vf[2][2];
            #pragma unroll
            for (int j = 0; j < 2; j++)
                ldsm2(vf[j][0], vf[j][1], aV0[j] + vbo + ks * 2);
            #pragma unroll
            for (int i = 0; i < 4; i++) {
                uint32_t p0, p1, p2, p3;
                ldsm4(p0, p1, p2, p3, aPf0 + (uint32_t)(i * 16 * PQ * 2) + ks * 2);
                #pragma unroll
                for (int j = 0; j < 2; j++)
                    mma_f16(accO[i][j], p0, p1, p2, p3, vf[j][0], vf[j][1]);
            }
        }
        __syncthreads();
    }

    const int b = bh >> 4, h = bh & 15;
    #pragma unroll
    for (int i = 0; i < 4; i++) {
        #pragma unroll
        for (int j = 0; j < 2; j++) {
            const int row = q0 + mw + i * 16 + g;
            const int col = h * 64 + wc * 16 + j * 8 + t * 2;
            size_t d0 = ((size_t)(b * 2048 + row)) * 1024 + col;
            size_t d1 = ((size_t)(b * 2048 + row + 8)) * 1024 + col;
            __half2 h0 = __floats2half2_rn(accO[i][j][0], accO[i][j][1]);
            __half2 h1 = __floats2half2_rn(accO[i][j][2], accO[i][j][3]);
            *(uint32_t*)&AOf[d0] = *(uint32_t*)&h0;
            *(uint32_t*)&AOf[d1] = *(uint32_t*)&h1;
        }
    }
}

// ---------------------------------------------------------------------------
extern "C" void kernel_launch(void* const* d_in, const int* in_sizes, int n_in,
                              void* d_out, int out_size) {
    const float* q  = (const float*)d_in[0];
    const float* k  = (const float*)d_in[1];
    const float* v  = (const float*)d_in[2];
    const float* Wq = (const float*)d_in[3];
    const float* bq = (const float*)d_in[4];
    const float* Wk = (const float*)d_in[5];
    const float* bk = (const float*)d_in[6];
    const float* Wv = (const float*)d_in[7];
    const float* bv = (const float*)d_in[8];
    const float* Wo = (const float*)d_in[9];
    const float* bo = (const float*)d_in[10];

    float* out   = (float*)d_out;
    float* alpha = out + (size_t)B_ * S_ * D_;

    __nv_bfloat16 *qh,*ql,*kh,*kl;
    __nv_bfloat16 *Wqh,*Wql,*Wkh,*Wkl;
    __nv_bfloat16 *Qh,*Ql,*Kh,*Kl;
    __half *vf,*Wvf,*Wof,*Vf,*Vtf,*AOf;
    cudaGetSymbolAddress((void**)&qh, g_qh);   cudaGetSymbolAddress((void**)&ql, g_ql);
    cudaGetSymbolAddress((void**)&kh, g_kh);   cudaGetSymbolAddress((void**)&kl, g_kl);
    cudaGetSymbolAddress((void**)&vf, g_vf);
    cudaGetSymbolAddress((void**)&Wqh, g_Wqh); cudaGetSymbolAddress((void**)&Wql, g_Wql);
    cudaGetSymbolAddress((void**)&Wkh, g_Wkh); cudaGetSymbolAddress((void**)&Wkl, g_Wkl);
    cudaGetSymbolAddress((void**)&Wvf, g_Wvf);
    cudaGetSymbolAddress((void**)&Wof, g_Wof);
    cudaGetSymbolAddress((void**)&Qh, g_Qh);   cudaGetSymbolAddress((void**)&Ql, g_Ql);
    cudaGetSymbolAddress((void**)&Kh, g_Kh);   cudaGetSymbolAddress((void**)&Kl, g_Kl);
    cudaGetSymbolAddress((void**)&Vf, g_Vf);   cudaGetSymbolAddress((void**)&Vtf, g_Vtf);
    cudaGetSymbolAddress((void**)&AOf, g_AOf);

    static bool attr_set = false;
    if (!attr_set) {
        cudaFuncSetAttribute(proj_bf16, cudaFuncAttributeMaxDynamicSharedMemorySize, PROJ_SMEM);
        cudaFuncSetAttribute(proj_f16<0>, cudaFuncAttributeMaxDynamicSharedMemorySize, PF_SMEM);
        cudaFuncSetAttribute(proj_f16<1>, cudaFuncAttributeMaxDynamicSharedMemorySize, PF_SMEM);
        cudaFuncSetAttribute(attn_bf16, cudaFuncAttributeMaxDynamicSharedMemorySize, ATTN_SMEM);
        attr_set = true;
    }

    const int n4 = BS_ * HD_ / 4;
    split_in<<<(n4 + 255) / 256, 256>>>(q, qh, ql, n4);
    split_in<<<(n4 + 255) / 256, 256>>>(k, kh, kl, n4);
    split_in_f16<<<(n4 + 255) / 256, 256>>>(v, vf, n4);

    dim3 gW(32, 32), bW(32, 8);
    wsplit<<<gW, bW>>>(Wq, Wqh, Wql);
    wsplit<<<gW, bW>>>(Wk, Wkh, Wkl);
    wsplit_f16<<<gW, bW>>>(Wv, Wvf);
    wsplit_f16<<<gW, bW>>>(Wo, Wof);

    dim3 gProj(HD_ / 128, BS_ / 128);   // (8, 64)
    proj_bf16<<<gProj, 256, PROJ_SMEM>>>(qh, ql, Wqh, Wql, bq, Qh, Ql);
    proj_bf16<<<gProj, 256, PROJ_SMEM>>>(kh, kl, Wkh, Wkl, bk, Kh, Kl);
    proj_f16<0><<<gProj, 256, PF_SMEM>>>(vf, Wvf, bv, Vf);

    vtrans_f16<<<dim3(32, 64), 256>>>(Vf, Vtf);

    dim3 gAttn(S_ / 128, B_ * H_);      // (16, 64)
    attn_bf16<<<gAttn, 256, ATTN_SMEM>>>(alpha, AOf);

    proj_f16<1><<<gProj, 256, PF_SMEM>>>(AOf, Wof, bo, out);
}